// round 2
// baseline (speedup 1.0000x reference)
#include <cuda_runtime.h>
#include <math.h>

#define NB 2
#define NS 2048
#define NH 16
#define HD 64
#define NDIM 1024
#define NM (NB*NS)
#define OUT_ELEMS (NB*NS*NDIM)   // 4194304 per tensor (out, k, v)

// Scratch (allocation-free rule: __device__ globals)
__device__ float g_q[NB*NH*NS*HD];     // q after proj (+RoPE), [b,h,s,d]
__device__ float g_ctx[NB*NS*NDIM];    // attention context, [b,s, h*64+d] flat
__device__ float g_cos[NS*32];
__device__ float g_sin[NS*32];

// ---------------------------------------------------------------------------
// RoPE tables: inv_freq[j] = 10000^(-j/32); angle = s * inv_freq (fp32 product
// to match the jnp fp32 einsum), cos/sin evaluated in double.
// ---------------------------------------------------------------------------
__global__ void rope_table_kernel() {
    int idx = blockIdx.x * blockDim.x + threadIdx.x;
    if (idx >= NS * 32) return;
    int s = idx >> 5, j = idx & 31;
    float invf = (float)exp(-(double)j * (log(10000.0) / 32.0));
    float ang = (float)s * invf;       // fp32 rounding like the reference
    g_cos[idx] = (float)cos((double)ang);
    g_sin[idx] = (float)sin((double)ang);
}

// In-place RoPE on [b,h,s,d] tensors. blockIdx.y: 0 -> g_q, 1 -> kptr.
__global__ void rope_apply_kernel(float* __restrict__ kptr) {
    int idx = blockIdx.x * blockDim.x + threadIdx.x;   // NB*NH*NS*32 threads
    float* p = blockIdx.y ? kptr : g_q;
    int j = idx & 31;
    int row = idx >> 5;                // bh*NS + s
    int s = row & (NS - 1);
    int base = row * 64 + j;
    float c = g_cos[(s << 5) + j], sn = g_sin[(s << 5) + j];
    float x1 = p[base], x2 = p[base + 32];
    p[base]      = x1 * c - x2 * sn;
    p[base + 32] = x2 * c + x1 * sn;
}

// ---------------------------------------------------------------------------
// y = A @ W^T + bias.  A: [M,1024] row-major, W: [N,1024] row-major (torch
// Linear layout, so both operands are K-contiguous).  64x64 tile, 4x4 micro.
// headLayout=1: scatter into [b,h,s,d]; headLayout=0: flat [m, n].
// ---------------------------------------------------------------------------
__global__ void linear64_kernel(const float* __restrict__ A, const float* __restrict__ W,
                                const float* __restrict__ bias, float* __restrict__ dst,
                                int headLayout)
{
    __shared__ __align__(16) float As[32][68];   // [k][m], padded
    __shared__ __align__(16) float Bs[32][68];   // [k][n], padded
    int tid = threadIdx.x;
    int tx = tid & 15, ty = tid >> 4;
    int m0 = blockIdx.y << 6, n0 = blockIdx.x << 6;

    float acc[4][4];
    #pragma unroll
    for (int i = 0; i < 4; i++)
        #pragma unroll
        for (int j = 0; j < 4; j++) acc[i][j] = 0.f;

    for (int k0 = 0; k0 < NDIM; k0 += 32) {
        #pragma unroll
        for (int i = 0; i < 2; i++) {
            int lin = tid + (i << 8);
            int row = lin >> 3;              // 0..63
            int kk  = (lin & 7) << 2;        // 0..28
            float4 av = *(const float4*)(A + (m0 + row) * NDIM + k0 + kk);
            As[kk+0][row] = av.x; As[kk+1][row] = av.y;
            As[kk+2][row] = av.z; As[kk+3][row] = av.w;
            float4 bv = *(const float4*)(W + (n0 + row) * NDIM + k0 + kk);
            Bs[kk+0][row] = bv.x; Bs[kk+1][row] = bv.y;
            Bs[kk+2][row] = bv.z; Bs[kk+3][row] = bv.w;
        }
        __syncthreads();
        #pragma unroll 8
        for (int kk = 0; kk < 32; kk++) {
            float4 a  = *(const float4*)&As[kk][ty << 2];
            float4 bb = *(const float4*)&Bs[kk][tx << 2];
            float av[4] = {a.x, a.y, a.z, a.w};
            float bv[4] = {bb.x, bb.y, bb.z, bb.w};
            #pragma unroll
            for (int i = 0; i < 4; i++)
                #pragma unroll
                for (int j = 0; j < 4; j++)
                    acc[i][j] += av[i] * bv[j];
        }
        __syncthreads();
    }

    #pragma unroll
    for (int i = 0; i < 4; i++) {
        int m = m0 + (ty << 2) + i;
        #pragma unroll
        for (int j = 0; j < 4; j++) {
            int n = n0 + (tx << 2) + j;
            float val = acc[i][j] + bias[n];
            if (headLayout) {
                int b = m >> 11, s = m & (NS - 1);
                int h = n >> 6, d = n & 63;
                dst[(((size_t)((b << 4) + h) * NS + s)) * HD + d] = val;
            } else {
                dst[(size_t)m * NDIM + n] = val;
            }
        }
    }
}

// ---------------------------------------------------------------------------
// Flash attention: one block = one (b,h) and 64 query rows.  Streams K/V in
// 64-key tiles. 256 threads; thread (tx,ty) owns 4 q-rows x 4 cols for both
// the score tile and the output tile. Online softmax with 16-lane shfl.
// ---------------------------------------------------------------------------
__global__ void attn_kernel(const float* __restrict__ Kg, const float* __restrict__ Vg,
                            const int* __restrict__ mask)
{
    __shared__ __align__(16) float Qst[64][64];  // [d][r]
    __shared__ __align__(16) float KPs[64][64];  // Kst [d][kc] -> reused as P [r][kc]
    __shared__ __align__(16) float Vs[64][64];   // [kc][n]

    int tid = threadIdx.x;
    int tx = tid & 15, ty = tid >> 4;
    int bh = blockIdx.y;
    int b  = bh >> 4, h = bh & 15;
    int q0 = blockIdx.x << 6;

    const float* qptr = g_q + ((size_t)bh * NS + q0) * HD;
    const float* kptr = Kg + (size_t)bh * NS * HD;
    const float* vptr = Vg + (size_t)bh * NS * HD;
    const int*   mptr = mask + ((size_t)b * NS + q0) * NS;

    // Load Q tile transposed: Qst[d][r].  64 rows x 16 float4 = 1024 loads.
    #pragma unroll
    for (int i = 0; i < 4; i++) {
        int lin = tid + (i << 8);        // 0..1023
        int row = lin >> 4;              // 0..63
        int d4  = (lin & 15) << 2;       // 0..60
        float4 qv = *(const float4*)(qptr + row * HD + d4);
        Qst[d4+0][row] = qv.x; Qst[d4+1][row] = qv.y;
        Qst[d4+2][row] = qv.z; Qst[d4+3][row] = qv.w;
    }

    float m_i[4], l_i[4], o[4][4];
    #pragma unroll
    for (int i = 0; i < 4; i++) {
        m_i[i] = -3.0e38f; l_i[i] = 0.f;
        #pragma unroll
        for (int j = 0; j < 4; j++) o[i][j] = 0.f;
    }

    for (int k0 = 0; k0 < NS; k0 += 64) {
        __syncthreads();  // prior-tile PV reads done; also publishes Qst on iter 0
        #pragma unroll
        for (int i = 0; i < 4; i++) {
            int lin = tid + (i << 8);    // 0..1023
            int row = lin >> 4;          // 0..63 (key index)
            int d4  = (lin & 15) << 2;   // 0..60 (dim)
            float4 kv = *(const float4*)(kptr + (k0 + row) * HD + d4);
            KPs[d4+0][row] = kv.x; KPs[d4+1][row] = kv.y;
            KPs[d4+2][row] = kv.z; KPs[d4+3][row] = kv.w;
            *(float4*)&Vs[row][d4] = *(const float4*)(vptr + (k0 + row) * HD + d4);
        }
        __syncthreads();

        // S = Q K^T (4x4 per thread)
        float sc[4][4];
        #pragma unroll
        for (int i = 0; i < 4; i++)
            #pragma unroll
            for (int j = 0; j < 4; j++) sc[i][j] = 0.f;

        #pragma unroll 8
        for (int d = 0; d < 64; d++) {
            float4 a  = *(const float4*)&Qst[d][ty << 2];
            float4 bb = *(const float4*)&KPs[d][tx << 2];
            float av[4] = {a.x, a.y, a.z, a.w};
            float bv[4] = {bb.x, bb.y, bb.z, bb.w};
            #pragma unroll
            for (int i = 0; i < 4; i++)
                #pragma unroll
                for (int j = 0; j < 4; j++)
                    sc[i][j] += av[i] * bv[j];
        }

        // scale + mask
        #pragma unroll
        for (int i = 0; i < 4; i++) {
            int4 mm = *(const int4*)(mptr + ((ty << 2) + i) * NS + k0 + (tx << 2));
            sc[i][0] = mm.x ? sc[i][0] * 0.125f : -1e30f;
            sc[i][1] = mm.y ? sc[i][1] * 0.125f : -1e30f;
            sc[i][2] = mm.z ? sc[i][2] * 0.125f : -1e30f;
            sc[i][3] = mm.w ? sc[i][3] * 0.125f : -1e30f;
        }

        // online softmax (row spread across 16 tx lanes)
        #pragma unroll
        for (int i = 0; i < 4; i++) {
            float mx = fmaxf(fmaxf(sc[i][0], sc[i][1]), fmaxf(sc[i][2], sc[i][3]));
            mx = fmaxf(mx, __shfl_xor_sync(0xffffffffu, mx, 1));
            mx = fmaxf(mx, __shfl_xor_sync(0xffffffffu, mx, 2));
            mx = fmaxf(mx, __shfl_xor_sync(0xffffffffu, mx, 4));
            mx = fmaxf(mx, __shfl_xor_sync(0xffffffffu, mx, 8));
            float mnew = fmaxf(m_i[i], mx);
            float corr = __expf(m_i[i] - mnew);
            m_i[i] = mnew;
            float ps = 0.f;
            #pragma unroll
            for (int j = 0; j < 4; j++) { sc[i][j] = __expf(sc[i][j] - mnew); ps += sc[i][j]; }
            ps += __shfl_xor_sync(0xffffffffu, ps, 1);
            ps += __shfl_xor_sync(0xffffffffu, ps, 2);
            ps += __shfl_xor_sync(0xffffffffu, ps, 4);
            ps += __shfl_xor_sync(0xffffffffu, ps, 8);
            l_i[i] = l_i[i] * corr + ps;
            #pragma unroll
            for (int j = 0; j < 4; j++) o[i][j] *= corr;
        }

        __syncthreads();   // everyone done reading K tile
        // store P into KPs as [r][kc]
        #pragma unroll
        for (int i = 0; i < 4; i++)
            #pragma unroll
            for (int j = 0; j < 4; j++)
                KPs[(ty << 2) + i][(tx << 2) + j] = sc[i][j];
        __syncthreads();

        // O += P V
        #pragma unroll 4
        for (int kc0 = 0; kc0 < 64; kc0 += 4) {
            float4 pa[4];
            #pragma unroll
            for (int i = 0; i < 4; i++)
                pa[i] = *(const float4*)&KPs[(ty << 2) + i][kc0];
            #pragma unroll
            for (int u = 0; u < 4; u++) {
                float4 vv = *(const float4*)&Vs[kc0 + u][tx << 2];
                float vb[4] = {vv.x, vv.y, vv.z, vv.w};
                #pragma unroll
                for (int i = 0; i < 4; i++) {
                    float pi = ((const float*)&pa[i])[u];
                    #pragma unroll
                    for (int j = 0; j < 4; j++) o[i][j] += pi * vb[j];
                }
            }
        }
    }

    #pragma unroll
    for (int i = 0; i < 4; i++) {
        float inv = 1.0f / l_i[i];
        int srow = q0 + (ty << 2) + i;
        float4 out4 = make_float4(o[i][0] * inv, o[i][1] * inv, o[i][2] * inv, o[i][3] * inv);
        *(float4*)&g_ctx[((size_t)b * NS + srow) * NDIM + h * HD + (tx << 2)] = out4;
    }
}

// ---------------------------------------------------------------------------
extern "C" void kernel_launch(void* const* d_in, const int* in_sizes, int n_in,
                              void* d_out, int out_size) {
    const float* query = (const float*)d_in[0];
    const float* key   = (const float*)d_in[1];
    const float* value = (const float*)d_in[2];
    const int*   mask  = (const int*)d_in[3];
    const float* Wq = (const float*)d_in[4];
    const float* bq = (const float*)d_in[5];
    const float* Wk = (const float*)d_in[6];
    const float* bk = (const float*)d_in[7];
    const float* Wv = (const float*)d_in[8];
    const float* bv = (const float*)d_in[9];
    const float* Wo = (const float*)d_in[10];
    const float* bo = (const float*)d_in[11];

    float* out  = (float*)d_out;                 // [B,S,1024]
    float* outK = out + OUT_ELEMS;               // [B,H,S,64] (post-RoPE k)
    float* outV = out + 2 * (size_t)OUT_ELEMS;   // [B,H,S,64] (v)

    float* g_q_p;   cudaGetSymbolAddress((void**)&g_q_p, g_q);
    float* g_ctx_p; cudaGetSymbolAddress((void**)&g_ctx_p, g_ctx);

    rope_table_kernel<<<(NS * 32 + 255) / 256, 256>>>();

    dim3 lgrid(NDIM / 64, NM / 64);
    linear64_kernel<<<lgrid, 256>>>(query, Wq, bq, g_q_p, 1);
    linear64_kernel<<<lgrid, 256>>>(key,   Wk, bk, outK,  1);
    linear64_kernel<<<lgrid, 256>>>(value, Wv, bv, outV,  1);

    dim3 rgrid((NB * NH * NS * 32) / 256, 2);
    rope_apply_kernel<<<rgrid, 256>>>(outK);

    dim3 agrid(NS / 64, NB * NH);
    attn_kernel<<<agrid, 256>>>(outK, outV, mask);

    linear64_kernel<<<lgrid, 256>>>(g_ctx_p, Wo, bo, out, 0);
}

// round 3
// speedup vs baseline: 1.1859x; 1.1859x over previous
#include <cuda_runtime.h>
#include <math.h>

#define NB 2
#define NS 2048
#define NH 16
#define HD 64
#define NDIM 1024
#define NM (NB*NS)
#define OUT_ELEMS (NB*NS*NDIM)   // 4194304 per tensor (out, k, v)

// Scratch (allocation-free rule: __device__ globals)
__device__ float g_q[NB*NH*NS*HD];     // q after proj (+RoPE), [b,h,s,d]
__device__ float g_ctx[NB*NS*NDIM];    // attention context, [b,s, h*64+d] flat
__device__ float g_cos[NS*32];
__device__ float g_sin[NS*32];

// ---------------------------------------------------------------------------
// RoPE tables
// ---------------------------------------------------------------------------
__global__ void rope_table_kernel() {
    int idx = blockIdx.x * blockDim.x + threadIdx.x;
    if (idx >= NS * 32) return;
    int s = idx >> 5, j = idx & 31;
    float invf = (float)exp(-(double)j * (log(10000.0) / 32.0));
    float ang = (float)s * invf;       // fp32 rounding like the reference
    g_cos[idx] = (float)cos((double)ang);
    g_sin[idx] = (float)sin((double)ang);
}

__global__ void rope_apply_kernel(float* __restrict__ kptr) {
    int idx = blockIdx.x * blockDim.x + threadIdx.x;   // NB*NH*NS*32 threads
    float* p = blockIdx.y ? kptr : g_q;
    int j = idx & 31;
    int row = idx >> 5;                // bh*NS + s
    int s = row & (NS - 1);
    int base = row * 64 + j;
    float c = g_cos[(s << 5) + j], sn = g_sin[(s << 5) + j];
    float x1 = p[base], x2 = p[base + 32];
    p[base]      = x1 * c - x2 * sn;
    p[base + 32] = x2 * c + x1 * sn;
}

// ---------------------------------------------------------------------------
// y = A @ W^T + bias.  128x128 block, 8x8 micro-tile, k-step 8, double buffer.
// A: [M,1024] row-major, W: [N,1024] row-major (both K-contiguous).
// headLayout=1: scatter into [b,h,s,d]; headLayout=0: flat [m,n].
// ---------------------------------------------------------------------------
__global__ __launch_bounds__(256, 2)
void linear128_kernel(const float* __restrict__ A, const float* __restrict__ W,
                      const float* __restrict__ bias, float* __restrict__ dst,
                      int headLayout)
{
    __shared__ __align__(16) float As[2][8][132];   // [buf][k][m]
    __shared__ __align__(16) float Bs[2][8][132];   // [buf][k][n]

    int tid = threadIdx.x;
    int tx = tid & 15, ty = tid >> 4;
    int m0 = blockIdx.y << 7, n0 = blockIdx.x << 7;

    int lrow  = tid >> 1;       // 0..127
    int lhalf = tid & 1;        // which float4 of the 8-wide k-slice
    const float* aptr = A + (size_t)(m0 + lrow) * NDIM + (lhalf << 2);
    const float* bptr = W + (size_t)(n0 + lrow) * NDIM + (lhalf << 2);

    float acc[8][8];
    #pragma unroll
    for (int i = 0; i < 8; i++)
        #pragma unroll
        for (int j = 0; j < 8; j++) acc[i][j] = 0.f;

    float4 ra = *(const float4*)(aptr);
    float4 rb = *(const float4*)(bptr);
    int kb = lhalf << 2;
    As[0][kb+0][lrow] = ra.x; As[0][kb+1][lrow] = ra.y;
    As[0][kb+2][lrow] = ra.z; As[0][kb+3][lrow] = ra.w;
    Bs[0][kb+0][lrow] = rb.x; Bs[0][kb+1][lrow] = rb.y;
    Bs[0][kb+2][lrow] = rb.z; Bs[0][kb+3][lrow] = rb.w;
    __syncthreads();

    int buf = 0;
    for (int kt = 0; kt < NDIM / 8; kt++) {
        if (kt < NDIM / 8 - 1) {
            ra = *(const float4*)(aptr + (kt + 1) * 8);
            rb = *(const float4*)(bptr + (kt + 1) * 8);
        }
        #pragma unroll
        for (int kk = 0; kk < 8; kk++) {
            float a[8], b[8];
            *(float4*)&a[0] = *(const float4*)&As[buf][kk][ty << 3];
            *(float4*)&a[4] = *(const float4*)&As[buf][kk][(ty << 3) + 4];
            *(float4*)&b[0] = *(const float4*)&Bs[buf][kk][tx << 3];
            *(float4*)&b[4] = *(const float4*)&Bs[buf][kk][(tx << 3) + 4];
            #pragma unroll
            for (int i = 0; i < 8; i++)
                #pragma unroll
                for (int j = 0; j < 8; j++)
                    acc[i][j] += a[i] * b[j];
        }
        if (kt < NDIM / 8 - 1) {
            int nb = buf ^ 1;
            As[nb][kb+0][lrow] = ra.x; As[nb][kb+1][lrow] = ra.y;
            As[nb][kb+2][lrow] = ra.z; As[nb][kb+3][lrow] = ra.w;
            Bs[nb][kb+0][lrow] = rb.x; Bs[nb][kb+1][lrow] = rb.y;
            Bs[nb][kb+2][lrow] = rb.z; Bs[nb][kb+3][lrow] = rb.w;
            __syncthreads();
            buf = nb;
        }
    }

    #pragma unroll
    for (int i = 0; i < 8; i++) {
        int m = m0 + (ty << 3) + i;
        #pragma unroll
        for (int j4 = 0; j4 < 8; j4 += 4) {
            int n = n0 + (tx << 3) + j4;
            float4 v;
            v.x = acc[i][j4+0] + bias[n+0];
            v.y = acc[i][j4+1] + bias[n+1];
            v.z = acc[i][j4+2] + bias[n+2];
            v.w = acc[i][j4+3] + bias[n+3];
            if (headLayout) {
                int b = m >> 11, s = m & (NS - 1);
                int h = n >> 6, d = n & 63;   // 4-col group never crosses a head
                *(float4*)&dst[(((size_t)((b << 4) + h) * NS + s)) * HD + d] = v;
            } else {
                *(float4*)&dst[(size_t)m * NDIM + n] = v;
            }
        }
    }
}

// ---------------------------------------------------------------------------
// Flash attention: one block = one (b,h) and 128 query rows; 64-key tiles.
// 256 threads; thread (tx,ty) owns 8 q-rows x 4 cols (S and O micro-tiles).
// Dynamic smem: Qst[64][132] | KP[128][68] (K tile, reused for P) | Vs[64][68].
// ---------------------------------------------------------------------------
#define QST(d,r) Qst[(d)*132+(r)]
#define KPm(a,c) KP[(a)*68+(c)]
#define VSm(k,n) Vs[(k)*68+(n)]
#define ATTN_SMEM ((64*132 + 128*68 + 64*68) * 4)

__global__ __launch_bounds__(256, 2)
void attn_kernel(const float* __restrict__ Kg, const float* __restrict__ Vg,
                 const int* __restrict__ mask)
{
    extern __shared__ __align__(16) float sm_attn[];
    float* Qst = sm_attn;              // [64][132]  (q transposed: [d][r])
    float* KP  = sm_attn + 64*132;     // K as [d][kc] (d<64) -> P as [r][kc]
    float* Vs  = KP + 128*68;          // [kc][n]

    int tid = threadIdx.x;
    int tx = tid & 15, ty = tid >> 4;
    int bh = blockIdx.y;
    int b  = bh >> 4, h = bh & 15;
    int q0 = blockIdx.x << 7;

    const float* qptr = g_q + ((size_t)bh * NS + q0) * HD;
    const float* kptr = Kg + (size_t)bh * NS * HD;
    const float* vptr = Vg + (size_t)bh * NS * HD;
    const int*   mptr = mask + ((size_t)b * NS + q0) * NS;

    // Load Q tile transposed: 128 rows x 16 float4 = 2048 loads, 8/thread.
    #pragma unroll
    for (int i = 0; i < 8; i++) {
        int lin = tid + (i << 8);
        int row = lin >> 4;              // 0..127
        int d4  = (lin & 15) << 2;       // 0..60
        float4 qv = *(const float4*)(qptr + row * HD + d4);
        QST(d4+0, row) = qv.x; QST(d4+1, row) = qv.y;
        QST(d4+2, row) = qv.z; QST(d4+3, row) = qv.w;
    }

    float m_i[8], l_i[8], o[8][4];
    #pragma unroll
    for (int i = 0; i < 8; i++) {
        m_i[i] = -3.0e38f; l_i[i] = 0.f;
        #pragma unroll
        for (int j = 0; j < 4; j++) o[i][j] = 0.f;
    }

    for (int k0 = 0; k0 < NS; k0 += 64) {
        __syncthreads();   // prior-tile P readers done; publishes Qst on iter 0
        #pragma unroll
        for (int i = 0; i < 4; i++) {
            int lin = tid + (i << 8);    // 0..1023
            int row = lin >> 4;          // 0..63 (key index)
            int d4  = (lin & 15) << 2;   // 0..60 (dim)
            float4 kv = *(const float4*)(kptr + (k0 + row) * HD + d4);
            KPm(d4+0, row) = kv.x; KPm(d4+1, row) = kv.y;
            KPm(d4+2, row) = kv.z; KPm(d4+3, row) = kv.w;
            *(float4*)&VSm(row, d4) = *(const float4*)(vptr + (k0 + row) * HD + d4);
        }
        __syncthreads();

        // S = Q K^T : 8x4 per thread
        float sc[8][4];
        #pragma unroll
        for (int i = 0; i < 8; i++)
            #pragma unroll
            for (int j = 0; j < 4; j++) sc[i][j] = 0.f;

        #pragma unroll 16
        for (int d = 0; d < 64; d++) {
            float a[8], bv[4];
            *(float4*)&a[0] = *(const float4*)&QST(d, ty << 3);
            *(float4*)&a[4] = *(const float4*)&QST(d, (ty << 3) + 4);
            *(float4*)&bv[0] = *(const float4*)&KPm(d, tx << 2);
            #pragma unroll
            for (int i = 0; i < 8; i++)
                #pragma unroll
                for (int j = 0; j < 4; j++)
                    sc[i][j] += a[i] * bv[j];
        }

        // scale + mask + online softmax
        #pragma unroll
        for (int i = 0; i < 8; i++) {
            int4 mm = *(const int4*)(mptr + ((ty << 3) + i) * NS + k0 + (tx << 2));
            sc[i][0] = mm.x ? sc[i][0] * 0.125f : -1e30f;
            sc[i][1] = mm.y ? sc[i][1] * 0.125f : -1e30f;
            sc[i][2] = mm.z ? sc[i][2] * 0.125f : -1e30f;
            sc[i][3] = mm.w ? sc[i][3] * 0.125f : -1e30f;

            float mx = fmaxf(fmaxf(sc[i][0], sc[i][1]), fmaxf(sc[i][2], sc[i][3]));
            mx = fmaxf(mx, __shfl_xor_sync(0xffffffffu, mx, 1));
            mx = fmaxf(mx, __shfl_xor_sync(0xffffffffu, mx, 2));
            mx = fmaxf(mx, __shfl_xor_sync(0xffffffffu, mx, 4));
            mx = fmaxf(mx, __shfl_xor_sync(0xffffffffu, mx, 8));
            float mnew = fmaxf(m_i[i], mx);
            float corr = __expf(m_i[i] - mnew);
            m_i[i] = mnew;
            float ps = 0.f;
            #pragma unroll
            for (int j = 0; j < 4; j++) { sc[i][j] = __expf(sc[i][j] - mnew); ps += sc[i][j]; }
            ps += __shfl_xor_sync(0xffffffffu, ps, 1);
            ps += __shfl_xor_sync(0xffffffffu, ps, 2);
            ps += __shfl_xor_sync(0xffffffffu, ps, 4);
            ps += __shfl_xor_sync(0xffffffffu, ps, 8);
            l_i[i] = l_i[i] * corr + ps;
            #pragma unroll
            for (int j = 0; j < 4; j++) o[i][j] *= corr;
        }

        __syncthreads();   // all threads done reading K tile
        #pragma unroll
        for (int i = 0; i < 8; i++)
            *(float4*)&KPm((ty << 3) + i, tx << 2) = *(float4*)&sc[i][0];
        __syncthreads();

        // O += P V
        #pragma unroll 4
        for (int kc0 = 0; kc0 < 64; kc0 += 4) {
            float4 pa[8];
            #pragma unroll
            for (int i = 0; i < 8; i++)
                pa[i] = *(const float4*)&KPm((ty << 3) + i, kc0);
            #pragma unroll
            for (int u = 0; u < 4; u++) {
                float4 vv = *(const float4*)&VSm(kc0 + u, tx << 2);
                float vb[4] = {vv.x, vv.y, vv.z, vv.w};
                #pragma unroll
                for (int i = 0; i < 8; i++) {
                    float pi = ((const float*)&pa[i])[u];
                    #pragma unroll
                    for (int j = 0; j < 4; j++) o[i][j] += pi * vb[j];
                }
            }
        }
    }

    #pragma unroll
    for (int i = 0; i < 8; i++) {
        float inv = 1.0f / l_i[i];
        int srow = q0 + (ty << 3) + i;
        float4 out4 = make_float4(o[i][0] * inv, o[i][1] * inv, o[i][2] * inv, o[i][3] * inv);
        *(float4*)&g_ctx[((size_t)b * NS + srow) * NDIM + h * HD + (tx << 2)] = out4;
    }
}

// ---------------------------------------------------------------------------
extern "C" void kernel_launch(void* const* d_in, const int* in_sizes, int n_in,
                              void* d_out, int out_size) {
    const float* query = (const float*)d_in[0];
    const float* key   = (const float*)d_in[1];
    const float* value = (const float*)d_in[2];
    const int*   mask  = (const int*)d_in[3];
    const float* Wq = (const float*)d_in[4];
    const float* bq = (const float*)d_in[5];
    const float* Wk = (const float*)d_in[6];
    const float* bk = (const float*)d_in[7];
    const float* Wv = (const float*)d_in[8];
    const float* bv = (const float*)d_in[9];
    const float* Wo = (const float*)d_in[10];
    const float* bo = (const float*)d_in[11];

    float* out  = (float*)d_out;                 // [B,S,1024]
    float* outK = out + OUT_ELEMS;               // [B,H,S,64] (post-RoPE k)
    float* outV = out + 2 * (size_t)OUT_ELEMS;   // [B,H,S,64] (v)

    float* g_q_p;   cudaGetSymbolAddress((void**)&g_q_p, g_q);
    float* g_ctx_p; cudaGetSymbolAddress((void**)&g_ctx_p, g_ctx);

    static int attn_smem_set = 0;
    if (!attn_smem_set) {
        cudaFuncSetAttribute(attn_kernel, cudaFuncAttributeMaxDynamicSharedMemorySize,
                             ATTN_SMEM);
        attn_smem_set = 1;
    }

    rope_table_kernel<<<(NS * 32 + 255) / 256, 256>>>();

    dim3 lgrid(NDIM / 128, NM / 128);   // (8, 32)
    linear128_kernel<<<lgrid, 256>>>(query, Wq, bq, g_q_p, 1);
    linear128_kernel<<<lgrid, 256>>>(key,   Wk, bk, outK,  1);
    linear128_kernel<<<lgrid, 256>>>(value, Wv, bv, outV,  1);

    dim3 rgrid((NB * NH * NS * 32) / 256, 2);
    rope_apply_kernel<<<rgrid, 256>>>(outK);

    dim3 agrid(NS / 128, NB * NH);      // (16, 32)
    attn_kernel<<<agrid, 256, ATTN_SMEM>>>(outK, outV, mask);

    linear128_kernel<<<lgrid, 256>>>(g_ctx_p, Wo, bo, out, 0);
}

// round 4
// speedup vs baseline: 1.6714x; 1.4094x over previous
#include <cuda_runtime.h>
#include <math.h>

#define NB 2
#define NS 2048
#define NH 16
#define HD 64
#define NDIM 1024
#define NM (NB*NS)
#define OUT_ELEMS (NB*NS*NDIM)   // 4194304 per tensor (out, k, v)

// Scratch (allocation-free rule: __device__ globals)
__device__ float g_q[NB*NH*NS*HD];     // q after proj (+RoPE), [b,h,s,d]
__device__ float g_ctx[NB*NS*NDIM];    // attention context, [b,s, h*64+d] flat
__device__ float g_cos[NS*32];
__device__ float g_sin[NS*32];

__device__ __forceinline__ unsigned f2tf32(float x) {
    unsigned r; asm("cvt.rna.tf32.f32 %0, %1;" : "=r"(r) : "f"(x)); return r;
}
__device__ __forceinline__ void mma_tf32(float c[4], unsigned a0, unsigned a1,
                                         unsigned a2, unsigned a3,
                                         unsigned b0, unsigned b1) {
    asm volatile(
        "mma.sync.aligned.m16n8k8.row.col.f32.tf32.tf32.f32 "
        "{%0,%1,%2,%3}, {%4,%5,%6,%7}, {%8,%9}, {%0,%1,%2,%3};"
        : "+f"(c[0]), "+f"(c[1]), "+f"(c[2]), "+f"(c[3])
        : "r"(a0), "r"(a1), "r"(a2), "r"(a3), "r"(b0), "r"(b1));
}

// ---------------------------------------------------------------------------
// RoPE tables
// ---------------------------------------------------------------------------
__global__ void rope_table_kernel() {
    int idx = blockIdx.x * blockDim.x + threadIdx.x;
    if (idx >= NS * 32) return;
    int s = idx >> 5, j = idx & 31;
    float invf = (float)exp(-(double)j * (log(10000.0) / 32.0));
    float ang = (float)s * invf;       // fp32 rounding like the reference
    g_cos[idx] = (float)cos((double)ang);
    g_sin[idx] = (float)sin((double)ang);
}

__global__ void rope_apply_kernel(float* __restrict__ kptr) {
    int idx = blockIdx.x * blockDim.x + threadIdx.x;   // NB*NH*NS*32 threads
    float* p = blockIdx.y ? kptr : g_q;
    int j = idx & 31;
    int row = idx >> 5;                // bh*NS + s
    int s = row & (NS - 1);
    int base = row * 64 + j;
    float c = g_cos[(s << 5) + j], sn = g_sin[(s << 5) + j];
    float x1 = p[base], x2 = p[base + 32];
    p[base]      = x1 * c - x2 * sn;
    p[base + 32] = x2 * c + x1 * sn;
}

// ---------------------------------------------------------------------------
// TF32 tensor-core linear: y = A @ W^T + bias.
// 128x128 CTA tile, 8 warps as 2(m) x 4(n); warp tile 64x32 via m16n8k8.
// smem stages k=16, double buffered, [row][20] padding (conflict-free for
// both frag patterns). Inputs tf32-converted on smem store; fp32 accum.
// ---------------------------------------------------------------------------
#define KS 16
#define LPAD 20

__global__ __launch_bounds__(256, 2)
void linear_tc_kernel(const float* __restrict__ A, const float* __restrict__ W,
                      const float* __restrict__ bias, float* __restrict__ dst,
                      int headLayout)
{
    __shared__ unsigned As[2][128][LPAD];
    __shared__ unsigned Ws[2][128][LPAD];

    int tid  = threadIdx.x;
    int w    = tid >> 5;
    int lane = tid & 31;
    int grp  = lane >> 2;       // 0..7
    int qid  = lane & 3;        // 0..3
    int wm   = (w >> 2) * 64;   // warp m offset (0/64)
    int wn   = (w & 3) * 32;    // warp n offset (0/32/64/96)

    int m0 = blockIdx.y << 7, n0 = blockIdx.x << 7;

    int lrow  = tid >> 1;          // 0..127
    int kbase = (tid & 1) * 8;     // 0 or 8
    const float* aptr = A + (size_t)(m0 + lrow) * NDIM + kbase;
    const float* bptr = W + (size_t)(n0 + lrow) * NDIM + kbase;

    float acc[4][4][4];
    #pragma unroll
    for (int mt = 0; mt < 4; mt++)
        #pragma unroll
        for (int nt = 0; nt < 4; nt++)
            #pragma unroll
            for (int r = 0; r < 4; r++) acc[mt][nt][r] = 0.f;

    // prefetch stage 0
    float4 ra0 = *(const float4*)(aptr);
    float4 ra1 = *(const float4*)(aptr + 4);
    float4 rb0 = *(const float4*)(bptr);
    float4 rb1 = *(const float4*)(bptr + 4);

    {
        unsigned* as = &As[0][lrow][kbase];
        as[0]=f2tf32(ra0.x); as[1]=f2tf32(ra0.y); as[2]=f2tf32(ra0.z); as[3]=f2tf32(ra0.w);
        as[4]=f2tf32(ra1.x); as[5]=f2tf32(ra1.y); as[6]=f2tf32(ra1.z); as[7]=f2tf32(ra1.w);
        unsigned* ws = &Ws[0][lrow][kbase];
        ws[0]=f2tf32(rb0.x); ws[1]=f2tf32(rb0.y); ws[2]=f2tf32(rb0.z); ws[3]=f2tf32(rb0.w);
        ws[4]=f2tf32(rb1.x); ws[5]=f2tf32(rb1.y); ws[6]=f2tf32(rb1.z); ws[7]=f2tf32(rb1.w);
    }
    __syncthreads();

    int buf = 0;
    const int NKT = NDIM / KS;          // 64 stages
    for (int kt = 0; kt < NKT; kt++) {
        if (kt < NKT - 1) {
            const float* ap = aptr + (kt + 1) * KS;
            const float* bp = bptr + (kt + 1) * KS;
            ra0 = *(const float4*)(ap);
            ra1 = *(const float4*)(ap + 4);
            rb0 = *(const float4*)(bp);
            rb1 = *(const float4*)(bp + 4);
        }

        #pragma unroll
        for (int sl = 0; sl < 2; sl++) {
            int kk = sl * 8;
            unsigned afr[4][4], bfr[4][2];
            #pragma unroll
            for (int mt = 0; mt < 4; mt++) {
                const unsigned* ar = &As[buf][wm + mt*16 + grp][kk + qid];
                afr[mt][0] = ar[0];                 // (grp,      qid)
                afr[mt][1] = ar[8 * LPAD];          // (grp+8,    qid)
                afr[mt][2] = ar[4];                 // (grp,      qid+4)
                afr[mt][3] = ar[8 * LPAD + 4];      // (grp+8,    qid+4)
            }
            #pragma unroll
            for (int nt = 0; nt < 4; nt++) {
                const unsigned* br = &Ws[buf][wn + nt*8 + grp][kk + qid];
                bfr[nt][0] = br[0];                 // (k=qid,   n=grp)
                bfr[nt][1] = br[4];                 // (k=qid+4, n=grp)
            }
            #pragma unroll
            for (int mt = 0; mt < 4; mt++)
                #pragma unroll
                for (int nt = 0; nt < 4; nt++)
                    mma_tf32(acc[mt][nt], afr[mt][0], afr[mt][1], afr[mt][2], afr[mt][3],
                             bfr[nt][0], bfr[nt][1]);
        }

        if (kt < NKT - 1) {
            int nb = buf ^ 1;
            unsigned* as = &As[nb][lrow][kbase];
            as[0]=f2tf32(ra0.x); as[1]=f2tf32(ra0.y); as[2]=f2tf32(ra0.z); as[3]=f2tf32(ra0.w);
            as[4]=f2tf32(ra1.x); as[5]=f2tf32(ra1.y); as[6]=f2tf32(ra1.z); as[7]=f2tf32(ra1.w);
            unsigned* ws = &Ws[nb][lrow][kbase];
            ws[0]=f2tf32(rb0.x); ws[1]=f2tf32(rb0.y); ws[2]=f2tf32(rb0.z); ws[3]=f2tf32(rb0.w);
            ws[4]=f2tf32(rb1.x); ws[5]=f2tf32(rb1.y); ws[6]=f2tf32(rb1.z); ws[7]=f2tf32(rb1.w);
            __syncthreads();
            buf = nb;
        }
    }

    // epilogue: c0,c1 -> (grp, 2*qid(+1)); c2,c3 -> (grp+8, 2*qid(+1))
    #pragma unroll
    for (int mt = 0; mt < 4; mt++) {
        #pragma unroll
        for (int nt = 0; nt < 4; nt++) {
            int n = n0 + wn + nt * 8 + (qid << 1);
            float bx = bias[n], by = bias[n + 1];
            #pragma unroll
            for (int half = 0; half < 2; half++) {
                int m = m0 + wm + mt * 16 + grp + half * 8;
                float2 v;
                v.x = acc[mt][nt][half * 2 + 0] + bx;
                v.y = acc[mt][nt][half * 2 + 1] + by;
                if (headLayout) {
                    int b = m >> 11, s = m & (NS - 1);
                    int h = n >> 6, d = n & 63;
                    *(float2*)&dst[(((size_t)((b << 4) + h) * NS + s)) * HD + d] = v;
                } else {
                    *(float2*)&dst[(size_t)m * NDIM + n] = v;
                }
            }
        }
    }
}

// ---------------------------------------------------------------------------
// Flash attention (fp32 SIMT, unchanged from R3): BQ=128, BK=64, 8x4 micro.
// ---------------------------------------------------------------------------
#define QST(d,r) Qst[(d)*132+(r)]
#define KPm(a,c) KP[(a)*68+(c)]
#define VSm(k,n) Vs[(k)*68+(n)]
#define ATTN_SMEM ((64*132 + 128*68 + 64*68) * 4)

__global__ __launch_bounds__(256, 2)
void attn_kernel(const float* __restrict__ Kg, const float* __restrict__ Vg,
                 const int* __restrict__ mask)
{
    extern __shared__ __align__(16) float sm_attn[];
    float* Qst = sm_attn;              // [64][132]  (q transposed: [d][r])
    float* KP  = sm_attn + 64*132;     // K as [d][kc] (d<64) -> P as [r][kc]
    float* Vs  = KP + 128*68;          // [kc][n]

    int tid = threadIdx.x;
    int tx = tid & 15, ty = tid >> 4;
    int bh = blockIdx.y;
    int b  = bh >> 4, h = bh & 15;
    int q0 = blockIdx.x << 7;

    const float* qptr = g_q + ((size_t)bh * NS + q0) * HD;
    const float* kptr = Kg + (size_t)bh * NS * HD;
    const float* vptr = Vg + (size_t)bh * NS * HD;
    const int*   mptr = mask + ((size_t)b * NS + q0) * NS;

    #pragma unroll
    for (int i = 0; i < 8; i++) {
        int lin = tid + (i << 8);
        int row = lin >> 4;              // 0..127
        int d4  = (lin & 15) << 2;       // 0..60
        float4 qv = *(const float4*)(qptr + row * HD + d4);
        QST(d4+0, row) = qv.x; QST(d4+1, row) = qv.y;
        QST(d4+2, row) = qv.z; QST(d4+3, row) = qv.w;
    }

    float m_i[8], l_i[8], o[8][4];
    #pragma unroll
    for (int i = 0; i < 8; i++) {
        m_i[i] = -3.0e38f; l_i[i] = 0.f;
        #pragma unroll
        for (int j = 0; j < 4; j++) o[i][j] = 0.f;
    }

    for (int k0 = 0; k0 < NS; k0 += 64) {
        __syncthreads();
        #pragma unroll
        for (int i = 0; i < 4; i++) {
            int lin = tid + (i << 8);
            int row = lin >> 4;
            int d4  = (lin & 15) << 2;
            float4 kv = *(const float4*)(kptr + (k0 + row) * HD + d4);
            KPm(d4+0, row) = kv.x; KPm(d4+1, row) = kv.y;
            KPm(d4+2, row) = kv.z; KPm(d4+3, row) = kv.w;
            *(float4*)&VSm(row, d4) = *(const float4*)(vptr + (k0 + row) * HD + d4);
        }
        __syncthreads();

        float sc[8][4];
        #pragma unroll
        for (int i = 0; i < 8; i++)
            #pragma unroll
            for (int j = 0; j < 4; j++) sc[i][j] = 0.f;

        #pragma unroll 16
        for (int d = 0; d < 64; d++) {
            float a[8], bv[4];
            *(float4*)&a[0] = *(const float4*)&QST(d, ty << 3);
            *(float4*)&a[4] = *(const float4*)&QST(d, (ty << 3) + 4);
            *(float4*)&bv[0] = *(const float4*)&KPm(d, tx << 2);
            #pragma unroll
            for (int i = 0; i < 8; i++)
                #pragma unroll
                for (int j = 0; j < 4; j++)
                    sc[i][j] += a[i] * bv[j];
        }

        #pragma unroll
        for (int i = 0; i < 8; i++) {
            int4 mm = *(const int4*)(mptr + ((ty << 3) + i) * NS + k0 + (tx << 2));
            sc[i][0] = mm.x ? sc[i][0] * 0.125f : -1e30f;
            sc[i][1] = mm.y ? sc[i][1] * 0.125f : -1e30f;
            sc[i][2] = mm.z ? sc[i][2] * 0.125f : -1e30f;
            sc[i][3] = mm.w ? sc[i][3] * 0.125f : -1e30f;

            float mx = fmaxf(fmaxf(sc[i][0], sc[i][1]), fmaxf(sc[i][2], sc[i][3]));
            mx = fmaxf(mx, __shfl_xor_sync(0xffffffffu, mx, 1));
            mx = fmaxf(mx, __shfl_xor_sync(0xffffffffu, mx, 2));
            mx = fmaxf(mx, __shfl_xor_sync(0xffffffffu, mx, 4));
            mx = fmaxf(mx, __shfl_xor_sync(0xffffffffu, mx, 8));
            float mnew = fmaxf(m_i[i], mx);
            float corr = __expf(m_i[i] - mnew);
            m_i[i] = mnew;
            float ps = 0.f;
            #pragma unroll
            for (int j = 0; j < 4; j++) { sc[i][j] = __expf(sc[i][j] - mnew); ps += sc[i][j]; }
            ps += __shfl_xor_sync(0xffffffffu, ps, 1);
            ps += __shfl_xor_sync(0xffffffffu, ps, 2);
            ps += __shfl_xor_sync(0xffffffffu, ps, 4);
            ps += __shfl_xor_sync(0xffffffffu, ps, 8);
            l_i[i] = l_i[i] * corr + ps;
            #pragma unroll
            for (int j = 0; j < 4; j++) o[i][j] *= corr;
        }

        __syncthreads();
        #pragma unroll
        for (int i = 0; i < 8; i++)
            *(float4*)&KPm((ty << 3) + i, tx << 2) = *(float4*)&sc[i][0];
        __syncthreads();

        #pragma unroll 4
        for (int kc0 = 0; kc0 < 64; kc0 += 4) {
            float4 pa[8];
            #pragma unroll
            for (int i = 0; i < 8; i++)
                pa[i] = *(const float4*)&KPm((ty << 3) + i, kc0);
            #pragma unroll
            for (int u = 0; u < 4; u++) {
                float4 vv = *(const float4*)&VSm(kc0 + u, tx << 2);
                float vb[4] = {vv.x, vv.y, vv.z, vv.w};
                #pragma unroll
                for (int i = 0; i < 8; i++) {
                    float pi = ((const float*)&pa[i])[u];
                    #pragma unroll
                    for (int j = 0; j < 4; j++) o[i][j] += pi * vb[j];
                }
            }
        }
    }

    #pragma unroll
    for (int i = 0; i < 8; i++) {
        float inv = 1.0f / l_i[i];
        int srow = q0 + (ty << 3) + i;
        float4 out4 = make_float4(o[i][0] * inv, o[i][1] * inv, o[i][2] * inv, o[i][3] * inv);
        *(float4*)&g_ctx[((size_t)b * NS + srow) * NDIM + h * HD + (tx << 2)] = out4;
    }
}

// ---------------------------------------------------------------------------
extern "C" void kernel_launch(void* const* d_in, const int* in_sizes, int n_in,
                              void* d_out, int out_size) {
    const float* query = (const float*)d_in[0];
    const float* key   = (const float*)d_in[1];
    const float* value = (const float*)d_in[2];
    const int*   mask  = (const int*)d_in[3];
    const float* Wq = (const float*)d_in[4];
    const float* bq = (const float*)d_in[5];
    const float* Wk = (const float*)d_in[6];
    const float* bk = (const float*)d_in[7];
    const float* Wv = (const float*)d_in[8];
    const float* bv = (const float*)d_in[9];
    const float* Wo = (const float*)d_in[10];
    const float* bo = (const float*)d_in[11];

    float* out  = (float*)d_out;                 // [B,S,1024]
    float* outK = out + OUT_ELEMS;               // [B,H,S,64] (post-RoPE k)
    float* outV = out + 2 * (size_t)OUT_ELEMS;   // [B,H,S,64] (v)

    float* g_q_p;   cudaGetSymbolAddress((void**)&g_q_p, g_q);
    float* g_ctx_p; cudaGetSymbolAddress((void**)&g_ctx_p, g_ctx);

    static int attn_smem_set = 0;
    if (!attn_smem_set) {
        cudaFuncSetAttribute(attn_kernel, cudaFuncAttributeMaxDynamicSharedMemorySize,
                             ATTN_SMEM);
        attn_smem_set = 1;
    }

    rope_table_kernel<<<(NS * 32 + 255) / 256, 256>>>();

    dim3 lgrid(NDIM / 128, NM / 128);   // (8, 32)
    linear_tc_kernel<<<lgrid, 256>>>(query, Wq, bq, g_q_p, 1);
    linear_tc_kernel<<<lgrid, 256>>>(key,   Wk, bk, outK,  1);
    linear_tc_kernel<<<lgrid, 256>>>(value, Wv, bv, outV,  1);

    dim3 rgrid((NB * NH * NS * 32) / 256, 2);
    rope_apply_kernel<<<rgrid, 256>>>(outK);

    dim3 agrid(NS / 128, NB * NH);      // (16, 32)
    attn_kernel<<<agrid, 256, ATTN_SMEM>>>(outK, outV, mask);

    linear_tc_kernel<<<lgrid, 256>>>(g_ctx_p, Wo, bo, out, 0);
}

// round 5
// speedup vs baseline: 2.5306x; 1.5141x over previous
#include <cuda_runtime.h>
#include <math.h>

#define NB 2
#define NS 2048
#define NH 16
#define HD 64
#define NDIM 1024
#define NM (NB*NS)
#define OUT_ELEMS (NB*NS*NDIM)   // 4194304 per tensor (out, k, v)

// Scratch (allocation-free rule: __device__ globals)
__device__ float g_q[NB*NH*NS*HD];     // q after proj (+RoPE), [b,h,s,d]
__device__ float g_ctx[NB*NS*NDIM];    // attention context, [b,s, h*64+d] flat
__device__ float g_cos[NS*32];
__device__ float g_sin[NS*32];

__device__ __forceinline__ unsigned f2tf32(float x) {
    unsigned r; asm("cvt.rna.tf32.f32 %0, %1;" : "=r"(r) : "f"(x)); return r;
}
__device__ __forceinline__ void mma_tf32(float c[4], unsigned a0, unsigned a1,
                                         unsigned a2, unsigned a3,
                                         unsigned b0, unsigned b1) {
    asm volatile(
        "mma.sync.aligned.m16n8k8.row.col.f32.tf32.tf32.f32 "
        "{%0,%1,%2,%3}, {%4,%5,%6,%7}, {%8,%9}, {%0,%1,%2,%3};"
        : "+f"(c[0]), "+f"(c[1]), "+f"(c[2]), "+f"(c[3])
        : "r"(a0), "r"(a1), "r"(a2), "r"(a3), "r"(b0), "r"(b1));
}

// ---------------------------------------------------------------------------
// RoPE tables
// ---------------------------------------------------------------------------
__global__ void rope_table_kernel() {
    int idx = blockIdx.x * blockDim.x + threadIdx.x;
    if (idx >= NS * 32) return;
    int s = idx >> 5, j = idx & 31;
    float invf = (float)exp(-(double)j * (log(10000.0) / 32.0));
    float ang = (float)s * invf;       // fp32 rounding like the reference
    g_cos[idx] = (float)cos((double)ang);
    g_sin[idx] = (float)sin((double)ang);
}

__global__ void rope_apply_kernel(float* __restrict__ kptr) {
    int idx = blockIdx.x * blockDim.x + threadIdx.x;   // NB*NH*NS*32 threads
    float* p = blockIdx.y ? kptr : g_q;
    int j = idx & 31;
    int row = idx >> 5;                // bh*NS + s
    int s = row & (NS - 1);
    int base = row * 64 + j;
    float c = g_cos[(s << 5) + j], sn = g_sin[(s << 5) + j];
    float x1 = p[base], x2 = p[base + 32];
    p[base]      = x1 * c - x2 * sn;
    p[base + 32] = x2 * c + x1 * sn;
}

// ---------------------------------------------------------------------------
// TF32 tensor-core linear (unchanged from R4).
// ---------------------------------------------------------------------------
#define KS 16
#define LPAD 20

__global__ __launch_bounds__(256, 2)
void linear_tc_kernel(const float* __restrict__ A, const float* __restrict__ W,
                      const float* __restrict__ bias, float* __restrict__ dst,
                      int headLayout)
{
    __shared__ unsigned As[2][128][LPAD];
    __shared__ unsigned Ws[2][128][LPAD];

    int tid  = threadIdx.x;
    int w    = tid >> 5;
    int lane = tid & 31;
    int grp  = lane >> 2;
    int qid  = lane & 3;
    int wm   = (w >> 2) * 64;
    int wn   = (w & 3) * 32;

    int m0 = blockIdx.y << 7, n0 = blockIdx.x << 7;

    int lrow  = tid >> 1;
    int kbase = (tid & 1) * 8;
    const float* aptr = A + (size_t)(m0 + lrow) * NDIM + kbase;
    const float* bptr = W + (size_t)(n0 + lrow) * NDIM + kbase;

    float acc[4][4][4];
    #pragma unroll
    for (int mt = 0; mt < 4; mt++)
        #pragma unroll
        for (int nt = 0; nt < 4; nt++)
            #pragma unroll
            for (int r = 0; r < 4; r++) acc[mt][nt][r] = 0.f;

    float4 ra0 = *(const float4*)(aptr);
    float4 ra1 = *(const float4*)(aptr + 4);
    float4 rb0 = *(const float4*)(bptr);
    float4 rb1 = *(const float4*)(bptr + 4);

    {
        unsigned* as = &As[0][lrow][kbase];
        as[0]=f2tf32(ra0.x); as[1]=f2tf32(ra0.y); as[2]=f2tf32(ra0.z); as[3]=f2tf32(ra0.w);
        as[4]=f2tf32(ra1.x); as[5]=f2tf32(ra1.y); as[6]=f2tf32(ra1.z); as[7]=f2tf32(ra1.w);
        unsigned* ws = &Ws[0][lrow][kbase];
        ws[0]=f2tf32(rb0.x); ws[1]=f2tf32(rb0.y); ws[2]=f2tf32(rb0.z); ws[3]=f2tf32(rb0.w);
        ws[4]=f2tf32(rb1.x); ws[5]=f2tf32(rb1.y); ws[6]=f2tf32(rb1.z); ws[7]=f2tf32(rb1.w);
    }
    __syncthreads();

    int buf = 0;
    const int NKT = NDIM / KS;
    for (int kt = 0; kt < NKT; kt++) {
        if (kt < NKT - 1) {
            const float* ap = aptr + (kt + 1) * KS;
            const float* bp = bptr + (kt + 1) * KS;
            ra0 = *(const float4*)(ap);
            ra1 = *(const float4*)(ap + 4);
            rb0 = *(const float4*)(bp);
            rb1 = *(const float4*)(bp + 4);
        }

        #pragma unroll
        for (int sl = 0; sl < 2; sl++) {
            int kk = sl * 8;
            unsigned afr[4][4], bfr[4][2];
            #pragma unroll
            for (int mt = 0; mt < 4; mt++) {
                const unsigned* ar = &As[buf][wm + mt*16 + grp][kk + qid];
                afr[mt][0] = ar[0];
                afr[mt][1] = ar[8 * LPAD];
                afr[mt][2] = ar[4];
                afr[mt][3] = ar[8 * LPAD + 4];
            }
            #pragma unroll
            for (int nt = 0; nt < 4; nt++) {
                const unsigned* br = &Ws[buf][wn + nt*8 + grp][kk + qid];
                bfr[nt][0] = br[0];
                bfr[nt][1] = br[4];
            }
            #pragma unroll
            for (int mt = 0; mt < 4; mt++)
                #pragma unroll
                for (int nt = 0; nt < 4; nt++)
                    mma_tf32(acc[mt][nt], afr[mt][0], afr[mt][1], afr[mt][2], afr[mt][3],
                             bfr[nt][0], bfr[nt][1]);
        }

        if (kt < NKT - 1) {
            int nb = buf ^ 1;
            unsigned* as = &As[nb][lrow][kbase];
            as[0]=f2tf32(ra0.x); as[1]=f2tf32(ra0.y); as[2]=f2tf32(ra0.z); as[3]=f2tf32(ra0.w);
            as[4]=f2tf32(ra1.x); as[5]=f2tf32(ra1.y); as[6]=f2tf32(ra1.z); as[7]=f2tf32(ra1.w);
            unsigned* ws = &Ws[nb][lrow][kbase];
            ws[0]=f2tf32(rb0.x); ws[1]=f2tf32(rb0.y); ws[2]=f2tf32(rb0.z); ws[3]=f2tf32(rb0.w);
            ws[4]=f2tf32(rb1.x); ws[5]=f2tf32(rb1.y); ws[6]=f2tf32(rb1.z); ws[7]=f2tf32(rb1.w);
            __syncthreads();
            buf = nb;
        }
    }

    #pragma unroll
    for (int mt = 0; mt < 4; mt++) {
        #pragma unroll
        for (int nt = 0; nt < 4; nt++) {
            int n = n0 + wn + nt * 8 + (qid << 1);
            float bx = bias[n], by = bias[n + 1];
            #pragma unroll
            for (int half = 0; half < 2; half++) {
                int m = m0 + wm + mt * 16 + grp + half * 8;
                float2 v;
                v.x = acc[mt][nt][half * 2 + 0] + bx;
                v.y = acc[mt][nt][half * 2 + 1] + by;
                if (headLayout) {
                    int b = m >> 11, s = m & (NS - 1);
                    int h = n >> 6, d = n & 63;
                    *(float2*)&dst[(((size_t)((b << 4) + h) * NS + s)) * HD + d] = v;
                } else {
                    *(float2*)&dst[(size_t)m * NDIM + n] = v;
                }
            }
        }
    }
}

// ---------------------------------------------------------------------------
// TF32 MMA flash attention.
// CTA: 128 q-rows of one (b,h); 8 warps, each owns 16 q-rows (all 64 S cols).
// Tiles of 64 keys. Smem (tf32 words, pitch 68):
//   Qs[128][68] | KP[128][68] (K tile [64][68] -> P tile) | VsT[64][68].
// ---------------------------------------------------------------------------
#define APITCH 68
#define ATTN_SMEM ((128*APITCH + 128*APITCH + 64*APITCH) * 4)

__global__ __launch_bounds__(256, 2)
void attn_tc_kernel(const float* __restrict__ Kg, const float* __restrict__ Vg,
                    const int* __restrict__ mask)
{
    extern __shared__ unsigned sm_u[];
    unsigned* Qs  = sm_u;                    // [128][68]
    unsigned* KP  = sm_u + 128*APITCH;       // K [64][68] -> P [128][68]
    unsigned* VsT = KP + 128*APITCH;         // [64][68]  (V transposed: [dim][key])

    int tid = threadIdx.x;
    int w = tid >> 5, lane = tid & 31;
    int grp = lane >> 2, qid = lane & 3;
    int wm = w << 4;                          // warp's 16-row block
    int bh = blockIdx.y;
    int b = bh >> 4, h = bh & 15;
    int q0 = blockIdx.x << 7;

    const float* qptr = g_q + ((size_t)bh * NS + q0) * HD;
    const float* kptr = Kg + (size_t)bh * NS * HD;
    const float* vptr = Vg + (size_t)bh * NS * HD;
    const int* mrow0 = mask + ((size_t)b * NS + q0 + wm + grp) * NS;
    const int* mrow1 = mrow0 + 8 * NS;

    // Load Q tile (tf32): 128 rows x 16 float4
    #pragma unroll
    for (int i = 0; i < 8; i++) {
        int lin = tid + (i << 8);
        int row = lin >> 4, d4 = (lin & 15) << 2;
        float4 qv = *(const float4*)(qptr + row * HD + d4);
        unsigned* qs = &Qs[row * APITCH + d4];
        qs[0]=f2tf32(qv.x); qs[1]=f2tf32(qv.y); qs[2]=f2tf32(qv.z); qs[3]=f2tf32(qv.w);
    }

    float o[8][4];
    #pragma unroll
    for (int nt = 0; nt < 8; nt++)
        #pragma unroll
        for (int r = 0; r < 4; r++) o[nt][r] = 0.f;
    float m0 = -3.0e38f, m1 = -3.0e38f, l0 = 0.f, l1 = 0.f;

    for (int k0 = 0; k0 < NS; k0 += 64) {
        __syncthreads();   // prior PV reads done; publishes Qs on iter 0
        // K tile -> KP[key][dim]
        #pragma unroll
        for (int i = 0; i < 4; i++) {
            int lin = tid + (i << 8);
            int row = lin >> 4, d4 = (lin & 15) << 2;
            float4 kv = *(const float4*)(kptr + (k0 + row) * HD + d4);
            unsigned* ks = &KP[row * APITCH + d4];
            ks[0]=f2tf32(kv.x); ks[1]=f2tf32(kv.y); ks[2]=f2tf32(kv.z); ks[3]=f2tf32(kv.w);
        }
        // V tile transposed -> VsT[dim][key] (conflict-free stores: key = lane-major)
        #pragma unroll
        for (int i = 0; i < 4; i++) {
            int lin = tid + (i << 8);
            int key = lin & 63, d4 = (lin >> 6) << 2;
            float4 vv = *(const float4*)(vptr + (k0 + key) * HD + d4);
            VsT[(d4 + 0) * APITCH + key] = f2tf32(vv.x);
            VsT[(d4 + 1) * APITCH + key] = f2tf32(vv.y);
            VsT[(d4 + 2) * APITCH + key] = f2tf32(vv.z);
            VsT[(d4 + 3) * APITCH + key] = f2tf32(vv.w);
        }
        __syncthreads();

        // S = Q K^T : warp tile 16x64, fp32 accum
        float sc[8][4];
        #pragma unroll
        for (int nt = 0; nt < 8; nt++)
            #pragma unroll
            for (int r = 0; r < 4; r++) sc[nt][r] = 0.f;

        #pragma unroll
        for (int kk = 0; kk < 8; kk++) {
            const unsigned* ar = &Qs[(wm + grp) * APITCH + kk * 8 + qid];
            unsigned a0 = ar[0], a1 = ar[8 * APITCH], a2 = ar[4], a3 = ar[8 * APITCH + 4];
            #pragma unroll
            for (int nt = 0; nt < 8; nt++) {
                const unsigned* br = &KP[(nt * 8 + grp) * APITCH + kk * 8 + qid];
                mma_tf32(sc[nt], a0, a1, a2, a3, br[0], br[4]);
            }
        }

        // scale + mask
        #pragma unroll
        for (int nt = 0; nt < 8; nt++) {
            int col = k0 + nt * 8 + (qid << 1);
            int2 mA = *(const int2*)(mrow0 + col);
            int2 mB = *(const int2*)(mrow1 + col);
            sc[nt][0] = mA.x ? sc[nt][0] * 0.125f : -1e30f;
            sc[nt][1] = mA.y ? sc[nt][1] * 0.125f : -1e30f;
            sc[nt][2] = mB.x ? sc[nt][2] * 0.125f : -1e30f;
            sc[nt][3] = mB.y ? sc[nt][3] * 0.125f : -1e30f;
        }

        // online softmax (rows grp and grp+8; reduce over 4 qid lanes)
        float mx0 = -3.0e38f, mx1 = -3.0e38f;
        #pragma unroll
        for (int nt = 0; nt < 8; nt++) {
            mx0 = fmaxf(mx0, fmaxf(sc[nt][0], sc[nt][1]));
            mx1 = fmaxf(mx1, fmaxf(sc[nt][2], sc[nt][3]));
        }
        mx0 = fmaxf(mx0, __shfl_xor_sync(0xffffffffu, mx0, 1));
        mx0 = fmaxf(mx0, __shfl_xor_sync(0xffffffffu, mx0, 2));
        mx1 = fmaxf(mx1, __shfl_xor_sync(0xffffffffu, mx1, 1));
        mx1 = fmaxf(mx1, __shfl_xor_sync(0xffffffffu, mx1, 2));

        float mn0 = fmaxf(m0, mx0), mn1 = fmaxf(m1, mx1);
        float corr0 = __expf(m0 - mn0), corr1 = __expf(m1 - mn1);
        m0 = mn0; m1 = mn1;

        float ps0 = 0.f, ps1 = 0.f;
        #pragma unroll
        for (int nt = 0; nt < 8; nt++) {
            sc[nt][0] = __expf(sc[nt][0] - mn0); ps0 += sc[nt][0];
            sc[nt][1] = __expf(sc[nt][1] - mn0); ps0 += sc[nt][1];
            sc[nt][2] = __expf(sc[nt][2] - mn1); ps1 += sc[nt][2];
            sc[nt][3] = __expf(sc[nt][3] - mn1); ps1 += sc[nt][3];
        }
        ps0 += __shfl_xor_sync(0xffffffffu, ps0, 1);
        ps0 += __shfl_xor_sync(0xffffffffu, ps0, 2);
        ps1 += __shfl_xor_sync(0xffffffffu, ps1, 1);
        ps1 += __shfl_xor_sync(0xffffffffu, ps1, 2);
        l0 = l0 * corr0 + ps0;
        l1 = l1 * corr1 + ps1;
        #pragma unroll
        for (int nt = 0; nt < 8; nt++) {
            o[nt][0] *= corr0; o[nt][1] *= corr0;
            o[nt][2] *= corr1; o[nt][3] *= corr1;
        }

        __syncthreads();   // all warps done reading K tile (P overlays it)
        #pragma unroll
        for (int nt = 0; nt < 8; nt++) {
            unsigned* p0 = &KP[(wm + grp) * APITCH + nt * 8 + (qid << 1)];
            p0[0] = f2tf32(sc[nt][0]); p0[1] = f2tf32(sc[nt][1]);
            unsigned* p1 = &KP[(wm + grp + 8) * APITCH + nt * 8 + (qid << 1)];
            p1[0] = f2tf32(sc[nt][2]); p1[1] = f2tf32(sc[nt][3]);
        }
        __syncthreads();

        // O += P V  (A = P from smem, B = VsT)
        #pragma unroll
        for (int kk = 0; kk < 8; kk++) {
            const unsigned* ar = &KP[(wm + grp) * APITCH + kk * 8 + qid];
            unsigned a0 = ar[0], a1 = ar[8 * APITCH], a2 = ar[4], a3 = ar[8 * APITCH + 4];
            #pragma unroll
            for (int nt = 0; nt < 8; nt++) {
                const unsigned* br = &VsT[(nt * 8 + grp) * APITCH + kk * 8 + qid];
                mma_tf32(o[nt], a0, a1, a2, a3, br[0], br[4]);
            }
        }
    }

    // epilogue
    float inv0 = 1.0f / l0, inv1 = 1.0f / l1;
    int r0 = q0 + wm + grp, r1 = r0 + 8;
    #pragma unroll
    for (int nt = 0; nt < 8; nt++) {
        int col = h * HD + nt * 8 + (qid << 1);
        float2 v0 = make_float2(o[nt][0] * inv0, o[nt][1] * inv0);
        float2 v1 = make_float2(o[nt][2] * inv1, o[nt][3] * inv1);
        *(float2*)&g_ctx[((size_t)b * NS + r0) * NDIM + col] = v0;
        *(float2*)&g_ctx[((size_t)b * NS + r1) * NDIM + col] = v1;
    }
}

// ---------------------------------------------------------------------------
extern "C" void kernel_launch(void* const* d_in, const int* in_sizes, int n_in,
                              void* d_out, int out_size) {
    const float* query = (const float*)d_in[0];
    const float* key   = (const float*)d_in[1];
    const float* value = (const float*)d_in[2];
    const int*   mask  = (const int*)d_in[3];
    const float* Wq = (const float*)d_in[4];
    const float* bq = (const float*)d_in[5];
    const float* Wk = (const float*)d_in[6];
    const float* bk = (const float*)d_in[7];
    const float* Wv = (const float*)d_in[8];
    const float* bv = (const float*)d_in[9];
    const float* Wo = (const float*)d_in[10];
    const float* bo = (const float*)d_in[11];

    float* out  = (float*)d_out;                 // [B,S,1024]
    float* outK = out + OUT_ELEMS;               // [B,H,S,64] (post-RoPE k)
    float* outV = out + 2 * (size_t)OUT_ELEMS;   // [B,H,S,64] (v)

    float* g_q_p;   cudaGetSymbolAddress((void**)&g_q_p, g_q);
    float* g_ctx_p; cudaGetSymbolAddress((void**)&g_ctx_p, g_ctx);

    static int attn_smem_set = 0;
    if (!attn_smem_set) {
        cudaFuncSetAttribute(attn_tc_kernel, cudaFuncAttributeMaxDynamicSharedMemorySize,
                             ATTN_SMEM);
        attn_smem_set = 1;
    }

    rope_table_kernel<<<(NS * 32 + 255) / 256, 256>>>();

    dim3 lgrid(NDIM / 128, NM / 128);   // (8, 32)
    linear_tc_kernel<<<lgrid, 256>>>(query, Wq, bq, g_q_p, 1);
    linear_tc_kernel<<<lgrid, 256>>>(key,   Wk, bk, outK,  1);
    linear_tc_kernel<<<lgrid, 256>>>(value, Wv, bv, outV,  1);

    dim3 rgrid((NB * NH * NS * 32) / 256, 2);
    rope_apply_kernel<<<rgrid, 256>>>(outK);

    dim3 agrid(NS / 128, NB * NH);      // (16, 32)
    attn_tc_kernel<<<agrid, 256, ATTN_SMEM>>>(outK, outV, mask);

    linear_tc_kernel<<<lgrid, 256>>>(g_ctx_p, Wo, bo, out, 0);
}

// round 6
// speedup vs baseline: 2.7803x; 1.0987x over previous
#include <cuda_runtime.h>
#include <math.h>

#define NB 2
#define NS 2048
#define NH 16
#define HD 64
#define NDIM 1024
#define NM (NB*NS)
#define OUT_ELEMS (NB*NS*NDIM)   // 4194304 per tensor (out, k, v)

// Scratch (allocation-free rule: __device__ globals)
__device__ float g_q[NB*NH*NS*HD];     // q after proj (+RoPE), [b,h,s,d]
__device__ float g_ctx[NB*NS*NDIM];    // attention context, [b,s, h*64+d] flat
__device__ float g_cos[NS*32];
__device__ float g_sin[NS*32];

__device__ __forceinline__ unsigned f2tf32(float x) {
    unsigned r; asm("cvt.rna.tf32.f32 %0, %1;" : "=r"(r) : "f"(x)); return r;
}
__device__ __forceinline__ void mma_tf32(float c[4], unsigned a0, unsigned a1,
                                         unsigned a2, unsigned a3,
                                         unsigned b0, unsigned b1) {
    asm volatile(
        "mma.sync.aligned.m16n8k8.row.col.f32.tf32.tf32.f32 "
        "{%0,%1,%2,%3}, {%4,%5,%6,%7}, {%8,%9}, {%0,%1,%2,%3};"
        : "+f"(c[0]), "+f"(c[1]), "+f"(c[2]), "+f"(c[3])
        : "r"(a0), "r"(a1), "r"(a2), "r"(a3), "r"(b0), "r"(b1));
}
// ldmatrix x4 on b32 tiles: lane l of each 8-lane group supplies one 16B row.
__device__ __forceinline__ void ldsm4(unsigned &r0, unsigned &r1, unsigned &r2,
                                      unsigned &r3, const void* p) {
    unsigned a = (unsigned)__cvta_generic_to_shared(p);
    asm volatile("ldmatrix.sync.aligned.m8n8.x4.shared.b16 {%0,%1,%2,%3}, [%4];"
                 : "=r"(r0), "=r"(r1), "=r"(r2), "=r"(r3) : "r"(a));
}

// ---------------------------------------------------------------------------
// RoPE tables
// ---------------------------------------------------------------------------
__global__ void rope_table_kernel() {
    int idx = blockIdx.x * blockDim.x + threadIdx.x;
    if (idx >= NS * 32) return;
    int s = idx >> 5, j = idx & 31;
    float invf = (float)exp(-(double)j * (log(10000.0) / 32.0));
    float ang = (float)s * invf;       // fp32 rounding like the reference
    g_cos[idx] = (float)cos((double)ang);
    g_sin[idx] = (float)sin((double)ang);
}

__global__ void rope_apply_kernel(float* __restrict__ kptr) {
    int idx = blockIdx.x * blockDim.x + threadIdx.x;   // NB*NH*NS*32 threads
    float* p = blockIdx.y ? kptr : g_q;
    int j = idx & 31;
    int row = idx >> 5;                // bh*NS + s
    int s = row & (NS - 1);
    int base = row * 64 + j;
    float c = g_cos[(s << 5) + j], sn = g_sin[(s << 5) + j];
    float x1 = p[base], x2 = p[base + 32];
    p[base]      = x1 * c - x2 * sn;
    p[base + 32] = x2 * c + x1 * sn;
}

// ---------------------------------------------------------------------------
// TF32 tensor-core linear, fragments via ldmatrix.
// ---------------------------------------------------------------------------
#define KS 16
#define LPAD 20

__global__ __launch_bounds__(256, 2)
void linear_tc_kernel(const float* __restrict__ A, const float* __restrict__ W,
                      const float* __restrict__ bias, float* __restrict__ dst,
                      int headLayout)
{
    __shared__ unsigned As[2][128][LPAD];
    __shared__ unsigned Ws[2][128][LPAD];

    int tid  = threadIdx.x;
    int w    = tid >> 5;
    int lane = tid & 31;
    int grp  = lane >> 2;
    int qid  = lane & 3;
    int wm   = (w >> 2) * 64;
    int wn   = (w & 3) * 32;

    // ldmatrix per-lane row/col selectors
    int lane15   = lane & 15;
    int acolsel  = (lane >> 4) << 2;                 // 0 or 4
    int b_rowoff = (lane & 7) + ((lane >> 4) << 3);  // 0..15
    int bcolsel  = ((lane >> 3) & 1) << 2;           // 0 or 4

    int m0 = blockIdx.y << 7, n0 = blockIdx.x << 7;

    int lrow  = tid >> 1;
    int kbase = (tid & 1) * 8;
    const float* aptr = A + (size_t)(m0 + lrow) * NDIM + kbase;
    const float* bptr = W + (size_t)(n0 + lrow) * NDIM + kbase;

    float acc[4][4][4];
    #pragma unroll
    for (int mt = 0; mt < 4; mt++)
        #pragma unroll
        for (int nt = 0; nt < 4; nt++)
            #pragma unroll
            for (int r = 0; r < 4; r++) acc[mt][nt][r] = 0.f;

    float4 ra0 = *(const float4*)(aptr);
    float4 ra1 = *(const float4*)(aptr + 4);
    float4 rb0 = *(const float4*)(bptr);
    float4 rb1 = *(const float4*)(bptr + 4);

    {
        unsigned* as = &As[0][lrow][kbase];
        as[0]=f2tf32(ra0.x); as[1]=f2tf32(ra0.y); as[2]=f2tf32(ra0.z); as[3]=f2tf32(ra0.w);
        as[4]=f2tf32(ra1.x); as[5]=f2tf32(ra1.y); as[6]=f2tf32(ra1.z); as[7]=f2tf32(ra1.w);
        unsigned* ws = &Ws[0][lrow][kbase];
        ws[0]=f2tf32(rb0.x); ws[1]=f2tf32(rb0.y); ws[2]=f2tf32(rb0.z); ws[3]=f2tf32(rb0.w);
        ws[4]=f2tf32(rb1.x); ws[5]=f2tf32(rb1.y); ws[6]=f2tf32(rb1.z); ws[7]=f2tf32(rb1.w);
    }
    __syncthreads();

    int buf = 0;
    const int NKT = NDIM / KS;
    for (int kt = 0; kt < NKT; kt++) {
        if (kt < NKT - 1) {
            const float* ap = aptr + (kt + 1) * KS;
            const float* bp = bptr + (kt + 1) * KS;
            ra0 = *(const float4*)(ap);
            ra1 = *(const float4*)(ap + 4);
            rb0 = *(const float4*)(bp);
            rb1 = *(const float4*)(bp + 4);
        }

        #pragma unroll
        for (int sl = 0; sl < 2; sl++) {
            int kk = sl * 8;
            unsigned afr[4][4], bfr[4][2];
            #pragma unroll
            for (int mt = 0; mt < 4; mt++)
                ldsm4(afr[mt][0], afr[mt][1], afr[mt][2], afr[mt][3],
                      &As[buf][wm + mt * 16 + lane15][kk + acolsel]);
            #pragma unroll
            for (int ntp = 0; ntp < 2; ntp++) {
                unsigned r0, r1, r2, r3;
                ldsm4(r0, r1, r2, r3, &Ws[buf][wn + ntp * 16 + b_rowoff][kk + bcolsel]);
                bfr[ntp*2][0]   = r0; bfr[ntp*2][1]   = r1;
                bfr[ntp*2+1][0] = r2; bfr[ntp*2+1][1] = r3;
            }
            #pragma unroll
            for (int mt = 0; mt < 4; mt++)
                #pragma unroll
                for (int nt = 0; nt < 4; nt++)
                    mma_tf32(acc[mt][nt], afr[mt][0], afr[mt][1], afr[mt][2], afr[mt][3],
                             bfr[nt][0], bfr[nt][1]);
        }

        if (kt < NKT - 1) {
            int nb = buf ^ 1;
            unsigned* as = &As[nb][lrow][kbase];
            as[0]=f2tf32(ra0.x); as[1]=f2tf32(ra0.y); as[2]=f2tf32(ra0.z); as[3]=f2tf32(ra0.w);
            as[4]=f2tf32(ra1.x); as[5]=f2tf32(ra1.y); as[6]=f2tf32(ra1.z); as[7]=f2tf32(ra1.w);
            unsigned* ws = &Ws[nb][lrow][kbase];
            ws[0]=f2tf32(rb0.x); ws[1]=f2tf32(rb0.y); ws[2]=f2tf32(rb0.z); ws[3]=f2tf32(rb0.w);
            ws[4]=f2tf32(rb1.x); ws[5]=f2tf32(rb1.y); ws[6]=f2tf32(rb1.z); ws[7]=f2tf32(rb1.w);
            __syncthreads();
            buf = nb;
        }
    }

    #pragma unroll
    for (int mt = 0; mt < 4; mt++) {
        #pragma unroll
        for (int nt = 0; nt < 4; nt++) {
            int n = n0 + wn + nt * 8 + (qid << 1);
            float bx = bias[n], by = bias[n + 1];
            #pragma unroll
            for (int half = 0; half < 2; half++) {
                int m = m0 + wm + mt * 16 + grp + half * 8;
                float2 v;
                v.x = acc[mt][nt][half * 2 + 0] + bx;
                v.y = acc[mt][nt][half * 2 + 1] + by;
                if (headLayout) {
                    int b = m >> 11, s = m & (NS - 1);
                    int h = n >> 6, d = n & 63;
                    *(float2*)&dst[(((size_t)((b << 4) + h) * NS + s)) * HD + d] = v;
                } else {
                    *(float2*)&dst[(size_t)m * NDIM + n] = v;
                }
            }
        }
    }
}

// ---------------------------------------------------------------------------
// TF32 MMA flash attention, fragments via ldmatrix.
// ---------------------------------------------------------------------------
#define APITCH 68
#define ATTN_SMEM ((128*APITCH + 128*APITCH + 64*APITCH) * 4)

__global__ __launch_bounds__(256, 2)
void attn_tc_kernel(const float* __restrict__ Kg, const float* __restrict__ Vg,
                    const int* __restrict__ mask)
{
    extern __shared__ unsigned sm_u[];
    unsigned* Qs  = sm_u;                    // [128][68]
    unsigned* KP  = sm_u + 128*APITCH;       // K [64][68] -> P [128][68]
    unsigned* VsT = KP + 128*APITCH;         // [64][68]  (V transposed: [dim][key])

    int tid = threadIdx.x;
    int w = tid >> 5, lane = tid & 31;
    int grp = lane >> 2, qid = lane & 3;
    int wm = w << 4;
    int bh = blockIdx.y;
    int b = bh >> 4, h = bh & 15;
    int q0 = blockIdx.x << 7;

    int lane15   = lane & 15;
    int acolsel  = (lane >> 4) << 2;
    int b_rowoff = (lane & 7) + ((lane >> 4) << 3);
    int bcolsel  = ((lane >> 3) & 1) << 2;

    const float* qptr = g_q + ((size_t)bh * NS + q0) * HD;
    const float* kptr = Kg + (size_t)bh * NS * HD;
    const float* vptr = Vg + (size_t)bh * NS * HD;
    const int* mrow0 = mask + ((size_t)b * NS + q0 + wm + grp) * NS;
    const int* mrow1 = mrow0 + 8 * NS;

    #pragma unroll
    for (int i = 0; i < 8; i++) {
        int lin = tid + (i << 8);
        int row = lin >> 4, d4 = (lin & 15) << 2;
        float4 qv = *(const float4*)(qptr + row * HD + d4);
        unsigned* qs = &Qs[row * APITCH + d4];
        qs[0]=f2tf32(qv.x); qs[1]=f2tf32(qv.y); qs[2]=f2tf32(qv.z); qs[3]=f2tf32(qv.w);
    }

    float o[8][4];
    #pragma unroll
    for (int nt = 0; nt < 8; nt++)
        #pragma unroll
        for (int r = 0; r < 4; r++) o[nt][r] = 0.f;
    float m0 = -3.0e38f, m1 = -3.0e38f, l0 = 0.f, l1 = 0.f;

    for (int k0 = 0; k0 < NS; k0 += 64) {
        __syncthreads();
        #pragma unroll
        for (int i = 0; i < 4; i++) {
            int lin = tid + (i << 8);
            int row = lin >> 4, d4 = (lin & 15) << 2;
            float4 kv = *(const float4*)(kptr + (k0 + row) * HD + d4);
            unsigned* ks = &KP[row * APITCH + d4];
            ks[0]=f2tf32(kv.x); ks[1]=f2tf32(kv.y); ks[2]=f2tf32(kv.z); ks[3]=f2tf32(kv.w);
        }
        #pragma unroll
        for (int i = 0; i < 4; i++) {
            int lin = tid + (i << 8);
            int key = lin & 63, d4 = (lin >> 6) << 2;
            float4 vv = *(const float4*)(vptr + (k0 + key) * HD + d4);
            VsT[(d4 + 0) * APITCH + key] = f2tf32(vv.x);
            VsT[(d4 + 1) * APITCH + key] = f2tf32(vv.y);
            VsT[(d4 + 2) * APITCH + key] = f2tf32(vv.z);
            VsT[(d4 + 3) * APITCH + key] = f2tf32(vv.w);
        }
        __syncthreads();

        // S = Q K^T
        float sc[8][4];
        #pragma unroll
        for (int nt = 0; nt < 8; nt++)
            #pragma unroll
            for (int r = 0; r < 4; r++) sc[nt][r] = 0.f;

        #pragma unroll
        for (int kk = 0; kk < 8; kk++) {
            unsigned a0, a1, a2, a3;
            ldsm4(a0, a1, a2, a3, &Qs[(wm + lane15) * APITCH + kk * 8 + acolsel]);
            #pragma unroll
            for (int ntp = 0; ntp < 4; ntp++) {
                unsigned r0, r1, r2, r3;
                ldsm4(r0, r1, r2, r3,
                      &KP[(ntp * 16 + b_rowoff) * APITCH + kk * 8 + bcolsel]);
                mma_tf32(sc[ntp*2],   a0, a1, a2, a3, r0, r1);
                mma_tf32(sc[ntp*2+1], a0, a1, a2, a3, r2, r3);
            }
        }

        // scale + mask
        #pragma unroll
        for (int nt = 0; nt < 8; nt++) {
            int col = k0 + nt * 8 + (qid << 1);
            int2 mA = *(const int2*)(mrow0 + col);
            int2 mB = *(const int2*)(mrow1 + col);
            sc[nt][0] = mA.x ? sc[nt][0] * 0.125f : -1e30f;
            sc[nt][1] = mA.y ? sc[nt][1] * 0.125f : -1e30f;
            sc[nt][2] = mB.x ? sc[nt][2] * 0.125f : -1e30f;
            sc[nt][3] = mB.y ? sc[nt][3] * 0.125f : -1e30f;
        }

        // online softmax
        float mx0 = -3.0e38f, mx1 = -3.0e38f;
        #pragma unroll
        for (int nt = 0; nt < 8; nt++) {
            mx0 = fmaxf(mx0, fmaxf(sc[nt][0], sc[nt][1]));
            mx1 = fmaxf(mx1, fmaxf(sc[nt][2], sc[nt][3]));
        }
        mx0 = fmaxf(mx0, __shfl_xor_sync(0xffffffffu, mx0, 1));
        mx0 = fmaxf(mx0, __shfl_xor_sync(0xffffffffu, mx0, 2));
        mx1 = fmaxf(mx1, __shfl_xor_sync(0xffffffffu, mx1, 1));
        mx1 = fmaxf(mx1, __shfl_xor_sync(0xffffffffu, mx1, 2));

        float mn0 = fmaxf(m0, mx0), mn1 = fmaxf(m1, mx1);
        float corr0 = __expf(m0 - mn0), corr1 = __expf(m1 - mn1);
        m0 = mn0; m1 = mn1;

        float ps0 = 0.f, ps1 = 0.f;
        #pragma unroll
        for (int nt = 0; nt < 8; nt++) {
            sc[nt][0] = __expf(sc[nt][0] - mn0); ps0 += sc[nt][0];
            sc[nt][1] = __expf(sc[nt][1] - mn0); ps0 += sc[nt][1];
            sc[nt][2] = __expf(sc[nt][2] - mn1); ps1 += sc[nt][2];
            sc[nt][3] = __expf(sc[nt][3] - mn1); ps1 += sc[nt][3];
        }
        ps0 += __shfl_xor_sync(0xffffffffu, ps0, 1);
        ps0 += __shfl_xor_sync(0xffffffffu, ps0, 2);
        ps1 += __shfl_xor_sync(0xffffffffu, ps1, 1);
        ps1 += __shfl_xor_sync(0xffffffffu, ps1, 2);
        l0 = l0 * corr0 + ps0;
        l1 = l1 * corr1 + ps1;
        #pragma unroll
        for (int nt = 0; nt < 8; nt++) {
            o[nt][0] *= corr0; o[nt][1] *= corr0;
            o[nt][2] *= corr1; o[nt][3] *= corr1;
        }

        __syncthreads();
        #pragma unroll
        for (int nt = 0; nt < 8; nt++) {
            unsigned* p0 = &KP[(wm + grp) * APITCH + nt * 8 + (qid << 1)];
            p0[0] = f2tf32(sc[nt][0]); p0[1] = f2tf32(sc[nt][1]);
            unsigned* p1 = &KP[(wm + grp + 8) * APITCH + nt * 8 + (qid << 1)];
            p1[0] = f2tf32(sc[nt][2]); p1[1] = f2tf32(sc[nt][3]);
        }
        __syncthreads();

        // O += P V
        #pragma unroll
        for (int kk = 0; kk < 8; kk++) {
            unsigned a0, a1, a2, a3;
            ldsm4(a0, a1, a2, a3, &KP[(wm + lane15) * APITCH + kk * 8 + acolsel]);
            #pragma unroll
            for (int ntp = 0; ntp < 4; ntp++) {
                unsigned r0, r1, r2, r3;
                ldsm4(r0, r1, r2, r3,
                      &VsT[(ntp * 16 + b_rowoff) * APITCH + kk * 8 + bcolsel]);
                mma_tf32(o[ntp*2],   a0, a1, a2, a3, r0, r1);
                mma_tf32(o[ntp*2+1], a0, a1, a2, a3, r2, r3);
            }
        }
    }

    float inv0 = 1.0f / l0, inv1 = 1.0f / l1;
    int r0 = q0 + wm + grp, r1 = r0 + 8;
    #pragma unroll
    for (int nt = 0; nt < 8; nt++) {
        int col = h * HD + nt * 8 + (qid << 1);
        float2 v0 = make_float2(o[nt][0] * inv0, o[nt][1] * inv0);
        float2 v1 = make_float2(o[nt][2] * inv1, o[nt][3] * inv1);
        *(float2*)&g_ctx[((size_t)b * NS + r0) * NDIM + col] = v0;
        *(float2*)&g_ctx[((size_t)b * NS + r1) * NDIM + col] = v1;
    }
}

// ---------------------------------------------------------------------------
extern "C" void kernel_launch(void* const* d_in, const int* in_sizes, int n_in,
                              void* d_out, int out_size) {
    const float* query = (const float*)d_in[0];
    const float* key   = (const float*)d_in[1];
    const float* value = (const float*)d_in[2];
    const int*   mask  = (const int*)d_in[3];
    const float* Wq = (const float*)d_in[4];
    const float* bq = (const float*)d_in[5];
    const float* Wk = (const float*)d_in[6];
    const float* bk = (const float*)d_in[7];
    const float* Wv = (const float*)d_in[8];
    const float* bv = (const float*)d_in[9];
    const float* Wo = (const float*)d_in[10];
    const float* bo = (const float*)d_in[11];

    float* out  = (float*)d_out;                 // [B,S,1024]
    float* outK = out + OUT_ELEMS;               // [B,H,S,64] (post-RoPE k)
    float* outV = out + 2 * (size_t)OUT_ELEMS;   // [B,H,S,64] (v)

    float* g_q_p;   cudaGetSymbolAddress((void**)&g_q_p, g_q);
    float* g_ctx_p; cudaGetSymbolAddress((void**)&g_ctx_p, g_ctx);

    static int attn_smem_set = 0;
    if (!attn_smem_set) {
        cudaFuncSetAttribute(attn_tc_kernel, cudaFuncAttributeMaxDynamicSharedMemorySize,
                             ATTN_SMEM);
        attn_smem_set = 1;
    }

    rope_table_kernel<<<(NS * 32 + 255) / 256, 256>>>();

    dim3 lgrid(NDIM / 128, NM / 128);   // (8, 32)
    linear_tc_kernel<<<lgrid, 256>>>(query, Wq, bq, g_q_p, 1);
    linear_tc_kernel<<<lgrid, 256>>>(key,   Wk, bk, outK,  1);
    linear_tc_kernel<<<lgrid, 256>>>(value, Wv, bv, outV,  1);

    dim3 rgrid((NB * NH * NS * 32) / 256, 2);
    rope_apply_kernel<<<rgrid, 256>>>(outK);

    dim3 agrid(NS / 128, NB * NH);      // (16, 32)
    attn_tc_kernel<<<agrid, 256, ATTN_SMEM>>>(outK, outV, mask);

    linear_tc_kernel<<<lgrid, 256>>>(g_ctx_p, Wo, bo, out, 0);
}

// round 8
// speedup vs baseline: 2.9190x; 1.0499x over previous
#include <cuda_runtime.h>
#include <math.h>

#define NB 2
#define NS 2048
#define NH 16
#define HD 64
#define NDIM 1024
#define NM (NB*NS)
#define OUT_ELEMS (NB*NS*NDIM)   // 4194304 per tensor (out, k, v)

// Scratch (allocation-free rule: __device__ globals)
__device__ float g_q[NB*NH*NS*HD];     // q after proj (+RoPE), [b,h,s,d]
__device__ float g_ctx[NB*NS*NDIM];    // attention context, [b,s, h*64+d] flat
__device__ float g_cos[NS*32];
__device__ float g_sin[NS*32];

__device__ __forceinline__ unsigned f2tf32(float x) {
    unsigned r; asm("cvt.rna.tf32.f32 %0, %1;" : "=r"(r) : "f"(x)); return r;
}
__device__ __forceinline__ void mma_tf32(float c[4], unsigned a0, unsigned a1,
                                         unsigned a2, unsigned a3,
                                         unsigned b0, unsigned b1) {
    asm volatile(
        "mma.sync.aligned.m16n8k8.row.col.f32.tf32.tf32.f32 "
        "{%0,%1,%2,%3}, {%4,%5,%6,%7}, {%8,%9}, {%0,%1,%2,%3};"
        : "+f"(c[0]), "+f"(c[1]), "+f"(c[2]), "+f"(c[3])
        : "r"(a0), "r"(a1), "r"(a2), "r"(a3), "r"(b0), "r"(b1));
}
__device__ __forceinline__ void ldsm4(unsigned &r0, unsigned &r1, unsigned &r2,
                                      unsigned &r3, const void* p) {
    unsigned a = (unsigned)__cvta_generic_to_shared(p);
    asm volatile("ldmatrix.sync.aligned.m8n8.x4.shared.b16 {%0,%1,%2,%3}, [%4];"
                 : "=r"(r0), "=r"(r1), "=r"(r2), "=r"(r3) : "r"(a));
}

// ---------------------------------------------------------------------------
// RoPE tables
// ---------------------------------------------------------------------------
__global__ void rope_table_kernel() {
    int idx = blockIdx.x * blockDim.x + threadIdx.x;
    if (idx >= NS * 32) return;
    int s = idx >> 5, j = idx & 31;
    float invf = (float)exp(-(double)j * (log(10000.0) / 32.0));
    float ang = (float)s * invf;
    g_cos[idx] = (float)cos((double)ang);
    g_sin[idx] = (float)sin((double)ang);
}

__global__ void rope_apply_kernel(float* __restrict__ kptr) {
    int idx = blockIdx.x * blockDim.x + threadIdx.x;
    float* p = blockIdx.y ? kptr : g_q;
    int j = idx & 31;
    int row = idx >> 5;
    int s = row & (NS - 1);
    int base = row * 64 + j;
    float c = g_cos[(s << 5) + j], sn = g_sin[(s << 5) + j];
    float x1 = p[base], x2 = p[base + 32];
    p[base]      = x1 * c - x2 * sn;
    p[base + 32] = x2 * c + x1 * sn;
}

// ---------------------------------------------------------------------------
// TF32 tensor-core linear: CTA tile 128m x 256n, warp tile 64x64 (8 warps as
// 2m x 4n), k stages of 16, double buffered.  Fragments via ldmatrix; smem
// staging stores vectorized (STS.128).
// ---------------------------------------------------------------------------
#define KS 16
#define LPAD 20
#define LIN_SMEM ((2*128*LPAD + 2*256*LPAD) * 4)   // 61440 bytes

__global__ __launch_bounds__(256)
void linear_tc_kernel(const float* __restrict__ A, const float* __restrict__ W,
                      const float* __restrict__ bias, float* __restrict__ dst,
                      int headLayout)
{
    extern __shared__ unsigned lsm[];
    unsigned (*As)[128][LPAD] = (unsigned(*)[128][LPAD])lsm;
    unsigned (*Bs)[256][LPAD] = (unsigned(*)[256][LPAD])(lsm + 2*128*LPAD);

    int tid  = threadIdx.x;
    int w    = tid >> 5;
    int lane = tid & 31;
    int grp  = lane >> 2;
    int qid  = lane & 3;
    int wm   = (w & 1) * 64;        // warp m offset (0/64)
    int wn   = (w >> 1) * 64;       // warp n offset (0/64/128/192)

    int lane15   = lane & 15;
    int acolsel  = (lane >> 4) << 2;
    int b_rowoff = (lane & 7) + ((lane >> 4) << 3);
    int bcolsel  = ((lane >> 3) & 1) << 2;

    int m0 = blockIdx.y << 7, n0 = blockIdx.x << 8;

    int lrow  = tid >> 1;          // 0..127
    int kbase = (tid & 1) * 8;     // 0 or 8
    const float* aptr  = A + (size_t)(m0 + lrow) * NDIM + kbase;
    const float* bptr0 = W + (size_t)(n0 + lrow) * NDIM + kbase;
    const float* bptr1 = W + (size_t)(n0 + lrow + 128) * NDIM + kbase;

    float acc[4][8][4];
    #pragma unroll
    for (int mt = 0; mt < 4; mt++)
        #pragma unroll
        for (int nt = 0; nt < 8; nt++)
            #pragma unroll
            for (int r = 0; r < 4; r++) acc[mt][nt][r] = 0.f;

    float4 ra0 = *(const float4*)(aptr);
    float4 ra1 = *(const float4*)(aptr + 4);
    float4 rb00 = *(const float4*)(bptr0);
    float4 rb01 = *(const float4*)(bptr0 + 4);
    float4 rb10 = *(const float4*)(bptr1);
    float4 rb11 = *(const float4*)(bptr1 + 4);

    {
        uint4 u;
        u.x=f2tf32(ra0.x); u.y=f2tf32(ra0.y); u.z=f2tf32(ra0.z); u.w=f2tf32(ra0.w);
        *(uint4*)&As[0][lrow][kbase] = u;
        u.x=f2tf32(ra1.x); u.y=f2tf32(ra1.y); u.z=f2tf32(ra1.z); u.w=f2tf32(ra1.w);
        *(uint4*)&As[0][lrow][kbase+4] = u;
        u.x=f2tf32(rb00.x); u.y=f2tf32(rb00.y); u.z=f2tf32(rb00.z); u.w=f2tf32(rb00.w);
        *(uint4*)&Bs[0][lrow][kbase] = u;
        u.x=f2tf32(rb01.x); u.y=f2tf32(rb01.y); u.z=f2tf32(rb01.z); u.w=f2tf32(rb01.w);
        *(uint4*)&Bs[0][lrow][kbase+4] = u;
        u.x=f2tf32(rb10.x); u.y=f2tf32(rb10.y); u.z=f2tf32(rb10.z); u.w=f2tf32(rb10.w);
        *(uint4*)&Bs[0][lrow+128][kbase] = u;
        u.x=f2tf32(rb11.x); u.y=f2tf32(rb11.y); u.z=f2tf32(rb11.z); u.w=f2tf32(rb11.w);
        *(uint4*)&Bs[0][lrow+128][kbase+4] = u;
    }
    __syncthreads();

    int buf = 0;
    const int NKT = NDIM / KS;     // 64
    for (int kt = 0; kt < NKT; kt++) {
        if (kt < NKT - 1) {
            const float* ap = aptr + (kt + 1) * KS;
            const float* bp0 = bptr0 + (kt + 1) * KS;
            const float* bp1 = bptr1 + (kt + 1) * KS;
            ra0 = *(const float4*)(ap);
            ra1 = *(const float4*)(ap + 4);
            rb00 = *(const float4*)(bp0);
            rb01 = *(const float4*)(bp0 + 4);
            rb10 = *(const float4*)(bp1);
            rb11 = *(const float4*)(bp1 + 4);
        }

        #pragma unroll
        for (int sl = 0; sl < 2; sl++) {
            int kk = sl * 8;
            unsigned afr[4][4], bfr[8][2];
            #pragma unroll
            for (int mt = 0; mt < 4; mt++)
                ldsm4(afr[mt][0], afr[mt][1], afr[mt][2], afr[mt][3],
                      &As[buf][wm + mt * 16 + lane15][kk + acolsel]);
            #pragma unroll
            for (int ntp = 0; ntp < 4; ntp++) {
                unsigned r0, r1, r2, r3;
                ldsm4(r0, r1, r2, r3, &Bs[buf][wn + ntp * 16 + b_rowoff][kk + bcolsel]);
                bfr[ntp*2][0]   = r0; bfr[ntp*2][1]   = r1;
                bfr[ntp*2+1][0] = r2; bfr[ntp*2+1][1] = r3;
            }
            #pragma unroll
            for (int mt = 0; mt < 4; mt++)
                #pragma unroll
                for (int nt = 0; nt < 8; nt++)
                    mma_tf32(acc[mt][nt], afr[mt][0], afr[mt][1], afr[mt][2], afr[mt][3],
                             bfr[nt][0], bfr[nt][1]);
        }

        if (kt < NKT - 1) {
            int nb = buf ^ 1;
            uint4 u;
            u.x=f2tf32(ra0.x); u.y=f2tf32(ra0.y); u.z=f2tf32(ra0.z); u.w=f2tf32(ra0.w);
            *(uint4*)&As[nb][lrow][kbase] = u;
            u.x=f2tf32(ra1.x); u.y=f2tf32(ra1.y); u.z=f2tf32(ra1.z); u.w=f2tf32(ra1.w);
            *(uint4*)&As[nb][lrow][kbase+4] = u;
            u.x=f2tf32(rb00.x); u.y=f2tf32(rb00.y); u.z=f2tf32(rb00.z); u.w=f2tf32(rb00.w);
            *(uint4*)&Bs[nb][lrow][kbase] = u;
            u.x=f2tf32(rb01.x); u.y=f2tf32(rb01.y); u.z=f2tf32(rb01.z); u.w=f2tf32(rb01.w);
            *(uint4*)&Bs[nb][lrow][kbase+4] = u;
            u.x=f2tf32(rb10.x); u.y=f2tf32(rb10.y); u.z=f2tf32(rb10.z); u.w=f2tf32(rb10.w);
            *(uint4*)&Bs[nb][lrow+128][kbase] = u;
            u.x=f2tf32(rb11.x); u.y=f2tf32(rb11.y); u.z=f2tf32(rb11.z); u.w=f2tf32(rb11.w);
            *(uint4*)&Bs[nb][lrow+128][kbase+4] = u;
            __syncthreads();
            buf = nb;
        }
    }

    #pragma unroll
    for (int mt = 0; mt < 4; mt++) {
        #pragma unroll
        for (int nt = 0; nt < 8; nt++) {
            int n = n0 + wn + nt * 8 + (qid << 1);
            float bx = bias[n], by = bias[n + 1];
            #pragma unroll
            for (int half = 0; half < 2; half++) {
                int m = m0 + wm + mt * 16 + grp + half * 8;
                float2 v;
                v.x = acc[mt][nt][half * 2 + 0] + bx;
                v.y = acc[mt][nt][half * 2 + 1] + by;
                if (headLayout) {
                    int b = m >> 11, s = m & (NS - 1);
                    int h = n >> 6, d = n & 63;
                    *(float2*)&dst[(((size_t)((b << 4) + h) * NS + s)) * HD + d] = v;
                } else {
                    *(float2*)&dst[(size_t)m * NDIM + n] = v;
                }
            }
        }
    }
}

// ---------------------------------------------------------------------------
// TF32 MMA flash attention (R6 structure, vectorized Q/K staging stores).
// ---------------------------------------------------------------------------
#define APITCH 68
#define ATTN_SMEM ((128*APITCH + 128*APITCH + 64*APITCH) * 4)

__global__ __launch_bounds__(256, 2)
void attn_tc_kernel(const float* __restrict__ Kg, const float* __restrict__ Vg,
                    const int* __restrict__ mask)
{
    extern __shared__ unsigned sm_u[];
    unsigned* Qs  = sm_u;
    unsigned* KP  = sm_u + 128*APITCH;
    unsigned* VsT = KP + 128*APITCH;

    int tid = threadIdx.x;
    int w = tid >> 5, lane = tid & 31;
    int grp = lane >> 2, qid = lane & 3;
    int wm = w << 4;
    int bh = blockIdx.y;
    int b = bh >> 4, h = bh & 15;
    int q0 = blockIdx.x << 7;

    int lane15   = lane & 15;
    int acolsel  = (lane >> 4) << 2;
    int b_rowoff = (lane & 7) + ((lane >> 4) << 3);
    int bcolsel  = ((lane >> 3) & 1) << 2;

    const float* qptr = g_q + ((size_t)bh * NS + q0) * HD;
    const float* kptr = Kg + (size_t)bh * NS * HD;
    const float* vptr = Vg + (size_t)bh * NS * HD;
    const int* mrow0 = mask + ((size_t)b * NS + q0 + wm + grp) * NS;
    const int* mrow1 = mrow0 + 8 * NS;

    #pragma unroll
    for (int i = 0; i < 8; i++) {
        int lin = tid + (i << 8);
        int row = lin >> 4, d4 = (lin & 15) << 2;
        float4 qv = *(const float4*)(qptr + row * HD + d4);
        uint4 u;
        u.x=f2tf32(qv.x); u.y=f2tf32(qv.y); u.z=f2tf32(qv.z); u.w=f2tf32(qv.w);
        *(uint4*)&Qs[row * APITCH + d4] = u;
    }

    float o[8][4];
    #pragma unroll
    for (int nt = 0; nt < 8; nt++)
        #pragma unroll
        for (int r = 0; r < 4; r++) o[nt][r] = 0.f;
    float m0 = -3.0e38f, m1 = -3.0e38f, l0 = 0.f, l1 = 0.f;

    for (int k0 = 0; k0 < NS; k0 += 64) {
        __syncthreads();
        #pragma unroll
        for (int i = 0; i < 4; i++) {
            int lin = tid + (i << 8);
            int row = lin >> 4, d4 = (lin & 15) << 2;
            float4 kv = *(const float4*)(kptr + (k0 + row) * HD + d4);
            uint4 u;
            u.x=f2tf32(kv.x); u.y=f2tf32(kv.y); u.z=f2tf32(kv.z); u.w=f2tf32(kv.w);
            *(uint4*)&KP[row * APITCH + d4] = u;
        }
        #pragma unroll
        for (int i = 0; i < 4; i++) {
            int lin = tid + (i << 8);
            int key = lin & 63, d4 = (lin >> 6) << 2;
            float4 vv = *(const float4*)(vptr + (k0 + key) * HD + d4);
            VsT[(d4 + 0) * APITCH + key] = f2tf32(vv.x);
            VsT[(d4 + 1) * APITCH + key] = f2tf32(vv.y);
            VsT[(d4 + 2) * APITCH + key] = f2tf32(vv.z);
            VsT[(d4 + 3) * APITCH + key] = f2tf32(vv.w);
        }
        __syncthreads();

        float sc[8][4];
        #pragma unroll
        for (int nt = 0; nt < 8; nt++)
            #pragma unroll
            for (int r = 0; r < 4; r++) sc[nt][r] = 0.f;

        #pragma unroll
        for (int kk = 0; kk < 8; kk++) {
            unsigned a0, a1, a2, a3;
            ldsm4(a0, a1, a2, a3, &Qs[(wm + lane15) * APITCH + kk * 8 + acolsel]);
            #pragma unroll
            for (int ntp = 0; ntp < 4; ntp++) {
                unsigned r0, r1, r2, r3;
                ldsm4(r0, r1, r2, r3,
                      &KP[(ntp * 16 + b_rowoff) * APITCH + kk * 8 + bcolsel]);
                mma_tf32(sc[ntp*2],   a0, a1, a2, a3, r0, r1);
                mma_tf32(sc[ntp*2+1], a0, a1, a2, a3, r2, r3);
            }
        }

        #pragma unroll
        for (int nt = 0; nt < 8; nt++) {
            int col = k0 + nt * 8 + (qid << 1);
            int2 mA = *(const int2*)(mrow0 + col);
            int2 mB = *(const int2*)(mrow1 + col);
            sc[nt][0] = mA.x ? sc[nt][0] * 0.125f : -1e30f;
            sc[nt][1] = mA.y ? sc[nt][1] * 0.125f : -1e30f;
            sc[nt][2] = mB.x ? sc[nt][2] * 0.125f : -1e30f;
            sc[nt][3] = mB.y ? sc[nt][3] * 0.125f : -1e30f;
        }

        float mx0 = -3.0e38f, mx1 = -3.0e38f;
        #pragma unroll
        for (int nt = 0; nt < 8; nt++) {
            mx0 = fmaxf(mx0, fmaxf(sc[nt][0], sc[nt][1]));
            mx1 = fmaxf(mx1, fmaxf(sc[nt][2], sc[nt][3]));
        }
        mx0 = fmaxf(mx0, __shfl_xor_sync(0xffffffffu, mx0, 1));
        mx0 = fmaxf(mx0, __shfl_xor_sync(0xffffffffu, mx0, 2));
        mx1 = fmaxf(mx1, __shfl_xor_sync(0xffffffffu, mx1, 1));
        mx1 = fmaxf(mx1, __shfl_xor_sync(0xffffffffu, mx1, 2));

        float mn0 = fmaxf(m0, mx0), mn1 = fmaxf(m1, mx1);
        float corr0 = __expf(m0 - mn0), corr1 = __expf(m1 - mn1);
        m0 = mn0; m1 = mn1;

        float ps0 = 0.f, ps1 = 0.f;
        #pragma unroll
        for (int nt = 0; nt < 8; nt++) {
            sc[nt][0] = __expf(sc[nt][0] - mn0); ps0 += sc[nt][0];
            sc[nt][1] = __expf(sc[nt][1] - mn0); ps0 += sc[nt][1];
            sc[nt][2] = __expf(sc[nt][2] - mn1); ps1 += sc[nt][2];
            sc[nt][3] = __expf(sc[nt][3] - mn1); ps1 += sc[nt][3];
        }
        ps0 += __shfl_xor_sync(0xffffffffu, ps0, 1);
        ps0 += __shfl_xor_sync(0xffffffffu, ps0, 2);
        ps1 += __shfl_xor_sync(0xffffffffu, ps1, 1);
        ps1 += __shfl_xor_sync(0xffffffffu, ps1, 2);
        l0 = l0 * corr0 + ps0;
        l1 = l1 * corr1 + ps1;
        #pragma unroll
        for (int nt = 0; nt < 8; nt++) {
            o[nt][0] *= corr0; o[nt][1] *= corr0;
            o[nt][2] *= corr1; o[nt][3] *= corr1;
        }

        __syncthreads();
        #pragma unroll
        for (int nt = 0; nt < 8; nt++) {
            unsigned* p0 = &KP[(wm + grp) * APITCH + nt * 8 + (qid << 1)];
            p0[0] = f2tf32(sc[nt][0]); p0[1] = f2tf32(sc[nt][1]);
            unsigned* p1 = &KP[(wm + grp + 8) * APITCH + nt * 8 + (qid << 1)];
            p1[0] = f2tf32(sc[nt][2]); p1[1] = f2tf32(sc[nt][3]);
        }
        __syncthreads();

        #pragma unroll
        for (int kk = 0; kk < 8; kk++) {
            unsigned a0, a1, a2, a3;
            ldsm4(a0, a1, a2, a3, &KP[(wm + lane15) * APITCH + kk * 8 + acolsel]);
            #pragma unroll
            for (int ntp = 0; ntp < 4; ntp++) {
                unsigned r0, r1, r2, r3;
                ldsm4(r0, r1, r2, r3,
                      &VsT[(ntp * 16 + b_rowoff) * APITCH + kk * 8 + bcolsel]);
                mma_tf32(o[ntp*2],   a0, a1, a2, a3, r0, r1);
                mma_tf32(o[ntp*2+1], a0, a1, a2, a3, r2, r3);
            }
        }
    }

    float inv0 = 1.0f / l0, inv1 = 1.0f / l1;
    int r0 = q0 + wm + grp, r1 = r0 + 8;
    #pragma unroll
    for (int nt = 0; nt < 8; nt++) {
        int col = h * HD + nt * 8 + (qid << 1);
        float2 v0 = make_float2(o[nt][0] * inv0, o[nt][1] * inv0);
        float2 v1 = make_float2(o[nt][2] * inv1, o[nt][3] * inv1);
        *(float2*)&g_ctx[((size_t)b * NS + r0) * NDIM + col] = v0;
        *(float2*)&g_ctx[((size_t)b * NS + r1) * NDIM + col] = v1;
    }
}

// ---------------------------------------------------------------------------
extern "C" void kernel_launch(void* const* d_in, const int* in_sizes, int n_in,
                              void* d_out, int out_size) {
    const float* query = (const float*)d_in[0];
    const float* key   = (const float*)d_in[1];
    const float* value = (const float*)d_in[2];
    const int*   mask  = (const int*)d_in[3];
    const float* Wq = (const float*)d_in[4];
    const float* bq = (const float*)d_in[5];
    const float* Wk = (const float*)d_in[6];
    const float* bk = (const float*)d_in[7];
    const float* Wv = (const float*)d_in[8];
    const float* bv = (const float*)d_in[9];
    const float* Wo = (const float*)d_in[10];
    const float* bo = (const float*)d_in[11];

    float* out  = (float*)d_out;                 // [B,S,1024]
    float* outK = out + OUT_ELEMS;               // [B,H,S,64] (post-RoPE k)
    float* outV = out + 2 * (size_t)OUT_ELEMS;   // [B,H,S,64] (v)

    float* g_q_p;   cudaGetSymbolAddress((void**)&g_q_p, g_q);
    float* g_ctx_p; cudaGetSymbolAddress((void**)&g_ctx_p, g_ctx);

    static int smem_set = 0;
    if (!smem_set) {
        cudaFuncSetAttribute(attn_tc_kernel, cudaFuncAttributeMaxDynamicSharedMemorySize,
                             ATTN_SMEM);
        cudaFuncSetAttribute(linear_tc_kernel, cudaFuncAttributeMaxDynamicSharedMemorySize,
                             LIN_SMEM);
        smem_set = 1;
    }

    rope_table_kernel<<<(NS * 32 + 255) / 256, 256>>>();

    dim3 lgrid(NDIM / 256, NM / 128);   // (4, 32) = 128 CTAs
    linear_tc_kernel<<<lgrid, 256, LIN_SMEM>>>(query, Wq, bq, g_q_p, 1);
    linear_tc_kernel<<<lgrid, 256, LIN_SMEM>>>(key,   Wk, bk, outK,  1);
    linear_tc_kernel<<<lgrid, 256, LIN_SMEM>>>(value, Wv, bv, outV,  1);

    dim3 rgrid((NB * NH * NS * 32) / 256, 2);
    rope_apply_kernel<<<rgrid, 256>>>(outK);

    dim3 agrid(NS / 128, NB * NH);      // (16, 32)
    attn_tc_kernel<<<agrid, 256, ATTN_SMEM>>>(outK, outV, mask);

    linear_tc_kernel<<<lgrid, 256, LIN_SMEM>>>(g_ctx_p, Wo, bo, out, 0);
}

// round 9
// speedup vs baseline: 3.2887x; 1.1266x over previous
#include <cuda_runtime.h>
#include <cuda_fp16.h>
#include <math.h>

#define NB 2
#define NS 2048
#define NH 16
#define HD 64
#define NDIM 1024
#define NM (NB*NS)
#define OUT_ELEMS (NB*NS*NDIM)   // 4194304 per tensor (out, k, v)

// Scratch (allocation-free rule: __device__ globals)
__device__ float g_q[NB*NH*NS*HD];     // q after proj (+RoPE), [b,h,s,d]
__device__ float g_ctx[NB*NS*NDIM];    // attention context, [b,s, h*64+d] flat
__device__ float g_cos[NS*32];
__device__ float g_sin[NS*32];

__device__ __forceinline__ unsigned packh2(float x, float y) {
    __half2 h = __floats2half2_rn(x, y);
    return *(unsigned*)&h;
}
__device__ __forceinline__ void mma_f16(float c[4], unsigned a0, unsigned a1,
                                        unsigned a2, unsigned a3,
                                        unsigned b0, unsigned b1) {
    asm volatile(
        "mma.sync.aligned.m16n8k16.row.col.f32.f16.f16.f32 "
        "{%0,%1,%2,%3}, {%4,%5,%6,%7}, {%8,%9}, {%0,%1,%2,%3};"
        : "+f"(c[0]), "+f"(c[1]), "+f"(c[2]), "+f"(c[3])
        : "r"(a0), "r"(a1), "r"(a2), "r"(a3), "r"(b0), "r"(b1));
}
__device__ __forceinline__ void ldsm4(unsigned &r0, unsigned &r1, unsigned &r2,
                                      unsigned &r3, const void* p) {
    unsigned a = (unsigned)__cvta_generic_to_shared(p);
    asm volatile("ldmatrix.sync.aligned.m8n8.x4.shared.b16 {%0,%1,%2,%3}, [%4];"
                 : "=r"(r0), "=r"(r1), "=r"(r2), "=r"(r3) : "r"(a));
}

// ---------------------------------------------------------------------------
// RoPE tables
// ---------------------------------------------------------------------------
__global__ void rope_table_kernel() {
    int idx = blockIdx.x * blockDim.x + threadIdx.x;
    if (idx >= NS * 32) return;
    int s = idx >> 5, j = idx & 31;
    float invf = (float)exp(-(double)j * (log(10000.0) / 32.0));
    float ang = (float)s * invf;
    g_cos[idx] = (float)cos((double)ang);
    g_sin[idx] = (float)sin((double)ang);
}

__global__ void rope_apply_kernel(float* __restrict__ kptr) {
    int idx = blockIdx.x * blockDim.x + threadIdx.x;
    float* p = blockIdx.y ? kptr : g_q;
    int j = idx & 31;
    int row = idx >> 5;
    int s = row & (NS - 1);
    int base = row * 64 + j;
    float c = g_cos[(s << 5) + j], sn = g_sin[(s << 5) + j];
    float x1 = p[base], x2 = p[base + 32];
    p[base]      = x1 * c - x2 * sn;
    p[base + 32] = x2 * c + x1 * sn;
}

// ---------------------------------------------------------------------------
// FP16 tensor-core linear: CTA tile 128m x 256n, warp tile 64x64 (8 warps
// as 2m x 4n), k stages of 16, double buffered, m16n8k16 mma, fp32 accum.
// ---------------------------------------------------------------------------
#define KS 16
#define LPADH 24   // halves per row (48B stride; ldsm rows distinct mod 128)

__global__ __launch_bounds__(256)
void linear_tc_kernel(const float* __restrict__ A, const float* __restrict__ W,
                      const float* __restrict__ bias, float* __restrict__ dst,
                      int headLayout)
{
    __shared__ __align__(16) __half As[2][128][LPADH];
    __shared__ __align__(16) __half Bs[2][256][LPADH];

    int tid  = threadIdx.x;
    int w    = tid >> 5;
    int lane = tid & 31;
    int grp  = lane >> 2;
    int qid  = lane & 3;
    int wm   = (w & 1) * 64;
    int wn   = (w >> 1) * 64;

    int lane15   = lane & 15;
    int acolsel  = (lane >> 4) << 3;                 // halves: 0 or 8
    int b_rowoff = (lane & 7) + ((lane >> 4) << 3);
    int bcolsel  = ((lane >> 3) & 1) << 3;           // halves: 0 or 8

    int m0 = blockIdx.y << 7, n0 = blockIdx.x << 8;

    int lrow = tid >> 1;           // A row 0..127
    int kh   = (tid & 1) * 8;      // half-offset 0 or 8
    const float* aptr = A + (size_t)(m0 + lrow) * NDIM + kh;
    const float* bptr = W + (size_t)(n0 + tid) * NDIM;   // B: one row per thread

    float acc[4][8][4];
    #pragma unroll
    for (int mt = 0; mt < 4; mt++)
        #pragma unroll
        for (int nt = 0; nt < 8; nt++)
            #pragma unroll
            for (int r = 0; r < 4; r++) acc[mt][nt][r] = 0.f;

    float4 ra0 = *(const float4*)(aptr);
    float4 ra1 = *(const float4*)(aptr + 4);
    float4 rb0 = *(const float4*)(bptr);
    float4 rb1 = *(const float4*)(bptr + 4);
    float4 rb2 = *(const float4*)(bptr + 8);
    float4 rb3 = *(const float4*)(bptr + 12);

    {
        uint4 u;
        u.x = packh2(ra0.x, ra0.y); u.y = packh2(ra0.z, ra0.w);
        u.z = packh2(ra1.x, ra1.y); u.w = packh2(ra1.z, ra1.w);
        *(uint4*)&As[0][lrow][kh] = u;
        u.x = packh2(rb0.x, rb0.y); u.y = packh2(rb0.z, rb0.w);
        u.z = packh2(rb1.x, rb1.y); u.w = packh2(rb1.z, rb1.w);
        *(uint4*)&Bs[0][tid][0] = u;
        u.x = packh2(rb2.x, rb2.y); u.y = packh2(rb2.z, rb2.w);
        u.z = packh2(rb3.x, rb3.y); u.w = packh2(rb3.z, rb3.w);
        *(uint4*)&Bs[0][tid][8] = u;
    }
    __syncthreads();

    int buf = 0;
    const int NKT = NDIM / KS;     // 64
    for (int kt = 0; kt < NKT; kt++) {
        if (kt < NKT - 1) {
            const float* ap = aptr + (kt + 1) * KS;
            const float* bp = bptr + (kt + 1) * KS;
            ra0 = *(const float4*)(ap);
            ra1 = *(const float4*)(ap + 4);
            rb0 = *(const float4*)(bp);
            rb1 = *(const float4*)(bp + 4);
            rb2 = *(const float4*)(bp + 8);
            rb3 = *(const float4*)(bp + 12);
        }

        {
            unsigned afr[4][4], bfr[8][2];
            #pragma unroll
            for (int mt = 0; mt < 4; mt++)
                ldsm4(afr[mt][0], afr[mt][1], afr[mt][2], afr[mt][3],
                      &As[buf][wm + mt * 16 + lane15][acolsel]);
            #pragma unroll
            for (int ntp = 0; ntp < 4; ntp++) {
                unsigned r0, r1, r2, r3;
                ldsm4(r0, r1, r2, r3, &Bs[buf][wn + ntp * 16 + b_rowoff][bcolsel]);
                bfr[ntp*2][0]   = r0; bfr[ntp*2][1]   = r1;
                bfr[ntp*2+1][0] = r2; bfr[ntp*2+1][1] = r3;
            }
            #pragma unroll
            for (int mt = 0; mt < 4; mt++)
                #pragma unroll
                for (int nt = 0; nt < 8; nt++)
                    mma_f16(acc[mt][nt], afr[mt][0], afr[mt][1], afr[mt][2], afr[mt][3],
                            bfr[nt][0], bfr[nt][1]);
        }

        if (kt < NKT - 1) {
            int nb = buf ^ 1;
            uint4 u;
            u.x = packh2(ra0.x, ra0.y); u.y = packh2(ra0.z, ra0.w);
            u.z = packh2(ra1.x, ra1.y); u.w = packh2(ra1.z, ra1.w);
            *(uint4*)&As[nb][lrow][kh] = u;
            u.x = packh2(rb0.x, rb0.y); u.y = packh2(rb0.z, rb0.w);
            u.z = packh2(rb1.x, rb1.y); u.w = packh2(rb1.z, rb1.w);
            *(uint4*)&Bs[nb][tid][0] = u;
            u.x = packh2(rb2.x, rb2.y); u.y = packh2(rb2.z, rb2.w);
            u.z = packh2(rb3.x, rb3.y); u.w = packh2(rb3.z, rb3.w);
            *(uint4*)&Bs[nb][tid][8] = u;
            __syncthreads();
            buf = nb;
        }
    }

    #pragma unroll
    for (int mt = 0; mt < 4; mt++) {
        #pragma unroll
        for (int nt = 0; nt < 8; nt++) {
            int n = n0 + wn + nt * 8 + (qid << 1);
            float bx = bias[n], by = bias[n + 1];
            #pragma unroll
            for (int half = 0; half < 2; half++) {
                int m = m0 + wm + mt * 16 + grp + half * 8;
                float2 v;
                v.x = acc[mt][nt][half * 2 + 0] + bx;
                v.y = acc[mt][nt][half * 2 + 1] + by;
                if (headLayout) {
                    int b = m >> 11, s = m & (NS - 1);
                    int h = n >> 6, d = n & 63;
                    *(float2*)&dst[(((size_t)((b << 4) + h) * NS + s)) * HD + d] = v;
                } else {
                    *(float2*)&dst[(size_t)m * NDIM + n] = v;
                }
            }
        }
    }
}

// ---------------------------------------------------------------------------
// FP16 MMA flash attention.  BQ=128 (8 warps x 16 rows), BK=64 key tiles.
// Smem (halves, pitch 72): Qs[128] | KP[128] (K tile -> P tile) | VsT[64].
// ---------------------------------------------------------------------------
#define APH 72

__global__ __launch_bounds__(256, 2)
void attn_tc_kernel(const float* __restrict__ Kg, const float* __restrict__ Vg,
                    const int* __restrict__ mask)
{
    __shared__ __align__(16) __half Qs[128][APH];
    __shared__ __align__(16) __half KP[128][APH];
    __shared__ __align__(16) __half VsT[64][APH];

    int tid = threadIdx.x;
    int w = tid >> 5, lane = tid & 31;
    int grp = lane >> 2, qid = lane & 3;
    int wm = w << 4;
    int bh = blockIdx.y;
    int b = bh >> 4, h = bh & 15;
    int q0 = blockIdx.x << 7;

    int lane15   = lane & 15;
    int acolsel  = (lane >> 4) << 3;
    int b_rowoff = (lane & 7) + ((lane >> 4) << 3);
    int bcolsel  = ((lane >> 3) & 1) << 3;

    const float* qptr = g_q + ((size_t)bh * NS + q0) * HD;
    const float* kptr = Kg + (size_t)bh * NS * HD;
    const float* vptr = Vg + (size_t)bh * NS * HD;
    const int* mrow0 = mask + ((size_t)b * NS + q0 + wm + grp) * NS;
    const int* mrow1 = mrow0 + 8 * NS;

    #pragma unroll
    for (int i = 0; i < 8; i++) {
        int lin = tid + (i << 8);
        int row = lin >> 4, d4 = (lin & 15) << 2;
        float4 qv = *(const float4*)(qptr + row * HD + d4);
        uint2 u;
        u.x = packh2(qv.x, qv.y); u.y = packh2(qv.z, qv.w);
        *(uint2*)&Qs[row][d4] = u;
    }

    float o[8][4];
    #pragma unroll
    for (int nt = 0; nt < 8; nt++)
        #pragma unroll
        for (int r = 0; r < 4; r++) o[nt][r] = 0.f;
    float m0 = -3.0e38f, m1 = -3.0e38f, l0 = 0.f, l1 = 0.f;

    for (int k0 = 0; k0 < NS; k0 += 64) {
        __syncthreads();
        #pragma unroll
        for (int i = 0; i < 4; i++) {
            int lin = tid + (i << 8);
            int row = lin >> 4, d4 = (lin & 15) << 2;
            float4 kv = *(const float4*)(kptr + (k0 + row) * HD + d4);
            uint2 u;
            u.x = packh2(kv.x, kv.y); u.y = packh2(kv.z, kv.w);
            *(uint2*)&KP[row][d4] = u;
        }
        #pragma unroll
        for (int i = 0; i < 4; i++) {
            int lin = tid + (i << 8);
            int key = lin & 63, d4 = (lin >> 6) << 2;
            float4 vv = *(const float4*)(vptr + (k0 + key) * HD + d4);
            VsT[d4 + 0][key] = __float2half_rn(vv.x);
            VsT[d4 + 1][key] = __float2half_rn(vv.y);
            VsT[d4 + 2][key] = __float2half_rn(vv.z);
            VsT[d4 + 3][key] = __float2half_rn(vv.w);
        }
        __syncthreads();

        // S = Q K^T  (A = Q rows, B = K rows as n; k = head dim, 4 k16 steps)
        float sc[8][4];
        #pragma unroll
        for (int nt = 0; nt < 8; nt++)
            #pragma unroll
            for (int r = 0; r < 4; r++) sc[nt][r] = 0.f;

        #pragma unroll
        for (int kk = 0; kk < 4; kk++) {
            unsigned a0, a1, a2, a3;
            ldsm4(a0, a1, a2, a3, &Qs[wm + lane15][kk * 16 + acolsel]);
            #pragma unroll
            for (int ntp = 0; ntp < 4; ntp++) {
                unsigned r0, r1, r2, r3;
                ldsm4(r0, r1, r2, r3, &KP[ntp * 16 + b_rowoff][kk * 16 + bcolsel]);
                mma_f16(sc[ntp*2],   a0, a1, a2, a3, r0, r1);
                mma_f16(sc[ntp*2+1], a0, a1, a2, a3, r2, r3);
            }
        }

        // scale + mask
        #pragma unroll
        for (int nt = 0; nt < 8; nt++) {
            int col = k0 + nt * 8 + (qid << 1);
            int2 mA = *(const int2*)(mrow0 + col);
            int2 mB = *(const int2*)(mrow1 + col);
            sc[nt][0] = mA.x ? sc[nt][0] * 0.125f : -1e30f;
            sc[nt][1] = mA.y ? sc[nt][1] * 0.125f : -1e30f;
            sc[nt][2] = mB.x ? sc[nt][2] * 0.125f : -1e30f;
            sc[nt][3] = mB.y ? sc[nt][3] * 0.125f : -1e30f;
        }

        // online softmax (rows grp and grp+8; reduce over 4 qid lanes)
        float mx0 = -3.0e38f, mx1 = -3.0e38f;
        #pragma unroll
        for (int nt = 0; nt < 8; nt++) {
            mx0 = fmaxf(mx0, fmaxf(sc[nt][0], sc[nt][1]));
            mx1 = fmaxf(mx1, fmaxf(sc[nt][2], sc[nt][3]));
        }
        mx0 = fmaxf(mx0, __shfl_xor_sync(0xffffffffu, mx0, 1));
        mx0 = fmaxf(mx0, __shfl_xor_sync(0xffffffffu, mx0, 2));
        mx1 = fmaxf(mx1, __shfl_xor_sync(0xffffffffu, mx1, 1));
        mx1 = fmaxf(mx1, __shfl_xor_sync(0xffffffffu, mx1, 2));

        float mn0 = fmaxf(m0, mx0), mn1 = fmaxf(m1, mx1);
        float corr0 = __expf(m0 - mn0), corr1 = __expf(m1 - mn1);
        m0 = mn0; m1 = mn1;

        float ps0 = 0.f, ps1 = 0.f;
        #pragma unroll
        for (int nt = 0; nt < 8; nt++) {
            sc[nt][0] = __expf(sc[nt][0] - mn0); ps0 += sc[nt][0];
            sc[nt][1] = __expf(sc[nt][1] - mn0); ps0 += sc[nt][1];
            sc[nt][2] = __expf(sc[nt][2] - mn1); ps1 += sc[nt][2];
            sc[nt][3] = __expf(sc[nt][3] - mn1); ps1 += sc[nt][3];
        }
        ps0 += __shfl_xor_sync(0xffffffffu, ps0, 1);
        ps0 += __shfl_xor_sync(0xffffffffu, ps0, 2);
        ps1 += __shfl_xor_sync(0xffffffffu, ps1, 1);
        ps1 += __shfl_xor_sync(0xffffffffu, ps1, 2);
        l0 = l0 * corr0 + ps0;
        l1 = l1 * corr1 + ps1;
        #pragma unroll
        for (int nt = 0; nt < 8; nt++) {
            o[nt][0] *= corr0; o[nt][1] *= corr0;
            o[nt][2] *= corr1; o[nt][3] *= corr1;
        }

        __syncthreads();   // all warps done reading K tile (P overlays it)
        #pragma unroll
        for (int nt = 0; nt < 8; nt++) {
            *(unsigned*)&KP[wm + grp][nt * 8 + (qid << 1)] =
                packh2(sc[nt][0], sc[nt][1]);
            *(unsigned*)&KP[wm + grp + 8][nt * 8 + (qid << 1)] =
                packh2(sc[nt][2], sc[nt][3]);
        }
        __syncthreads();

        // O += P V  (A = P rows [q][key], B = VsT rows [dim][key]; 4 k16 steps)
        #pragma unroll
        for (int kk = 0; kk < 4; kk++) {
            unsigned a0, a1, a2, a3;
            ldsm4(a0, a1, a2, a3, &KP[wm + lane15][kk * 16 + acolsel]);
            #pragma unroll
            for (int ntp = 0; ntp < 4; ntp++) {
                unsigned r0, r1, r2, r3;
                ldsm4(r0, r1, r2, r3, &VsT[ntp * 16 + b_rowoff][kk * 16 + bcolsel]);
                mma_f16(o[ntp*2],   a0, a1, a2, a3, r0, r1);
                mma_f16(o[ntp*2+1], a0, a1, a2, a3, r2, r3);
            }
        }
    }

    float inv0 = 1.0f / l0, inv1 = 1.0f / l1;
    int r0 = q0 + wm + grp, r1 = r0 + 8;
    #pragma unroll
    for (int nt = 0; nt < 8; nt++) {
        int col = h * HD + nt * 8 + (qid << 1);
        float2 v0 = make_float2(o[nt][0] * inv0, o[nt][1] * inv0);
        float2 v1 = make_float2(o[nt][2] * inv1, o[nt][3] * inv1);
        *(float2*)&g_ctx[((size_t)b * NS + r0) * NDIM + col] = v0;
        *(float2*)&g_ctx[((size_t)b * NS + r1) * NDIM + col] = v1;
    }
}

// ---------------------------------------------------------------------------
extern "C" void kernel_launch(void* const* d_in, const int* in_sizes, int n_in,
                              void* d_out, int out_size) {
    const float* query = (const float*)d_in[0];
    const float* key   = (const float*)d_in[1];
    const float* value = (const float*)d_in[2];
    const int*   mask  = (const int*)d_in[3];
    const float* Wq = (const float*)d_in[4];
    const float* bq = (const float*)d_in[5];
    const float* Wk = (const float*)d_in[6];
    const float* bk = (const float*)d_in[7];
    const float* Wv = (const float*)d_in[8];
    const float* bv = (const float*)d_in[9];
    const float* Wo = (const float*)d_in[10];
    const float* bo = (const float*)d_in[11];

    float* out  = (float*)d_out;                 // [B,S,1024]
    float* outK = out + OUT_ELEMS;               // [B,H,S,64] (post-RoPE k)
    float* outV = out + 2 * (size_t)OUT_ELEMS;   // [B,H,S,64] (v)

    float* g_q_p;   cudaGetSymbolAddress((void**)&g_q_p, g_q);
    float* g_ctx_p; cudaGetSymbolAddress((void**)&g_ctx_p, g_ctx);

    rope_table_kernel<<<(NS * 32 + 255) / 256, 256>>>();

    dim3 lgrid(NDIM / 256, NM / 128);   // (4, 32) = 128 CTAs
    linear_tc_kernel<<<lgrid, 256>>>(query, Wq, bq, g_q_p, 1);
    linear_tc_kernel<<<lgrid, 256>>>(key,   Wk, bk, outK,  1);
    linear_tc_kernel<<<lgrid, 256>>>(value, Wv, bv, outV,  1);

    dim3 rgrid((NB * NH * NS * 32) / 256, 2);
    rope_apply_kernel<<<rgrid, 256>>>(outK);

    dim3 agrid(NS / 128, NB * NH);      // (16, 32)
    attn_tc_kernel<<<agrid, 256>>>(outK, outV, mask);

    linear_tc_kernel<<<lgrid, 256>>>(g_ctx_p, Wo, bo, out, 0);
}

// round 10
// speedup vs baseline: 4.8652x; 1.4794x over previous
#include <cuda_runtime.h>
#include <cuda_fp16.h>
#include <math.h>

#define NB 2
#define NS 2048
#define NH 16
#define HD 64
#define NDIM 1024
#define NM (NB*NS)
#define OUT_ELEMS (NB*NS*NDIM)   // 4194304 per tensor (out, k, v)

// Scratch (allocation-free rule: __device__ globals)
__device__ __align__(256) float  g_q[NB*NH*NS*HD];   // q proj (+RoPE), fp32
__device__ __align__(256) float  g_ctx[NB*NS*NDIM];  // attention context fp32
__device__ __align__(256) __half g_ah[NM*NDIM];      // half A operand buffer
__device__ __align__(256) __half g_wh[NDIM*NDIM];    // half W operand buffer
__device__ __align__(256) __half g_qh[NB*NH*NS*HD];  // half Q [b,h,s,d]
__device__ __align__(256) __half g_kh[NB*NH*NS*HD];  // half K [b,h,s,d]
__device__ __align__(256) __half g_vTh[NB*NH*HD*NS]; // half V transposed [b,h,d,s]
__device__ float g_cos[NS*32];
__device__ float g_sin[NS*32];

__device__ __forceinline__ unsigned packh2(float x, float y) {
    __half2 h = __floats2half2_rn(x, y);
    return *(unsigned*)&h;
}
__device__ __forceinline__ void mma_f16(float c[4], unsigned a0, unsigned a1,
                                        unsigned a2, unsigned a3,
                                        unsigned b0, unsigned b1) {
    asm volatile(
        "mma.sync.aligned.m16n8k16.row.col.f32.f16.f16.f32 "
        "{%0,%1,%2,%3}, {%4,%5,%6,%7}, {%8,%9}, {%0,%1,%2,%3};"
        : "+f"(c[0]), "+f"(c[1]), "+f"(c[2]), "+f"(c[3])
        : "r"(a0), "r"(a1), "r"(a2), "r"(a3), "r"(b0), "r"(b1));
}
__device__ __forceinline__ void ldsm4(unsigned &r0, unsigned &r1, unsigned &r2,
                                      unsigned &r3, const void* p) {
    unsigned a = (unsigned)__cvta_generic_to_shared(p);
    asm volatile("ldmatrix.sync.aligned.m8n8.x4.shared.b16 {%0,%1,%2,%3}, [%4];"
                 : "=r"(r0), "=r"(r1), "=r"(r2), "=r"(r3) : "r"(a));
}
#define CP16(dst_u32, src_ptr) \
    asm volatile("cp.async.ca.shared.global [%0], [%1], 16;" \
                 :: "r"(dst_u32), "l"(src_ptr))
#define CP_COMMIT() asm volatile("cp.async.commit_group;" ::: "memory")
#define CP_WAIT1()  asm volatile("cp.async.wait_group 1;" ::: "memory")

// ---------------------------------------------------------------------------
// RoPE
// ---------------------------------------------------------------------------
__global__ void rope_table_kernel() {
    int idx = blockIdx.x * blockDim.x + threadIdx.x;
    if (idx >= NS * 32) return;
    int s = idx >> 5, j = idx & 31;
    float invf = (float)exp(-(double)j * (log(10000.0) / 32.0));
    float ang = (float)s * invf;
    g_cos[idx] = (float)cos((double)ang);
    g_sin[idx] = (float)sin((double)ang);
}

__global__ void rope_apply_kernel(float* __restrict__ kptr) {
    int idx = blockIdx.x * blockDim.x + threadIdx.x;
    float* p = blockIdx.y ? kptr : g_q;
    int j = idx & 31;
    int row = idx >> 5;
    int s = row & (NS - 1);
    int base = row * 64 + j;
    float c = g_cos[(s << 5) + j], sn = g_sin[(s << 5) + j];
    float x1 = p[base], x2 = p[base + 32];
    p[base]      = x1 * c - x2 * sn;
    p[base + 32] = x2 * c + x1 * sn;
}

// ---------------------------------------------------------------------------
// fp32 -> fp16 convert (vectorized)
// ---------------------------------------------------------------------------
__global__ void f2h_kernel(const float* __restrict__ in, __half* __restrict__ out,
                           int n4) {
    int i = blockIdx.x * blockDim.x + threadIdx.x;
    if (i >= n4) return;
    float4 v = ((const float4*)in)[i];
    uint2 u; u.x = packh2(v.x, v.y); u.y = packh2(v.z, v.w);
    ((uint2*)out)[i] = u;
}

// V [b,h,s,d] fp32 -> [b,h,d,s] fp16, smem-tiled. Block = (bh, 128-s chunk).
__global__ void vT_kernel(const float* __restrict__ in) {
    __shared__ __half t[64][136];
    int tid = threadIdx.x;
    int bh = blockIdx.y;
    int s0 = blockIdx.x << 7;
    const float* src = in + ((size_t)bh * NS + s0) * HD;
    #pragma unroll
    for (int it = 0; it < 8; it++) {
        int c = tid + (it << 8);
        int s = c >> 4, d4 = (c & 15) << 2;
        float4 v = *(const float4*)(src + s * HD + d4);
        t[d4 + 0][s] = __float2half_rn(v.x);
        t[d4 + 1][s] = __float2half_rn(v.y);
        t[d4 + 2][s] = __float2half_rn(v.z);
        t[d4 + 3][s] = __float2half_rn(v.w);
    }
    __syncthreads();
    __half* dst = g_vTh + (size_t)bh * HD * NS + s0;
    #pragma unroll
    for (int it = 0; it < 4; it++) {
        int c = tid + (it << 8);
        int d = c >> 4, s8 = (c & 15) << 3;
        *(uint4*)(dst + d * NS + s8) = *(const uint4*)&t[d][s8];
    }
}

// ---------------------------------------------------------------------------
// FP16 linear, cp.async 3-stage pipeline.  CTA 128m x 256n, warp 64x64,
// K stages of 32 (two k16 mma slices per stage), m16n8k16, fp32 accum.
// ---------------------------------------------------------------------------
#define LP 40                     // halves per smem row (80B, 16B-aligned)
#define LIN_SMEM (3*(128+256)*LP*2)   // 92160 bytes

__global__ __launch_bounds__(256)
void linear_tc_kernel(const __half* __restrict__ Ah, const __half* __restrict__ Wh,
                      const float* __restrict__ bias, float* __restrict__ dst,
                      int headLayout)
{
    extern __shared__ __align__(16) __half lsm[];
    __half* AsB = lsm;                         // 3 stages of [128][LP]
    __half* BsB = lsm + 3 * 128 * LP;          // 3 stages of [256][LP]
    unsigned As_u = (unsigned)__cvta_generic_to_shared(AsB);
    unsigned Bs_u = (unsigned)__cvta_generic_to_shared(BsB);

    int tid  = threadIdx.x;
    int w    = tid >> 5;
    int lane = tid & 31;
    int grp  = lane >> 2;
    int qid  = lane & 3;
    int wm   = (w & 1) * 64;
    int wn   = (w >> 1) * 64;

    int lane15   = lane & 15;
    int acolsel  = (lane >> 4) << 3;
    int b_rowoff = (lane & 7) + ((lane >> 4) << 3);
    int bcolsel  = ((lane >> 3) & 1) << 3;

    int m0 = blockIdx.y << 7, n0 = blockIdx.x << 8;

    // loader mapping (16B chunks of 8 halves)
    int arow = tid >> 2, aseg = tid & 3;       // +2 chunks: rows tid>>2, tid>>2+64
    const __half* abase = Ah + (size_t)(m0 + arow) * NDIM + aseg * 8;
    const __half* bbase = Wh + (size_t)(n0 + arow) * NDIM + aseg * 8;

    float acc[4][8][4];
    #pragma unroll
    for (int mt = 0; mt < 4; mt++)
        #pragma unroll
        for (int nt = 0; nt < 8; nt++)
            #pragma unroll
            for (int r = 0; r < 4; r++) acc[mt][nt][r] = 0.f;

    // issue stage ld for k-tile kt into pipeline slot st
    auto issue = [&](int kt, int st) {
        unsigned adst = As_u + (st * 128 * LP) * 2;
        unsigned bdst = Bs_u + (st * 256 * LP) * 2;
        int koff = kt * 32;
        #pragma unroll
        for (int i = 0; i < 2; i++) {
            int row = arow + i * 64;
            CP16(adst + (row * LP + aseg * 8) * 2, abase + (size_t)i * 64 * NDIM + koff);
        }
        #pragma unroll
        for (int i = 0; i < 4; i++) {
            int row = arow + i * 64;
            CP16(bdst + (row * LP + aseg * 8) * 2, bbase + (size_t)i * 64 * NDIM + koff);
        }
    };

    issue(0, 0); CP_COMMIT();
    issue(1, 1); CP_COMMIT();

    const int NKT = NDIM / 32;   // 32
    int st = 0;
    for (int kt = 0; kt < NKT; kt++) {
        CP_WAIT1();
        __syncthreads();
        if (kt + 2 < NKT) {
            int nst = st + 2; if (nst >= 3) nst -= 3;
            issue(kt + 2, nst);
        }
        CP_COMMIT();

        const __half* Asst = AsB + st * 128 * LP;
        const __half* Bsst = BsB + st * 256 * LP;
        #pragma unroll
        for (int sl = 0; sl < 2; sl++) {
            int kof = sl * 16;
            unsigned afr[4][4], bfr[8][2];
            #pragma unroll
            for (int mt = 0; mt < 4; mt++)
                ldsm4(afr[mt][0], afr[mt][1], afr[mt][2], afr[mt][3],
                      Asst + (wm + mt * 16 + lane15) * LP + kof + acolsel);
            #pragma unroll
            for (int ntp = 0; ntp < 4; ntp++) {
                unsigned r0, r1, r2, r3;
                ldsm4(r0, r1, r2, r3,
                      Bsst + (wn + ntp * 16 + b_rowoff) * LP + kof + bcolsel);
                bfr[ntp*2][0]   = r0; bfr[ntp*2][1]   = r1;
                bfr[ntp*2+1][0] = r2; bfr[ntp*2+1][1] = r3;
            }
            #pragma unroll
            for (int mt = 0; mt < 4; mt++)
                #pragma unroll
                for (int nt = 0; nt < 8; nt++)
                    mma_f16(acc[mt][nt], afr[mt][0], afr[mt][1], afr[mt][2], afr[mt][3],
                            bfr[nt][0], bfr[nt][1]);
        }
        st++; if (st >= 3) st = 0;
    }

    #pragma unroll
    for (int mt = 0; mt < 4; mt++) {
        #pragma unroll
        for (int nt = 0; nt < 8; nt++) {
            int n = n0 + wn + nt * 8 + (qid << 1);
            float bx = bias[n], by = bias[n + 1];
            #pragma unroll
            for (int half = 0; half < 2; half++) {
                int m = m0 + wm + mt * 16 + grp + half * 8;
                float2 v;
                v.x = acc[mt][nt][half * 2 + 0] + bx;
                v.y = acc[mt][nt][half * 2 + 1] + by;
                if (headLayout) {
                    int b = m >> 11, s = m & (NS - 1);
                    int h = n >> 6, d = n & 63;
                    *(float2*)&dst[(((size_t)((b << 4) + h) * NS + s)) * HD + d] = v;
                } else {
                    *(float2*)&dst[(size_t)m * NDIM + n] = v;
                }
            }
        }
    }
}

// ---------------------------------------------------------------------------
// FP16 MMA flash attention.  BQ=128 (8 warps x 16 rows), BK=64 key tiles.
// Half inputs: g_qh/g_kh [b,h,s,d], g_vTh [b,h,d,s].  Vectorized loaders.
// ---------------------------------------------------------------------------
#define APH 72

__global__ __launch_bounds__(256, 2)
void attn_tc_kernel(const int* __restrict__ mask)
{
    __shared__ __align__(16) __half Qs[128][APH];
    __shared__ __align__(16) __half KP[128][APH];
    __shared__ __align__(16) __half VsT[64][APH];

    int tid = threadIdx.x;
    int w = tid >> 5, lane = tid & 31;
    int grp = lane >> 2, qid = lane & 3;
    int wm = w << 4;
    int bh = blockIdx.y;
    int b = bh >> 4, h = bh & 15;
    int q0 = blockIdx.x << 7;

    int lane15   = lane & 15;
    int acolsel  = (lane >> 4) << 3;
    int b_rowoff = (lane & 7) + ((lane >> 4) << 3);
    int bcolsel  = ((lane >> 3) & 1) << 3;

    const __half* qptr  = g_qh + ((size_t)bh * NS + q0) * HD;
    const __half* kptr  = g_kh + (size_t)bh * NS * HD;
    const __half* vTptr = g_vTh + (size_t)bh * HD * NS;
    const int* mrow0 = mask + ((size_t)b * NS + q0 + wm + grp) * NS;
    const int* mrow1 = mrow0 + 8 * NS;

    // Q tile: 1024 16B chunks, 4/thread
    #pragma unroll
    for (int i = 0; i < 4; i++) {
        int c = tid + (i << 8);
        int row = c >> 3, seg = c & 7;
        *(uint4*)&Qs[row][seg * 8] = *(const uint4*)(qptr + row * HD + seg * 8);
    }

    float o[8][4];
    #pragma unroll
    for (int nt = 0; nt < 8; nt++)
        #pragma unroll
        for (int r = 0; r < 4; r++) o[nt][r] = 0.f;
    float m0 = -3.0e38f, m1 = -3.0e38f, l0 = 0.f, l1 = 0.f;

    for (int k0 = 0; k0 < NS; k0 += 64) {
        __syncthreads();
        // K tile: 512 chunks, 2/thread
        #pragma unroll
        for (int i = 0; i < 2; i++) {
            int c = tid + (i << 8);
            int row = c >> 3, seg = c & 7;
            *(uint4*)&KP[row][seg * 8] =
                *(const uint4*)(kptr + (k0 + row) * HD + seg * 8);
        }
        // V tile (transposed layout in gmem): 512 chunks, 2/thread
        #pragma unroll
        for (int i = 0; i < 2; i++) {
            int c = tid + (i << 8);
            int d = c >> 3, seg = c & 7;
            *(uint4*)&VsT[d][seg * 8] =
                *(const uint4*)(vTptr + d * NS + k0 + seg * 8);
        }
        __syncthreads();

        // S = Q K^T
        float sc[8][4];
        #pragma unroll
        for (int nt = 0; nt < 8; nt++)
            #pragma unroll
            for (int r = 0; r < 4; r++) sc[nt][r] = 0.f;

        #pragma unroll
        for (int kk = 0; kk < 4; kk++) {
            unsigned a0, a1, a2, a3;
            ldsm4(a0, a1, a2, a3, &Qs[wm + lane15][kk * 16 + acolsel]);
            #pragma unroll
            for (int ntp = 0; ntp < 4; ntp++) {
                unsigned r0, r1, r2, r3;
                ldsm4(r0, r1, r2, r3, &KP[ntp * 16 + b_rowoff][kk * 16 + bcolsel]);
                mma_f16(sc[ntp*2],   a0, a1, a2, a3, r0, r1);
                mma_f16(sc[ntp*2+1], a0, a1, a2, a3, r2, r3);
            }
        }

        #pragma unroll
        for (int nt = 0; nt < 8; nt++) {
            int col = k0 + nt * 8 + (qid << 1);
            int2 mA = *(const int2*)(mrow0 + col);
            int2 mB = *(const int2*)(mrow1 + col);
            sc[nt][0] = mA.x ? sc[nt][0] * 0.125f : -1e30f;
            sc[nt][1] = mA.y ? sc[nt][1] * 0.125f : -1e30f;
            sc[nt][2] = mB.x ? sc[nt][2] * 0.125f : -1e30f;
            sc[nt][3] = mB.y ? sc[nt][3] * 0.125f : -1e30f;
        }

        float mx0 = -3.0e38f, mx1 = -3.0e38f;
        #pragma unroll
        for (int nt = 0; nt < 8; nt++) {
            mx0 = fmaxf(mx0, fmaxf(sc[nt][0], sc[nt][1]));
            mx1 = fmaxf(mx1, fmaxf(sc[nt][2], sc[nt][3]));
        }
        mx0 = fmaxf(mx0, __shfl_xor_sync(0xffffffffu, mx0, 1));
        mx0 = fmaxf(mx0, __shfl_xor_sync(0xffffffffu, mx0, 2));
        mx1 = fmaxf(mx1, __shfl_xor_sync(0xffffffffu, mx1, 1));
        mx1 = fmaxf(mx1, __shfl_xor_sync(0xffffffffu, mx1, 2));

        float mn0 = fmaxf(m0, mx0), mn1 = fmaxf(m1, mx1);
        float corr0 = __expf(m0 - mn0), corr1 = __expf(m1 - mn1);
        m0 = mn0; m1 = mn1;

        float ps0 = 0.f, ps1 = 0.f;
        #pragma unroll
        for (int nt = 0; nt < 8; nt++) {
            sc[nt][0] = __expf(sc[nt][0] - mn0); ps0 += sc[nt][0];
            sc[nt][1] = __expf(sc[nt][1] - mn0); ps0 += sc[nt][1];
            sc[nt][2] = __expf(sc[nt][2] - mn1); ps1 += sc[nt][2];
            sc[nt][3] = __expf(sc[nt][3] - mn1); ps1 += sc[nt][3];
        }
        ps0 += __shfl_xor_sync(0xffffffffu, ps0, 1);
        ps0 += __shfl_xor_sync(0xffffffffu, ps0, 2);
        ps1 += __shfl_xor_sync(0xffffffffu, ps1, 1);
        ps1 += __shfl_xor_sync(0xffffffffu, ps1, 2);
        l0 = l0 * corr0 + ps0;
        l1 = l1 * corr1 + ps1;
        #pragma unroll
        for (int nt = 0; nt < 8; nt++) {
            o[nt][0] *= corr0; o[nt][1] *= corr0;
            o[nt][2] *= corr1; o[nt][3] *= corr1;
        }

        __syncthreads();
        #pragma unroll
        for (int nt = 0; nt < 8; nt++) {
            *(unsigned*)&KP[wm + grp][nt * 8 + (qid << 1)] =
                packh2(sc[nt][0], sc[nt][1]);
            *(unsigned*)&KP[wm + grp + 8][nt * 8 + (qid << 1)] =
                packh2(sc[nt][2], sc[nt][3]);
        }
        __syncthreads();

        // O += P V
        #pragma unroll
        for (int kk = 0; kk < 4; kk++) {
            unsigned a0, a1, a2, a3;
            ldsm4(a0, a1, a2, a3, &KP[wm + lane15][kk * 16 + acolsel]);
            #pragma unroll
            for (int ntp = 0; ntp < 4; ntp++) {
                unsigned r0, r1, r2, r3;
                ldsm4(r0, r1, r2, r3, &VsT[ntp * 16 + b_rowoff][kk * 16 + bcolsel]);
                mma_f16(o[ntp*2],   a0, a1, a2, a3, r0, r1);
                mma_f16(o[ntp*2+1], a0, a1, a2, a3, r2, r3);
            }
        }
    }

    float inv0 = 1.0f / l0, inv1 = 1.0f / l1;
    int r0 = q0 + wm + grp, r1 = r0 + 8;
    #pragma unroll
    for (int nt = 0; nt < 8; nt++) {
        int col = h * HD + nt * 8 + (qid << 1);
        float2 v0 = make_float2(o[nt][0] * inv0, o[nt][1] * inv0);
        float2 v1 = make_float2(o[nt][2] * inv1, o[nt][3] * inv1);
        *(float2*)&g_ctx[((size_t)b * NS + r0) * NDIM + col] = v0;
        *(float2*)&g_ctx[((size_t)b * NS + r1) * NDIM + col] = v1;
    }
}

// ---------------------------------------------------------------------------
extern "C" void kernel_launch(void* const* d_in, const int* in_sizes, int n_in,
                              void* d_out, int out_size) {
    const float* query = (const float*)d_in[0];
    const float* key   = (const float*)d_in[1];
    const float* value = (const float*)d_in[2];
    const int*   mask  = (const int*)d_in[3];
    const float* Wq = (const float*)d_in[4];
    const float* bq = (const float*)d_in[5];
    const float* Wk = (const float*)d_in[6];
    const float* bk = (const float*)d_in[7];
    const float* Wv = (const float*)d_in[8];
    const float* bv = (const float*)d_in[9];
    const float* Wo = (const float*)d_in[10];
    const float* bo = (const float*)d_in[11];

    float* out  = (float*)d_out;                 // [B,S,1024]
    float* outK = out + OUT_ELEMS;               // [B,H,S,64] (post-RoPE k)
    float* outV = out + 2 * (size_t)OUT_ELEMS;   // [B,H,S,64] (v)

    float*  g_q_p;   cudaGetSymbolAddress((void**)&g_q_p, g_q);
    float*  g_ctx_p; cudaGetSymbolAddress((void**)&g_ctx_p, g_ctx);
    __half* g_ah_p;  cudaGetSymbolAddress((void**)&g_ah_p, g_ah);
    __half* g_wh_p;  cudaGetSymbolAddress((void**)&g_wh_p, g_wh);
    __half* g_qh_p;  cudaGetSymbolAddress((void**)&g_qh_p, g_qh);
    __half* g_kh_p;  cudaGetSymbolAddress((void**)&g_kh_p, g_kh);

    static int smem_set = 0;
    if (!smem_set) {
        cudaFuncSetAttribute(linear_tc_kernel, cudaFuncAttributeMaxDynamicSharedMemorySize,
                             LIN_SMEM);
        smem_set = 1;
    }

    const int A4 = NM * NDIM / 4;       // float4 count for A-size tensors
    const int W4 = NDIM * NDIM / 4;

    rope_table_kernel<<<(NS * 32 + 255) / 256, 256>>>();

    dim3 lgrid(NDIM / 256, NM / 128);   // (4, 32) = 128 CTAs

    f2h_kernel<<<A4 / 256, 256>>>(query, g_ah_p, A4);
    f2h_kernel<<<W4 / 256, 256>>>(Wq, g_wh_p, W4);
    linear_tc_kernel<<<lgrid, 256, LIN_SMEM>>>(g_ah_p, g_wh_p, bq, g_q_p, 1);

    f2h_kernel<<<A4 / 256, 256>>>(key, g_ah_p, A4);
    f2h_kernel<<<W4 / 256, 256>>>(Wk, g_wh_p, W4);
    linear_tc_kernel<<<lgrid, 256, LIN_SMEM>>>(g_ah_p, g_wh_p, bk, outK, 1);

    f2h_kernel<<<A4 / 256, 256>>>(value, g_ah_p, A4);
    f2h_kernel<<<W4 / 256, 256>>>(Wv, g_wh_p, W4);
    linear_tc_kernel<<<lgrid, 256, LIN_SMEM>>>(g_ah_p, g_wh_p, bv, outV, 1);

    dim3 rgrid((NB * NH * NS * 32) / 256, 2);
    rope_apply_kernel<<<rgrid, 256>>>(outK);

    // half copies for attention
    f2h_kernel<<<A4 / 256, 256>>>(g_q_p, g_qh_p, A4);
    f2h_kernel<<<A4 / 256, 256>>>(outK, g_kh_p, A4);
    dim3 vgrid(NS / 128, NB * NH);
    vT_kernel<<<vgrid, 256>>>(outV);

    dim3 agrid(NS / 128, NB * NH);      // (16, 32)
    attn_tc_kernel<<<agrid, 256>>>(mask);

    f2h_kernel<<<A4 / 256, 256>>>(g_ctx_p, g_ah_p, A4);
    f2h_kernel<<<W4 / 256, 256>>>(Wo, g_wh_p, W4);
    linear_tc_kernel<<<lgrid, 256, LIN_SMEM>>>(g_ah_p, g_wh_p, bo, out, 0);
}

// round 11
// speedup vs baseline: 5.4756x; 1.1255x over previous
#include <cuda_runtime.h>
#include <cuda_fp16.h>
#include <math.h>

#define NB 2
#define NS 2048
#define NH 16
#define HD 64
#define NDIM 1024
#define NM (NB*NS)
#define OUT_ELEMS (NB*NS*NDIM)   // 4194304 per tensor (out, k, v)

// Scratch (allocation-free rule: __device__ globals)
__device__ __align__(256) float  g_q[NB*NH*NS*HD];   // q proj (pre-RoPE), fp32
__device__ __align__(256) __half g_ah[NM*NDIM];      // half A operand / ctx buffer
__device__ __align__(256) __half g_wh[NDIM*NDIM];    // half W operand buffer
__device__ __align__(256) __half g_qh[NB*NH*NS*HD];  // half Q (post-RoPE) [b,h,s,d]
__device__ __align__(256) __half g_kh[NB*NH*NS*HD];  // half K (post-RoPE) [b,h,s,d]
__device__ __align__(256) __half g_vTh[NB*NH*HD*NS]; // half V transposed [b,h,d,s]
__device__ __align__(256) unsigned g_mb[NB*NS*64];   // mask bitwords (32 cols/word)
__device__ float g_cos[NS*32];
__device__ float g_sin[NS*32];

__device__ __forceinline__ unsigned packh2(float x, float y) {
    __half2 h = __floats2half2_rn(x, y);
    return *(unsigned*)&h;
}
__device__ __forceinline__ void mma_f16(float c[4], unsigned a0, unsigned a1,
                                        unsigned a2, unsigned a3,
                                        unsigned b0, unsigned b1) {
    asm volatile(
        "mma.sync.aligned.m16n8k16.row.col.f32.f16.f16.f32 "
        "{%0,%1,%2,%3}, {%4,%5,%6,%7}, {%8,%9}, {%0,%1,%2,%3};"
        : "+f"(c[0]), "+f"(c[1]), "+f"(c[2]), "+f"(c[3])
        : "r"(a0), "r"(a1), "r"(a2), "r"(a3), "r"(b0), "r"(b1));
}
__device__ __forceinline__ void ldsm4(unsigned &r0, unsigned &r1, unsigned &r2,
                                      unsigned &r3, const void* p) {
    unsigned a = (unsigned)__cvta_generic_to_shared(p);
    asm volatile("ldmatrix.sync.aligned.m8n8.x4.shared.b16 {%0,%1,%2,%3}, [%4];"
                 : "=r"(r0), "=r"(r1), "=r"(r2), "=r"(r3) : "r"(a));
}
#define CP16(dst_u32, src_ptr) \
    asm volatile("cp.async.ca.shared.global [%0], [%1], 16;" \
                 :: "r"(dst_u32), "l"(src_ptr))
#define CP_COMMIT() asm volatile("cp.async.commit_group;" ::: "memory")
#define CP_WAIT1()  asm volatile("cp.async.wait_group 1;" ::: "memory")

// ---------------------------------------------------------------------------
// RoPE tables
// ---------------------------------------------------------------------------
__global__ void rope_table_kernel() {
    int idx = blockIdx.x * blockDim.x + threadIdx.x;
    if (idx >= NS * 32) return;
    int s = idx >> 5, j = idx & 31;
    float invf = (float)exp(-(double)j * (log(10000.0) / 32.0));
    float ang = (float)s * invf;
    g_cos[idx] = (float)cos((double)ang);
    g_sin[idx] = (float)sin((double)ang);
}

// RoPE + half conversion.  y=0: g_q -> g_qh (half only).
//                          y=1: kfp (outK) -> outK fp32 + g_kh half.
__global__ void rope_h_kernel(float* __restrict__ kfp) {
    int idx = blockIdx.x * blockDim.x + threadIdx.x;
    int j = idx & 31;
    int row = idx >> 5;
    int s = row & (NS - 1);
    int base = row * 64 + j;
    float c = g_cos[(s << 5) + j], sn = g_sin[(s << 5) + j];
    if (blockIdx.y == 0) {
        float x1 = g_q[base], x2 = g_q[base + 32];
        g_qh[base]      = __float2half_rn(x1 * c - x2 * sn);
        g_qh[base + 32] = __float2half_rn(x2 * c + x1 * sn);
    } else {
        float x1 = kfp[base], x2 = kfp[base + 32];
        float o1 = x1 * c - x2 * sn, o2 = x2 * c + x1 * sn;
        kfp[base] = o1; kfp[base + 32] = o2;
        g_kh[base]      = __float2half_rn(o1);
        g_kh[base + 32] = __float2half_rn(o2);
    }
}

// mask [B,S,S] int32 -> bitwords (32 cols per word)
__global__ void mask_bits_kernel(const int* __restrict__ mask) {
    int gw = (blockIdx.x * blockDim.x + threadIdx.x) >> 5;
    int lane = threadIdx.x & 31;
    if (gw >= NB * NS) return;
    const int* mrow = mask + (size_t)gw * NS;
    unsigned* dst = g_mb + (size_t)gw * 64;
    for (int wd = 0; wd < 64; wd++) {
        unsigned bits = __ballot_sync(0xffffffffu, mrow[wd * 32 + lane] != 0);
        if (lane == 0) dst[wd] = bits;
    }
}

// ---------------------------------------------------------------------------
// fp32 -> fp16 convert (vectorized)
// ---------------------------------------------------------------------------
__global__ void f2h_kernel(const float* __restrict__ in, __half* __restrict__ out,
                           int n4) {
    int i = blockIdx.x * blockDim.x + threadIdx.x;
    if (i >= n4) return;
    float4 v = ((const float4*)in)[i];
    uint2 u; u.x = packh2(v.x, v.y); u.y = packh2(v.z, v.w);
    ((uint2*)out)[i] = u;
}

// V [b,h,s,d] fp32 -> [b,h,d,s] fp16, smem-tiled.
__global__ void vT_kernel(const float* __restrict__ in) {
    __shared__ __half t[64][136];
    int tid = threadIdx.x;
    int bh = blockIdx.y;
    int s0 = blockIdx.x << 7;
    const float* src = in + ((size_t)bh * NS + s0) * HD;
    #pragma unroll
    for (int it = 0; it < 8; it++) {
        int c = tid + (it << 8);
        int s = c >> 4, d4 = (c & 15) << 2;
        float4 v = *(const float4*)(src + s * HD + d4);
        t[d4 + 0][s] = __float2half_rn(v.x);
        t[d4 + 1][s] = __float2half_rn(v.y);
        t[d4 + 2][s] = __float2half_rn(v.z);
        t[d4 + 3][s] = __float2half_rn(v.w);
    }
    __syncthreads();
    __half* dst = g_vTh + (size_t)bh * HD * NS + s0;
    #pragma unroll
    for (int it = 0; it < 4; it++) {
        int c = tid + (it << 8);
        int d = c >> 4, s8 = (c & 15) << 3;
        *(uint4*)(dst + d * NS + s8) = *(const uint4*)&t[d][s8];
    }
}

// ---------------------------------------------------------------------------
// FP16 linear, cp.async 3-stage pipeline (unchanged from R10).
// ---------------------------------------------------------------------------
#define LP 40
#define LIN_SMEM (3*(128+256)*LP*2)   // 92160 bytes

__global__ __launch_bounds__(256)
void linear_tc_kernel(const __half* __restrict__ Ah, const __half* __restrict__ Wh,
                      const float* __restrict__ bias, float* __restrict__ dst,
                      int headLayout)
{
    extern __shared__ __align__(16) __half lsm[];
    __half* AsB = lsm;
    __half* BsB = lsm + 3 * 128 * LP;
    unsigned As_u = (unsigned)__cvta_generic_to_shared(AsB);
    unsigned Bs_u = (unsigned)__cvta_generic_to_shared(BsB);

    int tid  = threadIdx.x;
    int w    = tid >> 5;
    int lane = tid & 31;
    int grp  = lane >> 2;
    int qid  = lane & 3;
    int wm   = (w & 1) * 64;
    int wn   = (w >> 1) * 64;

    int lane15   = lane & 15;
    int acolsel  = (lane >> 4) << 3;
    int b_rowoff = (lane & 7) + ((lane >> 4) << 3);
    int bcolsel  = ((lane >> 3) & 1) << 3;

    int m0 = blockIdx.y << 7, n0 = blockIdx.x << 8;

    int arow = tid >> 2, aseg = tid & 3;
    const __half* abase = Ah + (size_t)(m0 + arow) * NDIM + aseg * 8;
    const __half* bbase = Wh + (size_t)(n0 + arow) * NDIM + aseg * 8;

    float acc[4][8][4];
    #pragma unroll
    for (int mt = 0; mt < 4; mt++)
        #pragma unroll
        for (int nt = 0; nt < 8; nt++)
            #pragma unroll
            for (int r = 0; r < 4; r++) acc[mt][nt][r] = 0.f;

    auto issue = [&](int kt, int st) {
        unsigned adst = As_u + (st * 128 * LP) * 2;
        unsigned bdst = Bs_u + (st * 256 * LP) * 2;
        int koff = kt * 32;
        #pragma unroll
        for (int i = 0; i < 2; i++) {
            int row = arow + i * 64;
            CP16(adst + (row * LP + aseg * 8) * 2, abase + (size_t)i * 64 * NDIM + koff);
        }
        #pragma unroll
        for (int i = 0; i < 4; i++) {
            int row = arow + i * 64;
            CP16(bdst + (row * LP + aseg * 8) * 2, bbase + (size_t)i * 64 * NDIM + koff);
        }
    };

    issue(0, 0); CP_COMMIT();
    issue(1, 1); CP_COMMIT();

    const int NKT = NDIM / 32;
    int st = 0;
    for (int kt = 0; kt < NKT; kt++) {
        CP_WAIT1();
        __syncthreads();
        if (kt + 2 < NKT) {
            int nst = st + 2; if (nst >= 3) nst -= 3;
            issue(kt + 2, nst);
        }
        CP_COMMIT();

        const __half* Asst = AsB + st * 128 * LP;
        const __half* Bsst = BsB + st * 256 * LP;
        #pragma unroll
        for (int sl = 0; sl < 2; sl++) {
            int kof = sl * 16;
            unsigned afr[4][4], bfr[8][2];
            #pragma unroll
            for (int mt = 0; mt < 4; mt++)
                ldsm4(afr[mt][0], afr[mt][1], afr[mt][2], afr[mt][3],
                      Asst + (wm + mt * 16 + lane15) * LP + kof + acolsel);
            #pragma unroll
            for (int ntp = 0; ntp < 4; ntp++) {
                unsigned r0, r1, r2, r3;
                ldsm4(r0, r1, r2, r3,
                      Bsst + (wn + ntp * 16 + b_rowoff) * LP + kof + bcolsel);
                bfr[ntp*2][0]   = r0; bfr[ntp*2][1]   = r1;
                bfr[ntp*2+1][0] = r2; bfr[ntp*2+1][1] = r3;
            }
            #pragma unroll
            for (int mt = 0; mt < 4; mt++)
                #pragma unroll
                for (int nt = 0; nt < 8; nt++)
                    mma_f16(acc[mt][nt], afr[mt][0], afr[mt][1], afr[mt][2], afr[mt][3],
                            bfr[nt][0], bfr[nt][1]);
        }
        st++; if (st >= 3) st = 0;
    }

    #pragma unroll
    for (int mt = 0; mt < 4; mt++) {
        #pragma unroll
        for (int nt = 0; nt < 8; nt++) {
            int n = n0 + wn + nt * 8 + (qid << 1);
            float bx = bias[n], by = bias[n + 1];
            #pragma unroll
            for (int half = 0; half < 2; half++) {
                int m = m0 + wm + mt * 16 + grp + half * 8;
                float2 v;
                v.x = acc[mt][nt][half * 2 + 0] + bx;
                v.y = acc[mt][nt][half * 2 + 1] + by;
                if (headLayout) {
                    int b = m >> 11, s = m & (NS - 1);
                    int h = n >> 6, d = n & 63;
                    *(float2*)&dst[(((size_t)((b << 4) + h) * NS + s)) * HD + d] = v;
                } else {
                    *(float2*)&dst[(size_t)m * NDIM + n] = v;
                }
            }
        }
    }
}

// ---------------------------------------------------------------------------
// FP16 MMA flash attention, cp.async 3-stage K/V pipeline, bitmask,
// dedicated P buffer (warp-local: only __syncwarp around P).
// Smem (halves): Qs[128][72] | Ps[128][72] | K 3x[64][72] | V 3x[64][72].
// ---------------------------------------------------------------------------
#define APH 72
#define ATTN_SMEM ((128*APH + 128*APH + 3*64*APH + 3*64*APH) * 2)  // 92160 B

__global__ __launch_bounds__(256, 2)
void attn_tc_kernel()
{
    extern __shared__ __align__(16) __half asm_h[];
    __half* Qs  = asm_h;                       // [128][72]
    __half* Ps  = asm_h + 128 * APH;           // [128][72]
    __half* Kst = asm_h + 2 * 128 * APH;       // 3 x [64][72]
    __half* Vst = Kst + 3 * 64 * APH;          // 3 x [64][72]
    unsigned K_u = (unsigned)__cvta_generic_to_shared(Kst);
    unsigned V_u = (unsigned)__cvta_generic_to_shared(Vst);

    int tid = threadIdx.x;
    int w = tid >> 5, lane = tid & 31;
    int grp = lane >> 2, qid = lane & 3;
    int wm = w << 4;
    int bh = blockIdx.y;
    int b = bh >> 4, h = bh & 15;
    int q0 = blockIdx.x << 7;

    int lane15   = lane & 15;
    int acolsel  = (lane >> 4) << 3;
    int b_rowoff = (lane & 7) + ((lane >> 4) << 3);
    int bcolsel  = ((lane >> 3) & 1) << 3;

    const __half* qptr  = g_qh + ((size_t)bh * NS + q0) * HD;
    const __half* kptr  = g_kh + (size_t)bh * NS * HD;
    const __half* vTptr = g_vTh + (size_t)bh * HD * NS;
    const unsigned* mb0 = g_mb + (size_t)(b * NS + q0 + wm + grp) * 64;
    const unsigned* mb1 = mb0 + 8 * 64;

    // Q tile: 1024 16B chunks, 4/thread (plain loads; first barrier publishes)
    #pragma unroll
    for (int i = 0; i < 4; i++) {
        int c = tid + (i << 8);
        int row = c >> 3, seg = c & 7;
        *(uint4*)&Qs[row * APH + seg * 8] = *(const uint4*)(qptr + row * HD + seg * 8);
    }

    // K/V stage issue: 512 chunks each per tile, 2/thread each
    int crow = tid >> 3, cseg = tid & 7;
    auto issueKV = [&](int t, int st) {
        int k0 = t << 6;
        #pragma unroll
        for (int i = 0; i < 2; i++) {
            int row = crow + i * 32;
            CP16(K_u + ((st * 64 + row) * APH + cseg * 8) * 2,
                 kptr + (size_t)(k0 + row) * HD + cseg * 8);
            CP16(V_u + ((st * 64 + row) * APH + cseg * 8) * 2,
                 vTptr + (size_t)row * NS + k0 + cseg * 8);
        }
    };

    issueKV(0, 0); CP_COMMIT();
    issueKV(1, 1); CP_COMMIT();

    float o[8][4];
    #pragma unroll
    for (int nt = 0; nt < 8; nt++)
        #pragma unroll
        for (int r = 0; r < 4; r++) o[nt][r] = 0.f;
    float m0 = -3.0e38f, m1 = -3.0e38f, l0 = 0.f, l1 = 0.f;

    const int NT = NS / 64;   // 32
    int st = 0;
    for (int t = 0; t < NT; t++) {
        CP_WAIT1();
        __syncthreads();
        if (t + 2 < NT) {
            int nst = st + 2; if (nst >= 3) nst -= 3;
            issueKV(t + 2, nst);
        }
        CP_COMMIT();

        const __half* Ks = Kst + st * 64 * APH;
        const __half* Vs = Vst + st * 64 * APH;
        int k0 = t << 6;

        // S = Q K^T
        float sc[8][4];
        #pragma unroll
        for (int nt = 0; nt < 8; nt++)
            #pragma unroll
            for (int r = 0; r < 4; r++) sc[nt][r] = 0.f;

        #pragma unroll
        for (int kk = 0; kk < 4; kk++) {
            unsigned a0, a1, a2, a3;
            ldsm4(a0, a1, a2, a3, &Qs[(wm + lane15) * APH + kk * 16 + acolsel]);
            #pragma unroll
            for (int ntp = 0; ntp < 4; ntp++) {
                unsigned r0, r1, r2, r3;
                ldsm4(r0, r1, r2, r3,
                      Ks + (ntp * 16 + b_rowoff) * APH + kk * 16 + bcolsel);
                mma_f16(sc[ntp*2],   a0, a1, a2, a3, r0, r1);
                mma_f16(sc[ntp*2+1], a0, a1, a2, a3, r2, r3);
            }
        }

        // scale + bitmask
        unsigned long long w0 = *(const unsigned long long*)(mb0 + (k0 >> 5));
        unsigned long long w1 = *(const unsigned long long*)(mb1 + (k0 >> 5));
        #pragma unroll
        for (int nt = 0; nt < 8; nt++) {
            int p = nt * 8 + (qid << 1);
            sc[nt][0] = ((w0 >> p)     & 1) ? sc[nt][0] * 0.125f : -1e30f;
            sc[nt][1] = ((w0 >> (p+1)) & 1) ? sc[nt][1] * 0.125f : -1e30f;
            sc[nt][2] = ((w1 >> p)     & 1) ? sc[nt][2] * 0.125f : -1e30f;
            sc[nt][3] = ((w1 >> (p+1)) & 1) ? sc[nt][3] * 0.125f : -1e30f;
        }

        // online softmax
        float mx0 = -3.0e38f, mx1 = -3.0e38f;
        #pragma unroll
        for (int nt = 0; nt < 8; nt++) {
            mx0 = fmaxf(mx0, fmaxf(sc[nt][0], sc[nt][1]));
            mx1 = fmaxf(mx1, fmaxf(sc[nt][2], sc[nt][3]));
        }
        mx0 = fmaxf(mx0, __shfl_xor_sync(0xffffffffu, mx0, 1));
        mx0 = fmaxf(mx0, __shfl_xor_sync(0xffffffffu, mx0, 2));
        mx1 = fmaxf(mx1, __shfl_xor_sync(0xffffffffu, mx1, 1));
        mx1 = fmaxf(mx1, __shfl_xor_sync(0xffffffffu, mx1, 2));

        float mn0 = fmaxf(m0, mx0), mn1 = fmaxf(m1, mx1);
        float corr0 = __expf(m0 - mn0), corr1 = __expf(m1 - mn1);
        m0 = mn0; m1 = mn1;

        float ps0 = 0.f, ps1 = 0.f;
        #pragma unroll
        for (int nt = 0; nt < 8; nt++) {
            sc[nt][0] = __expf(sc[nt][0] - mn0); ps0 += sc[nt][0];
            sc[nt][1] = __expf(sc[nt][1] - mn0); ps0 += sc[nt][1];
            sc[nt][2] = __expf(sc[nt][2] - mn1); ps1 += sc[nt][2];
            sc[nt][3] = __expf(sc[nt][3] - mn1); ps1 += sc[nt][3];
        }
        ps0 += __shfl_xor_sync(0xffffffffu, ps0, 1);
        ps0 += __shfl_xor_sync(0xffffffffu, ps0, 2);
        ps1 += __shfl_xor_sync(0xffffffffu, ps1, 1);
        ps1 += __shfl_xor_sync(0xffffffffu, ps1, 2);
        l0 = l0 * corr0 + ps0;
        l1 = l1 * corr1 + ps1;
        #pragma unroll
        for (int nt = 0; nt < 8; nt++) {
            o[nt][0] *= corr0; o[nt][1] *= corr0;
            o[nt][2] *= corr1; o[nt][3] *= corr1;
        }

        // P store (warp-local rows) — only warp-level sync needed
        __syncwarp();
        #pragma unroll
        for (int nt = 0; nt < 8; nt++) {
            *(unsigned*)&Ps[(wm + grp) * APH + nt * 8 + (qid << 1)] =
                packh2(sc[nt][0], sc[nt][1]);
            *(unsigned*)&Ps[(wm + grp + 8) * APH + nt * 8 + (qid << 1)] =
                packh2(sc[nt][2], sc[nt][3]);
        }
        __syncwarp();

        // O += P V
        #pragma unroll
        for (int kk = 0; kk < 4; kk++) {
            unsigned a0, a1, a2, a3;
            ldsm4(a0, a1, a2, a3, &Ps[(wm + lane15) * APH + kk * 16 + acolsel]);
            #pragma unroll
            for (int ntp = 0; ntp < 4; ntp++) {
                unsigned r0, r1, r2, r3;
                ldsm4(r0, r1, r2, r3,
                      Vs + (ntp * 16 + b_rowoff) * APH + kk * 16 + bcolsel);
                mma_f16(o[ntp*2],   a0, a1, a2, a3, r0, r1);
                mma_f16(o[ntp*2+1], a0, a1, a2, a3, r2, r3);
            }
        }
        st++; if (st >= 3) st = 0;
    }

    // epilogue: write context as HALF directly into g_ah (A of out-proj)
    float inv0 = 1.0f / l0, inv1 = 1.0f / l1;
    int r0 = q0 + wm + grp, r1 = r0 + 8;
    #pragma unroll
    for (int nt = 0; nt < 8; nt++) {
        int col = h * HD + nt * 8 + (qid << 1);
        *(unsigned*)&g_ah[((size_t)b * NS + r0) * NDIM + col] =
            packh2(o[nt][0] * inv0, o[nt][1] * inv0);
        *(unsigned*)&g_ah[((size_t)b * NS + r1) * NDIM + col] =
            packh2(o[nt][2] * inv1, o[nt][3] * inv1);
    }
}

// ---------------------------------------------------------------------------
extern "C" void kernel_launch(void* const* d_in, const int* in_sizes, int n_in,
                              void* d_out, int out_size) {
    const float* query = (const float*)d_in[0];
    const float* key   = (const float*)d_in[1];
    const float* value = (const float*)d_in[2];
    const int*   mask  = (const int*)d_in[3];
    const float* Wq = (const float*)d_in[4];
    const float* bq = (const float*)d_in[5];
    const float* Wk = (const float*)d_in[6];
    const float* bk = (const float*)d_in[7];
    const float* Wv = (const float*)d_in[8];
    const float* bv = (const float*)d_in[9];
    const float* Wo = (const float*)d_in[10];
    const float* bo = (const float*)d_in[11];

    float* out  = (float*)d_out;                 // [B,S,1024]
    float* outK = out + OUT_ELEMS;               // [B,H,S,64] (post-RoPE k)
    float* outV = out + 2 * (size_t)OUT_ELEMS;   // [B,H,S,64] (v)

    float*  g_q_p;   cudaGetSymbolAddress((void**)&g_q_p, g_q);
    __half* g_ah_p;  cudaGetSymbolAddress((void**)&g_ah_p, g_ah);
    __half* g_wh_p;  cudaGetSymbolAddress((void**)&g_wh_p, g_wh);

    static int smem_set = 0;
    if (!smem_set) {
        cudaFuncSetAttribute(linear_tc_kernel, cudaFuncAttributeMaxDynamicSharedMemorySize,
                             LIN_SMEM);
        cudaFuncSetAttribute(attn_tc_kernel, cudaFuncAttributeMaxDynamicSharedMemorySize,
                             ATTN_SMEM);
        smem_set = 1;
    }

    const int A4 = NM * NDIM / 4;
    const int W4 = NDIM * NDIM / 4;

    rope_table_kernel<<<(NS * 32 + 255) / 256, 256>>>();
    mask_bits_kernel<<<(NB * NS * 32 + 255) / 256, 256>>>(mask);

    dim3 lgrid(NDIM / 256, NM / 128);   // (4, 32)

    f2h_kernel<<<A4 / 256, 256>>>(query, g_ah_p, A4);
    f2h_kernel<<<W4 / 256, 256>>>(Wq, g_wh_p, W4);
    linear_tc_kernel<<<lgrid, 256, LIN_SMEM>>>(g_ah_p, g_wh_p, bq, g_q_p, 1);

    f2h_kernel<<<A4 / 256, 256>>>(key, g_ah_p, A4);
    f2h_kernel<<<W4 / 256, 256>>>(Wk, g_wh_p, W4);
    linear_tc_kernel<<<lgrid, 256, LIN_SMEM>>>(g_ah_p, g_wh_p, bk, outK, 1);

    f2h_kernel<<<A4 / 256, 256>>>(value, g_ah_p, A4);
    f2h_kernel<<<W4 / 256, 256>>>(Wv, g_wh_p, W4);
    linear_tc_kernel<<<lgrid, 256, LIN_SMEM>>>(g_ah_p, g_wh_p, bv, outV, 1);

    dim3 rgrid((NB * NH * NS * 32) / 256, 2);
    rope_h_kernel<<<rgrid, 256>>>(outK);

    dim3 vgrid(NS / 128, NB * NH);
    vT_kernel<<<vgrid, 256>>>(outV);

    dim3 agrid(NS / 128, NB * NH);      // (16, 32)
    attn_tc_kernel<<<agrid, 256, ATTN_SMEM>>>();

    f2h_kernel<<<W4 / 256, 256>>>(Wo, g_wh_p, W4);
    linear_tc_kernel<<<lgrid, 256, LIN_SMEM>>>(g_ah_p, g_wh_p, bo, out, 0);
}

// round 12
// speedup vs baseline: 5.8092x; 1.0609x over previous
#include <cuda_runtime.h>
#include <cuda_fp16.h>
#include <math.h>

#define NB 2
#define NS 2048
#define NH 16
#define HD 64
#define NDIM 1024
#define NM (NB*NS)
#define OUT_ELEMS (NB*NS*NDIM)   // 4194304 per tensor (out, k, v)

// Scratch (allocation-free rule: __device__ globals)
__device__ __align__(256) float  g_q[NB*NH*NS*HD];    // q proj (pre-RoPE), fp32
__device__ __align__(256) __half g_ah[NM*NDIM];       // ctx half (A of out-proj)
__device__ __align__(256) __half g_inh[3*NM*NDIM];    // half query/key/value inputs
__device__ __align__(256) __half g_wh[4*NDIM*NDIM];   // half Wq/Wk/Wv/Wo
__device__ __align__(256) __half g_qh[NB*NH*NS*HD];   // half Q (post-RoPE)
__device__ __align__(256) __half g_kh[NB*NH*NS*HD];   // half K (post-RoPE)
__device__ __align__(256) __half g_vTh[NB*NH*HD*NS];  // half V transposed [b,h,d,s]
__device__ __align__(256) unsigned g_mb[NB*NS*64];    // mask bitwords
__device__ float g_cos[NS*32];
__device__ float g_sin[NS*32];

#define SCALE2 0.18033688011112042f   // 0.125 * log2(e)

__device__ __forceinline__ unsigned packh2(float x, float y) {
    __half2 h = __floats2half2_rn(x, y);
    return *(unsigned*)&h;
}
__device__ __forceinline__ float fex2(float x) {
    float r; asm("ex2.approx.ftz.f32 %0, %1;" : "=f"(r) : "f"(x)); return r;
}
__device__ __forceinline__ void mma_f16(float c[4], unsigned a0, unsigned a1,
                                        unsigned a2, unsigned a3,
                                        unsigned b0, unsigned b1) {
    asm volatile(
        "mma.sync.aligned.m16n8k16.row.col.f32.f16.f16.f32 "
        "{%0,%1,%2,%3}, {%4,%5,%6,%7}, {%8,%9}, {%0,%1,%2,%3};"
        : "+f"(c[0]), "+f"(c[1]), "+f"(c[2]), "+f"(c[3])
        : "r"(a0), "r"(a1), "r"(a2), "r"(a3), "r"(b0), "r"(b1));
}
__device__ __forceinline__ void ldsm4(unsigned &r0, unsigned &r1, unsigned &r2,
                                      unsigned &r3, const void* p) {
    unsigned a = (unsigned)__cvta_generic_to_shared(p);
    asm volatile("ldmatrix.sync.aligned.m8n8.x4.shared.b16 {%0,%1,%2,%3}, [%4];"
                 : "=r"(r0), "=r"(r1), "=r"(r2), "=r"(r3) : "r"(a));
}
#define CP16(dst_u32, src_ptr) \
    asm volatile("cp.async.ca.shared.global [%0], [%1], 16;" \
                 :: "r"(dst_u32), "l"(src_ptr))
#define CP_COMMIT() asm volatile("cp.async.commit_group;" ::: "memory")
#define CP_WAIT1()  asm volatile("cp.async.wait_group 1;" ::: "memory")

// ---------------------------------------------------------------------------
// RoPE tables
// ---------------------------------------------------------------------------
__global__ void rope_table_kernel() {
    int idx = blockIdx.x * blockDim.x + threadIdx.x;
    if (idx >= NS * 32) return;
    int s = idx >> 5, j = idx & 31;
    float invf = (float)exp(-(double)j * (log(10000.0) / 32.0));
    float ang = (float)s * invf;
    g_cos[idx] = (float)cos((double)ang);
    g_sin[idx] = (float)sin((double)ang);
}

// RoPE + half conversion.  y=0: g_q -> g_qh.  y=1: kfp -> kfp fp32 + g_kh half.
__global__ void rope_h_kernel(float* __restrict__ kfp) {
    int idx = blockIdx.x * blockDim.x + threadIdx.x;
    int j = idx & 31;
    int row = idx >> 5;
    int s = row & (NS - 1);
    int base = row * 64 + j;
    float c = g_cos[(s << 5) + j], sn = g_sin[(s << 5) + j];
    if (blockIdx.y == 0) {
        float x1 = g_q[base], x2 = g_q[base + 32];
        g_qh[base]      = __float2half_rn(x1 * c - x2 * sn);
        g_qh[base + 32] = __float2half_rn(x2 * c + x1 * sn);
    } else {
        float x1 = kfp[base], x2 = kfp[base + 32];
        float o1 = x1 * c - x2 * sn, o2 = x2 * c + x1 * sn;
        kfp[base] = o1; kfp[base + 32] = o2;
        g_kh[base]      = __float2half_rn(o1);
        g_kh[base + 32] = __float2half_rn(o2);
    }
}

// mask [B,S,S] int32 -> bitwords
__global__ void mask_bits_kernel(const int* __restrict__ mask) {
    int gw = (blockIdx.x * blockDim.x + threadIdx.x) >> 5;
    int lane = threadIdx.x & 31;
    if (gw >= NB * NS) return;
    const int* mrow = mask + (size_t)gw * NS;
    unsigned* dst = g_mb + (size_t)gw * 64;
    for (int wd = 0; wd < 64; wd++) {
        unsigned bits = __ballot_sync(0xffffffffu, mrow[wd * 32 + lane] != 0);
        if (lane == 0) dst[wd] = bits;
    }
}

// batched fp32->fp16: blockIdx.y selects one of up to 4 tensors
__global__ void f2h_multi_kernel(const float* s0, const float* s1,
                                 const float* s2, const float* s3,
                                 __half* __restrict__ out, int n4) {
    int i = blockIdx.x * blockDim.x + threadIdx.x;
    if (i >= n4) return;
    const float* srcs[4] = {s0, s1, s2, s3};
    const float* in = srcs[blockIdx.y];
    float4 v = ((const float4*)in)[i];
    uint2 u; u.x = packh2(v.x, v.y); u.y = packh2(v.z, v.w);
    ((uint2*)(out + (size_t)blockIdx.y * n4 * 4))[i] = u;
}

// V [b,h,s,d] fp32 -> [b,h,d,s] fp16, smem-tiled.
__global__ void vT_kernel(const float* __restrict__ in) {
    __shared__ __half t[64][136];
    int tid = threadIdx.x;
    int bh = blockIdx.y;
    int s0 = blockIdx.x << 7;
    const float* src = in + ((size_t)bh * NS + s0) * HD;
    #pragma unroll
    for (int it = 0; it < 8; it++) {
        int c = tid + (it << 8);
        int s = c >> 4, d4 = (c & 15) << 2;
        float4 v = *(const float4*)(src + s * HD + d4);
        t[d4 + 0][s] = __float2half_rn(v.x);
        t[d4 + 1][s] = __float2half_rn(v.y);
        t[d4 + 2][s] = __float2half_rn(v.z);
        t[d4 + 3][s] = __float2half_rn(v.w);
    }
    __syncthreads();
    __half* dst = g_vTh + (size_t)bh * HD * NS + s0;
    #pragma unroll
    for (int it = 0; it < 4; it++) {
        int c = tid + (it << 8);
        int d = c >> 4, s8 = (c & 15) << 3;
        *(uint4*)(dst + d * NS + s8) = *(const uint4*)&t[d][s8];
    }
}

// ---------------------------------------------------------------------------
// FP16 linear, cp.async 3-stage pipeline (unchanged from R10/R11).
// ---------------------------------------------------------------------------
#define LP 40
#define LIN_SMEM (3*(128+256)*LP*2)   // 92160 bytes

__global__ __launch_bounds__(256)
void linear_tc_kernel(const __half* __restrict__ Ah, const __half* __restrict__ Wh,
                      const float* __restrict__ bias, float* __restrict__ dst,
                      int headLayout)
{
    extern __shared__ __align__(16) __half lsm[];
    __half* AsB = lsm;
    __half* BsB = lsm + 3 * 128 * LP;
    unsigned As_u = (unsigned)__cvta_generic_to_shared(AsB);
    unsigned Bs_u = (unsigned)__cvta_generic_to_shared(BsB);

    int tid  = threadIdx.x;
    int w    = tid >> 5;
    int lane = tid & 31;
    int grp  = lane >> 2;
    int qid  = lane & 3;
    int wm   = (w & 1) * 64;
    int wn   = (w >> 1) * 64;

    int lane15   = lane & 15;
    int acolsel  = (lane >> 4) << 3;
    int b_rowoff = (lane & 7) + ((lane >> 4) << 3);
    int bcolsel  = ((lane >> 3) & 1) << 3;

    int m0 = blockIdx.y << 7, n0 = blockIdx.x << 8;

    int arow = tid >> 2, aseg = tid & 3;
    const __half* abase = Ah + (size_t)(m0 + arow) * NDIM + aseg * 8;
    const __half* bbase = Wh + (size_t)(n0 + arow) * NDIM + aseg * 8;

    float acc[4][8][4];
    #pragma unroll
    for (int mt = 0; mt < 4; mt++)
        #pragma unroll
        for (int nt = 0; nt < 8; nt++)
            #pragma unroll
            for (int r = 0; r < 4; r++) acc[mt][nt][r] = 0.f;

    auto issue = [&](int kt, int st) {
        unsigned adst = As_u + (st * 128 * LP) * 2;
        unsigned bdst = Bs_u + (st * 256 * LP) * 2;
        int koff = kt * 32;
        #pragma unroll
        for (int i = 0; i < 2; i++) {
            int row = arow + i * 64;
            CP16(adst + (row * LP + aseg * 8) * 2, abase + (size_t)i * 64 * NDIM + koff);
        }
        #pragma unroll
        for (int i = 0; i < 4; i++) {
            int row = arow + i * 64;
            CP16(bdst + (row * LP + aseg * 8) * 2, bbase + (size_t)i * 64 * NDIM + koff);
        }
    };

    issue(0, 0); CP_COMMIT();
    issue(1, 1); CP_COMMIT();

    const int NKT = NDIM / 32;
    int st = 0;
    for (int kt = 0; kt < NKT; kt++) {
        CP_WAIT1();
        __syncthreads();
        if (kt + 2 < NKT) {
            int nst = st + 2; if (nst >= 3) nst -= 3;
            issue(kt + 2, nst);
        }
        CP_COMMIT();

        const __half* Asst = AsB + st * 128 * LP;
        const __half* Bsst = BsB + st * 256 * LP;
        #pragma unroll
        for (int sl = 0; sl < 2; sl++) {
            int kof = sl * 16;
            unsigned afr[4][4], bfr[8][2];
            #pragma unroll
            for (int mt = 0; mt < 4; mt++)
                ldsm4(afr[mt][0], afr[mt][1], afr[mt][2], afr[mt][3],
                      Asst + (wm + mt * 16 + lane15) * LP + kof + acolsel);
            #pragma unroll
            for (int ntp = 0; ntp < 4; ntp++) {
                unsigned r0, r1, r2, r3;
                ldsm4(r0, r1, r2, r3,
                      Bsst + (wn + ntp * 16 + b_rowoff) * LP + kof + bcolsel);
                bfr[ntp*2][0]   = r0; bfr[ntp*2][1]   = r1;
                bfr[ntp*2+1][0] = r2; bfr[ntp*2+1][1] = r3;
            }
            #pragma unroll
            for (int mt = 0; mt < 4; mt++)
                #pragma unroll
                for (int nt = 0; nt < 8; nt++)
                    mma_f16(acc[mt][nt], afr[mt][0], afr[mt][1], afr[mt][2], afr[mt][3],
                            bfr[nt][0], bfr[nt][1]);
        }
        st++; if (st >= 3) st = 0;
    }

    #pragma unroll
    for (int mt = 0; mt < 4; mt++) {
        #pragma unroll
        for (int nt = 0; nt < 8; nt++) {
            int n = n0 + wn + nt * 8 + (qid << 1);
            float bx = bias[n], by = bias[n + 1];
            #pragma unroll
            for (int half = 0; half < 2; half++) {
                int m = m0 + wm + mt * 16 + grp + half * 8;
                float2 v;
                v.x = acc[mt][nt][half * 2 + 0] + bx;
                v.y = acc[mt][nt][half * 2 + 1] + by;
                if (headLayout) {
                    int b = m >> 11, s = m & (NS - 1);
                    int h = n >> 6, d = n & 63;
                    *(float2*)&dst[(((size_t)((b << 4) + h) * NS + s)) * HD + d] = v;
                } else {
                    *(float2*)&dst[(size_t)m * NDIM + n] = v;
                }
            }
        }
    }
}

// ---------------------------------------------------------------------------
// FP16 MMA flash attention, cp.async pipeline + P kept in registers (FA2).
// Smem (halves): Qs[128][72] | K 3x[64][72] | V 3x[64][72] = 73728 B.
// ---------------------------------------------------------------------------
#define APH 72
#define ATTN_SMEM ((128*APH + 3*64*APH + 3*64*APH) * 2)

__global__ __launch_bounds__(256, 2)
void attn_tc_kernel()
{
    extern __shared__ __align__(16) __half asm_h[];
    __half* Qs  = asm_h;                       // [128][72]
    __half* Kst = asm_h + 128 * APH;           // 3 x [64][72]
    __half* Vst = Kst + 3 * 64 * APH;          // 3 x [64][72]
    unsigned K_u = (unsigned)__cvta_generic_to_shared(Kst);
    unsigned V_u = (unsigned)__cvta_generic_to_shared(Vst);

    int tid = threadIdx.x;
    int w = tid >> 5, lane = tid & 31;
    int grp = lane >> 2, qid = lane & 3;
    int wm = w << 4;
    int bh = blockIdx.y;
    int b = bh >> 4, h = bh & 15;
    int q0 = blockIdx.x << 7;

    int lane15   = lane & 15;
    int acolsel  = (lane >> 4) << 3;
    int b_rowoff = (lane & 7) + ((lane >> 4) << 3);
    int bcolsel  = ((lane >> 3) & 1) << 3;

    const __half* qptr  = g_qh + ((size_t)bh * NS + q0) * HD;
    const __half* kptr  = g_kh + (size_t)bh * NS * HD;
    const __half* vTptr = g_vTh + (size_t)bh * HD * NS;
    const unsigned* mb0 = g_mb + (size_t)(b * NS + q0 + wm + grp) * 64;
    const unsigned* mb1 = mb0 + 8 * 64;

    #pragma unroll
    for (int i = 0; i < 4; i++) {
        int c = tid + (i << 8);
        int row = c >> 3, seg = c & 7;
        *(uint4*)&Qs[row * APH + seg * 8] = *(const uint4*)(qptr + row * HD + seg * 8);
    }

    int crow = tid >> 3, cseg = tid & 7;
    auto issueKV = [&](int t, int st) {
        int k0 = t << 6;
        #pragma unroll
        for (int i = 0; i < 2; i++) {
            int row = crow + i * 32;
            CP16(K_u + ((st * 64 + row) * APH + cseg * 8) * 2,
                 kptr + (size_t)(k0 + row) * HD + cseg * 8);
            CP16(V_u + ((st * 64 + row) * APH + cseg * 8) * 2,
                 vTptr + (size_t)row * NS + k0 + cseg * 8);
        }
    };

    issueKV(0, 0); CP_COMMIT();
    issueKV(1, 1); CP_COMMIT();

    float o[8][4];
    #pragma unroll
    for (int nt = 0; nt < 8; nt++)
        #pragma unroll
        for (int r = 0; r < 4; r++) o[nt][r] = 0.f;
    float m0 = -3.0e38f, m1 = -3.0e38f, l0 = 0.f, l1 = 0.f;

    const int NT = NS / 64;   // 32
    int st = 0;
    for (int t = 0; t < NT; t++) {
        CP_WAIT1();
        __syncthreads();
        if (t + 2 < NT) {
            int nst = st + 2; if (nst >= 3) nst -= 3;
            issueKV(t + 2, nst);
        }
        CP_COMMIT();

        const __half* Ks = Kst + st * 64 * APH;
        const __half* Vs = Vst + st * 64 * APH;
        int k0 = t << 6;

        // S = Q K^T
        float sc[8][4];
        #pragma unroll
        for (int nt = 0; nt < 8; nt++)
            #pragma unroll
            for (int r = 0; r < 4; r++) sc[nt][r] = 0.f;

        #pragma unroll
        for (int kk = 0; kk < 4; kk++) {
            unsigned a0, a1, a2, a3;
            ldsm4(a0, a1, a2, a3, &Qs[(wm + lane15) * APH + kk * 16 + acolsel]);
            #pragma unroll
            for (int ntp = 0; ntp < 4; ntp++) {
                unsigned r0, r1, r2, r3;
                ldsm4(r0, r1, r2, r3,
                      Ks + (ntp * 16 + b_rowoff) * APH + kk * 16 + bcolsel);
                mma_f16(sc[ntp*2],   a0, a1, a2, a3, r0, r1);
                mma_f16(sc[ntp*2+1], a0, a1, a2, a3, r2, r3);
            }
        }

        // scale (exp2 domain) + bitmask
        unsigned long long w0 = *(const unsigned long long*)(mb0 + (k0 >> 5));
        unsigned long long w1 = *(const unsigned long long*)(mb1 + (k0 >> 5));
        #pragma unroll
        for (int nt = 0; nt < 8; nt++) {
            int p = nt * 8 + (qid << 1);
            sc[nt][0] = ((w0 >> p)     & 1) ? sc[nt][0] * SCALE2 : -1e30f;
            sc[nt][1] = ((w0 >> (p+1)) & 1) ? sc[nt][1] * SCALE2 : -1e30f;
            sc[nt][2] = ((w1 >> p)     & 1) ? sc[nt][2] * SCALE2 : -1e30f;
            sc[nt][3] = ((w1 >> (p+1)) & 1) ? sc[nt][3] * SCALE2 : -1e30f;
        }

        // online softmax (log2 domain)
        float mx0 = -3.0e38f, mx1 = -3.0e38f;
        #pragma unroll
        for (int nt = 0; nt < 8; nt++) {
            mx0 = fmaxf(mx0, fmaxf(sc[nt][0], sc[nt][1]));
            mx1 = fmaxf(mx1, fmaxf(sc[nt][2], sc[nt][3]));
        }
        mx0 = fmaxf(mx0, __shfl_xor_sync(0xffffffffu, mx0, 1));
        mx0 = fmaxf(mx0, __shfl_xor_sync(0xffffffffu, mx0, 2));
        mx1 = fmaxf(mx1, __shfl_xor_sync(0xffffffffu, mx1, 1));
        mx1 = fmaxf(mx1, __shfl_xor_sync(0xffffffffu, mx1, 2));

        float mn0 = fmaxf(m0, mx0), mn1 = fmaxf(m1, mx1);
        float corr0 = fex2(m0 - mn0), corr1 = fex2(m1 - mn1);
        m0 = mn0; m1 = mn1;

        float ps0 = 0.f, ps1 = 0.f;
        #pragma unroll
        for (int nt = 0; nt < 8; nt++) {
            sc[nt][0] = fex2(sc[nt][0] - mn0); ps0 += sc[nt][0];
            sc[nt][1] = fex2(sc[nt][1] - mn0); ps0 += sc[nt][1];
            sc[nt][2] = fex2(sc[nt][2] - mn1); ps1 += sc[nt][2];
            sc[nt][3] = fex2(sc[nt][3] - mn1); ps1 += sc[nt][3];
        }
        ps0 += __shfl_xor_sync(0xffffffffu, ps0, 1);
        ps0 += __shfl_xor_sync(0xffffffffu, ps0, 2);
        ps1 += __shfl_xor_sync(0xffffffffu, ps1, 1);
        ps1 += __shfl_xor_sync(0xffffffffu, ps1, 2);
        l0 = l0 * corr0 + ps0;
        l1 = l1 * corr1 + ps1;
        #pragma unroll
        for (int nt = 0; nt < 8; nt++) {
            o[nt][0] *= corr0; o[nt][1] *= corr0;
            o[nt][2] *= corr1; o[nt][3] *= corr1;
        }

        // O += P V  — P fragments built directly from sc registers (FA2)
        #pragma unroll
        for (int kk = 0; kk < 4; kk++) {
            unsigned a0 = packh2(sc[2*kk][0],   sc[2*kk][1]);
            unsigned a1 = packh2(sc[2*kk][2],   sc[2*kk][3]);
            unsigned a2 = packh2(sc[2*kk+1][0], sc[2*kk+1][1]);
            unsigned a3 = packh2(sc[2*kk+1][2], sc[2*kk+1][3]);
            #pragma unroll
            for (int ntp = 0; ntp < 4; ntp++) {
                unsigned r0, r1, r2, r3;
                ldsm4(r0, r1, r2, r3,
                      Vs + (ntp * 16 + b_rowoff) * APH + kk * 16 + bcolsel);
                mma_f16(o[ntp*2],   a0, a1, a2, a3, r0, r1);
                mma_f16(o[ntp*2+1], a0, a1, a2, a3, r2, r3);
            }
        }
        st++; if (st >= 3) st = 0;
    }

    // epilogue: write context as HALF directly into g_ah (A of out-proj)
    float inv0 = 1.0f / l0, inv1 = 1.0f / l1;
    int r0 = q0 + wm + grp, r1 = r0 + 8;
    #pragma unroll
    for (int nt = 0; nt < 8; nt++) {
        int col = h * HD + nt * 8 + (qid << 1);
        *(unsigned*)&g_ah[((size_t)b * NS + r0) * NDIM + col] =
            packh2(o[nt][0] * inv0, o[nt][1] * inv0);
        *(unsigned*)&g_ah[((size_t)b * NS + r1) * NDIM + col] =
            packh2(o[nt][2] * inv1, o[nt][3] * inv1);
    }
}

// ---------------------------------------------------------------------------
extern "C" void kernel_launch(void* const* d_in, const int* in_sizes, int n_in,
                              void* d_out, int out_size) {
    const float* query = (const float*)d_in[0];
    const float* key   = (const float*)d_in[1];
    const float* value = (const float*)d_in[2];
    const int*   mask  = (const int*)d_in[3];
    const float* Wq = (const float*)d_in[4];
    const float* bq = (const float*)d_in[5];
    const float* Wk = (const float*)d_in[6];
    const float* bk = (const float*)d_in[7];
    const float* Wv = (const float*)d_in[8];
    const float* bv = (const float*)d_in[9];
    const float* Wo = (const float*)d_in[10];
    const float* bo = (const float*)d_in[11];

    float* out  = (float*)d_out;                 // [B,S,1024]
    float* outK = out + OUT_ELEMS;               // [B,H,S,64] (post-RoPE k)
    float* outV = out + 2 * (size_t)OUT_ELEMS;   // [B,H,S,64] (v)

    float*  g_q_p;   cudaGetSymbolAddress((void**)&g_q_p, g_q);
    __half* g_ah_p;  cudaGetSymbolAddress((void**)&g_ah_p, g_ah);
    __half* g_inh_p; cudaGetSymbolAddress((void**)&g_inh_p, g_inh);
    __half* g_wh_p;  cudaGetSymbolAddress((void**)&g_wh_p, g_wh);

    static int smem_set = 0;
    if (!smem_set) {
        cudaFuncSetAttribute(linear_tc_kernel, cudaFuncAttributeMaxDynamicSharedMemorySize,
                             LIN_SMEM);
        cudaFuncSetAttribute(attn_tc_kernel, cudaFuncAttributeMaxDynamicSharedMemorySize,
                             ATTN_SMEM);
        smem_set = 1;
    }

    const int A4 = NM * NDIM / 4;
    const int W4 = NDIM * NDIM / 4;
    const size_t WSZ = (size_t)NDIM * NDIM;

    rope_table_kernel<<<(NS * 32 + 255) / 256, 256>>>();
    mask_bits_kernel<<<(NB * NS * 32 + 255) / 256, 256>>>(mask);

    // batched conversions: 4 weights, 3 inputs
    dim3 wgrid4(W4 / 256, 4);
    f2h_multi_kernel<<<wgrid4, 256>>>(Wq, Wk, Wv, Wo, g_wh_p, W4);
    dim3 igrid3(A4 / 256, 3);
    f2h_multi_kernel<<<igrid3, 256>>>(query, key, value, value, g_inh_p, A4);

    dim3 lgrid(NDIM / 256, NM / 128);   // (4, 32)
    linear_tc_kernel<<<lgrid, 256, LIN_SMEM>>>(g_inh_p,                g_wh_p,         bq, g_q_p, 1);
    linear_tc_kernel<<<lgrid, 256, LIN_SMEM>>>(g_inh_p + (size_t)NM*NDIM,   g_wh_p + WSZ,   bk, outK, 1);
    linear_tc_kernel<<<lgrid, 256, LIN_SMEM>>>(g_inh_p + 2*(size_t)NM*NDIM, g_wh_p + 2*WSZ, bv, outV, 1);

    dim3 rgrid((NB * NH * NS * 32) / 256, 2);
    rope_h_kernel<<<rgrid, 256>>>(outK);

    dim3 vgrid(NS / 128, NB * NH);
    vT_kernel<<<vgrid, 256>>>(outV);

    dim3 agrid(NS / 128, NB * NH);      // (16, 32)
    attn_tc_kernel<<<agrid, 256, ATTN_SMEM>>>();

    linear_tc_kernel<<<lgrid, 256, LIN_SMEM>>>(g_ah_p, g_wh_p + 3*WSZ, bo, out, 0);
}

// round 13
// speedup vs baseline: 5.8688x; 1.0103x over previous
#include <cuda_runtime.h>
#include <cuda_fp16.h>
#include <math.h>

#define NB 2
#define NS 2048
#define NH 16
#define HD 64
#define NDIM 1024
#define NM (NB*NS)
#define OUT_ELEMS (NB*NS*NDIM)   // 4194304 per tensor (out, k, v)

// Scratch (allocation-free rule: __device__ globals)
__device__ __align__(256) __half g_ah[NM*NDIM];       // ctx half (A of out-proj)
__device__ __align__(256) __half g_inh[3*NM*NDIM];    // half query/key/value inputs
__device__ __align__(256) __half g_wh[4*NDIM*NDIM];   // half Wq/Wk/Wv/Wo
__device__ __align__(256) __half g_qh[NB*NH*NS*HD];   // half Q (post-RoPE)
__device__ __align__(256) __half g_kh[NB*NH*NS*HD];   // half K (post-RoPE)
__device__ __align__(256) __half g_vTh[NB*NH*HD*NS];  // half V transposed [b,h,d,s]
__device__ __align__(256) unsigned g_mb[NB*NS*64];    // mask bitwords
__device__ float g_cos[NS*32];
__device__ float g_sin[NS*32];

#define SCALE2 0.18033688011112042f   // 0.125 * log2(e)

__device__ __forceinline__ unsigned packh2(float x, float y) {
    __half2 h = __floats2half2_rn(x, y);
    return *(unsigned*)&h;
}
__device__ __forceinline__ float fex2(float x) {
    float r; asm("ex2.approx.ftz.f32 %0, %1;" : "=f"(r) : "f"(x)); return r;
}
__device__ __forceinline__ void mma_f16(float c[4], unsigned a0, unsigned a1,
                                        unsigned a2, unsigned a3,
                                        unsigned b0, unsigned b1) {
    asm volatile(
        "mma.sync.aligned.m16n8k16.row.col.f32.f16.f16.f32 "
        "{%0,%1,%2,%3}, {%4,%5,%6,%7}, {%8,%9}, {%0,%1,%2,%3};"
        : "+f"(c[0]), "+f"(c[1]), "+f"(c[2]), "+f"(c[3])
        : "r"(a0), "r"(a1), "r"(a2), "r"(a3), "r"(b0), "r"(b1));
}
__device__ __forceinline__ void ldsm4(unsigned &r0, unsigned &r1, unsigned &r2,
                                      unsigned &r3, const void* p) {
    unsigned a = (unsigned)__cvta_generic_to_shared(p);
    asm volatile("ldmatrix.sync.aligned.m8n8.x4.shared.b16 {%0,%1,%2,%3}, [%4];"
                 : "=r"(r0), "=r"(r1), "=r"(r2), "=r"(r3) : "r"(a));
}
#define CP16(dst_u32, src_ptr) \
    asm volatile("cp.async.ca.shared.global [%0], [%1], 16;" \
                 :: "r"(dst_u32), "l"(src_ptr))
#define CP_COMMIT() asm volatile("cp.async.commit_group;" ::: "memory")
#define CP_WAIT1()  asm volatile("cp.async.wait_group 1;" ::: "memory")

// ---------------------------------------------------------------------------
// RoPE tables
// ---------------------------------------------------------------------------
__global__ void rope_table_kernel() {
    int idx = blockIdx.x * blockDim.x + threadIdx.x;
    if (idx >= NS * 32) return;
    int s = idx >> 5, j = idx & 31;
    float invf = (float)exp(-(double)j * (log(10000.0) / 32.0));
    float ang = (float)s * invf;
    g_cos[idx] = (float)cos((double)ang);
    g_sin[idx] = (float)sin((double)ang);
}

// mask [B,S,S] int32 -> bitwords
__global__ void mask_bits_kernel(const int* __restrict__ mask) {
    int gw = (blockIdx.x * blockDim.x + threadIdx.x) >> 5;
    int lane = threadIdx.x & 31;
    if (gw >= NB * NS) return;
    const int* mrow = mask + (size_t)gw * NS;
    unsigned* dst = g_mb + (size_t)gw * 64;
    for (int wd = 0; wd < 64; wd++) {
        unsigned bits = __ballot_sync(0xffffffffu, mrow[wd * 32 + lane] != 0);
        if (lane == 0) dst[wd] = bits;
    }
}

// batched fp32->fp16, 2 float4 per thread
__global__ void f2h_multi_kernel(const float* s0, const float* s1,
                                 const float* s2, const float* s3,
                                 __half* __restrict__ out, int n4) {
    int i = (blockIdx.x * blockDim.x + threadIdx.x) * 2;
    if (i >= n4) return;
    const float* srcs[4] = {s0, s1, s2, s3};
    const float* in = srcs[blockIdx.y];
    __half* o = out + (size_t)blockIdx.y * n4 * 4;
    float4 v0 = ((const float4*)in)[i];
    float4 v1 = ((const float4*)in)[i + 1];
    uint4 u;
    u.x = packh2(v0.x, v0.y); u.y = packh2(v0.z, v0.w);
    u.z = packh2(v1.x, v1.y); u.w = packh2(v1.z, v1.w);
    *(uint4*)(o + (size_t)i * 4) = u;
}

// V [b,h,s,d] fp32 -> [b,h,d,s] fp16, smem-tiled.
__global__ void vT_kernel(const float* __restrict__ in) {
    __shared__ __half t[64][136];
    int tid = threadIdx.x;
    int bh = blockIdx.y;
    int s0 = blockIdx.x << 7;
    const float* src = in + ((size_t)bh * NS + s0) * HD;
    #pragma unroll
    for (int it = 0; it < 8; it++) {
        int c = tid + (it << 8);
        int s = c >> 4, d4 = (c & 15) << 2;
        float4 v = *(const float4*)(src + s * HD + d4);
        t[d4 + 0][s] = __float2half_rn(v.x);
        t[d4 + 1][s] = __float2half_rn(v.y);
        t[d4 + 2][s] = __float2half_rn(v.z);
        t[d4 + 3][s] = __float2half_rn(v.w);
    }
    __syncthreads();
    __half* dst = g_vTh + (size_t)bh * HD * NS + s0;
    #pragma unroll
    for (int it = 0; it < 4; it++) {
        int c = tid + (it << 8);
        int d = c >> 4, s8 = (c & 15) << 3;
        *(uint4*)(dst + d * NS + s8) = *(const uint4*)&t[d][s8];
    }
}

// ---------------------------------------------------------------------------
// FP16 linear, cp.async 3-stage pipeline.
// mode 0: flat fp32 [m,1024].   mode 1: head fp32 [b,h,s,d] (V).
// mode 2: Q — RoPE in epilogue, write g_qh half only.
// mode 3: K — RoPE in epilogue, write dst fp32 head + g_kh half.
// ---------------------------------------------------------------------------
#define LP 40
#define LIN_SMEM (3*(128+256)*LP*2)   // 92160 bytes

__global__ __launch_bounds__(256)
void linear_tc_kernel(const __half* __restrict__ Ah, const __half* __restrict__ Wh,
                      const float* __restrict__ bias, float* __restrict__ dst,
                      int mode)
{
    extern __shared__ __align__(16) __half lsm[];
    __half* AsB = lsm;
    __half* BsB = lsm + 3 * 128 * LP;
    unsigned As_u = (unsigned)__cvta_generic_to_shared(AsB);
    unsigned Bs_u = (unsigned)__cvta_generic_to_shared(BsB);

    int tid  = threadIdx.x;
    int w    = tid >> 5;
    int lane = tid & 31;
    int grp  = lane >> 2;
    int qid  = lane & 3;
    int wm   = (w & 1) * 64;
    int wn   = (w >> 1) * 64;

    int lane15   = lane & 15;
    int acolsel  = (lane >> 4) << 3;
    int b_rowoff = (lane & 7) + ((lane >> 4) << 3);
    int bcolsel  = ((lane >> 3) & 1) << 3;

    int m0 = blockIdx.y << 7, n0 = blockIdx.x << 8;

    int arow = tid >> 2, aseg = tid & 3;
    const __half* abase = Ah + (size_t)(m0 + arow) * NDIM + aseg * 8;
    const __half* bbase = Wh + (size_t)(n0 + arow) * NDIM + aseg * 8;

    float acc[4][8][4];
    #pragma unroll
    for (int mt = 0; mt < 4; mt++)
        #pragma unroll
        for (int nt = 0; nt < 8; nt++)
            #pragma unroll
            for (int r = 0; r < 4; r++) acc[mt][nt][r] = 0.f;

    auto issue = [&](int kt, int st) {
        unsigned adst = As_u + (st * 128 * LP) * 2;
        unsigned bdst = Bs_u + (st * 256 * LP) * 2;
        int koff = kt * 32;
        #pragma unroll
        for (int i = 0; i < 2; i++) {
            int row = arow + i * 64;
            CP16(adst + (row * LP + aseg * 8) * 2, abase + (size_t)i * 64 * NDIM + koff);
        }
        #pragma unroll
        for (int i = 0; i < 4; i++) {
            int row = arow + i * 64;
            CP16(bdst + (row * LP + aseg * 8) * 2, bbase + (size_t)i * 64 * NDIM + koff);
        }
    };

    issue(0, 0); CP_COMMIT();
    issue(1, 1); CP_COMMIT();

    const int NKT = NDIM / 32;
    int st = 0;
    for (int kt = 0; kt < NKT; kt++) {
        CP_WAIT1();
        __syncthreads();
        if (kt + 2 < NKT) {
            int nst = st + 2; if (nst >= 3) nst -= 3;
            issue(kt + 2, nst);
        }
        CP_COMMIT();

        const __half* Asst = AsB + st * 128 * LP;
        const __half* Bsst = BsB + st * 256 * LP;
        #pragma unroll
        for (int sl = 0; sl < 2; sl++) {
            int kof = sl * 16;
            unsigned afr[4][4], bfr[8][2];
            #pragma unroll
            for (int mt = 0; mt < 4; mt++)
                ldsm4(afr[mt][0], afr[mt][1], afr[mt][2], afr[mt][3],
                      Asst + (wm + mt * 16 + lane15) * LP + kof + acolsel);
            #pragma unroll
            for (int ntp = 0; ntp < 4; ntp++) {
                unsigned r0, r1, r2, r3;
                ldsm4(r0, r1, r2, r3,
                      Bsst + (wn + ntp * 16 + b_rowoff) * LP + kof + bcolsel);
                bfr[ntp*2][0]   = r0; bfr[ntp*2][1]   = r1;
                bfr[ntp*2+1][0] = r2; bfr[ntp*2+1][1] = r3;
            }
            #pragma unroll
            for (int mt = 0; mt < 4; mt++)
                #pragma unroll
                for (int nt = 0; nt < 8; nt++)
                    mma_f16(acc[mt][nt], afr[mt][0], afr[mt][1], afr[mt][2], afr[mt][3],
                            bfr[nt][0], bfr[nt][1]);
        }
        st++; if (st >= 3) st = 0;
    }

    if (mode <= 1) {
        #pragma unroll
        for (int mt = 0; mt < 4; mt++) {
            #pragma unroll
            for (int nt = 0; nt < 8; nt++) {
                int n = n0 + wn + nt * 8 + (qid << 1);
                float bx = bias[n], by = bias[n + 1];
                #pragma unroll
                for (int half = 0; half < 2; half++) {
                    int m = m0 + wm + mt * 16 + grp + half * 8;
                    float2 v;
                    v.x = acc[mt][nt][half * 2 + 0] + bx;
                    v.y = acc[mt][nt][half * 2 + 1] + by;
                    if (mode == 1) {
                        int b = m >> 11, s = m & (NS - 1);
                        int h = n >> 6, d = n & 63;
                        *(float2*)&dst[(((size_t)((b << 4) + h) * NS + s)) * HD + d] = v;
                    } else {
                        *(float2*)&dst[(size_t)m * NDIM + n] = v;
                    }
                }
            }
        }
    } else {
        // RoPE epilogue: pairs (ntp, ntp+4) give dims d and d+32 of one head.
        int h = (n0 + wn) >> 6;
        #pragma unroll
        for (int mt = 0; mt < 4; mt++) {
            #pragma unroll
            for (int half = 0; half < 2; half++) {
                int m = m0 + wm + mt * 16 + grp + half * 8;
                int b = m >> 11, s = m & (NS - 1);
                size_t rowbase = (((size_t)((b << 4) + h) * NS + s)) * HD;
                #pragma unroll
                for (int ntp = 0; ntp < 4; ntp++) {
                    int n = n0 + wn + ntp * 8 + (qid << 1);
                    int d = ntp * 8 + (qid << 1);          // < 32
                    float x1a = acc[mt][ntp][half*2+0]   + bias[n];
                    float x1b = acc[mt][ntp][half*2+1]   + bias[n+1];
                    float x2a = acc[mt][ntp+4][half*2+0] + bias[n+32];
                    float x2b = acc[mt][ntp+4][half*2+1] + bias[n+33];
                    float2 cv = *(const float2*)&g_cos[(s << 5) + d];
                    float2 sv = *(const float2*)&g_sin[(s << 5) + d];
                    float o1a = x1a * cv.x - x2a * sv.x;
                    float o1b = x1b * cv.y - x2b * sv.y;
                    float o2a = x2a * cv.x + x1a * sv.x;
                    float o2b = x2b * cv.y + x1b * sv.y;
                    if (mode == 2) {
                        *(unsigned*)&g_qh[rowbase + d]      = packh2(o1a, o1b);
                        *(unsigned*)&g_qh[rowbase + d + 32] = packh2(o2a, o2b);
                    } else {
                        *(float2*)&dst[rowbase + d]      = make_float2(o1a, o1b);
                        *(float2*)&dst[rowbase + d + 32] = make_float2(o2a, o2b);
                        *(unsigned*)&g_kh[rowbase + d]      = packh2(o1a, o1b);
                        *(unsigned*)&g_kh[rowbase + d + 32] = packh2(o2a, o2b);
                    }
                }
            }
        }
    }
}

// ---------------------------------------------------------------------------
// FP16 MMA flash attention, cp.async pipeline, P in registers, half2 exp2.
// Smem (halves): Qs[128][72] | K 3x[64][72] | V 3x[64][72] = 73728 B.
// ---------------------------------------------------------------------------
#define APH 72
#define ATTN_SMEM ((128*APH + 3*64*APH + 3*64*APH) * 2)

__global__ __launch_bounds__(256, 2)
void attn_tc_kernel()
{
    extern __shared__ __align__(16) __half asm_h[];
    __half* Qs  = asm_h;                       // [128][72]
    __half* Kst = asm_h + 128 * APH;           // 3 x [64][72]
    __half* Vst = Kst + 3 * 64 * APH;          // 3 x [64][72]
    unsigned K_u = (unsigned)__cvta_generic_to_shared(Kst);
    unsigned V_u = (unsigned)__cvta_generic_to_shared(Vst);

    int tid = threadIdx.x;
    int w = tid >> 5, lane = tid & 31;
    int grp = lane >> 2, qid = lane & 3;
    int wm = w << 4;
    int bh = blockIdx.y;
    int b = bh >> 4, h = bh & 15;
    int q0 = blockIdx.x << 7;

    int lane15   = lane & 15;
    int acolsel  = (lane >> 4) << 3;
    int b_rowoff = (lane & 7) + ((lane >> 4) << 3);
    int bcolsel  = ((lane >> 3) & 1) << 3;

    const __half* qptr  = g_qh + ((size_t)bh * NS + q0) * HD;
    const __half* kptr  = g_kh + (size_t)bh * NS * HD;
    const __half* vTptr = g_vTh + (size_t)bh * HD * NS;
    const unsigned* mb0 = g_mb + (size_t)(b * NS + q0 + wm + grp) * 64;
    const unsigned* mb1 = mb0 + 8 * 64;

    #pragma unroll
    for (int i = 0; i < 4; i++) {
        int c = tid + (i << 8);
        int row = c >> 3, seg = c & 7;
        *(uint4*)&Qs[row * APH + seg * 8] = *(const uint4*)(qptr + row * HD + seg * 8);
    }

    int crow = tid >> 3, cseg = tid & 7;
    auto issueKV = [&](int t, int st) {
        int k0 = t << 6;
        #pragma unroll
        for (int i = 0; i < 2; i++) {
            int row = crow + i * 32;
            CP16(K_u + ((st * 64 + row) * APH + cseg * 8) * 2,
                 kptr + (size_t)(k0 + row) * HD + cseg * 8);
            CP16(V_u + ((st * 64 + row) * APH + cseg * 8) * 2,
                 vTptr + (size_t)row * NS + k0 + cseg * 8);
        }
    };

    issueKV(0, 0); CP_COMMIT();
    issueKV(1, 1); CP_COMMIT();

    float o[8][4];
    #pragma unroll
    for (int nt = 0; nt < 8; nt++)
        #pragma unroll
        for (int r = 0; r < 4; r++) o[nt][r] = 0.f;
    float m0 = -3.0e38f, m1 = -3.0e38f, l0 = 0.f, l1 = 0.f;

    const int NT = NS / 64;   // 32
    int st = 0;
    for (int t = 0; t < NT; t++) {
        CP_WAIT1();
        __syncthreads();
        if (t + 2 < NT) {
            int nst = st + 2; if (nst >= 3) nst -= 3;
            issueKV(t + 2, nst);
        }
        CP_COMMIT();

        const __half* Ks = Kst + st * 64 * APH;
        const __half* Vs = Vst + st * 64 * APH;
        int k0 = t << 6;

        // S = Q K^T
        float sc[8][4];
        #pragma unroll
        for (int nt = 0; nt < 8; nt++)
            #pragma unroll
            for (int r = 0; r < 4; r++) sc[nt][r] = 0.f;

        #pragma unroll
        for (int kk = 0; kk < 4; kk++) {
            unsigned a0, a1, a2, a3;
            ldsm4(a0, a1, a2, a3, &Qs[(wm + lane15) * APH + kk * 16 + acolsel]);
            #pragma unroll
            for (int ntp = 0; ntp < 4; ntp++) {
                unsigned r0, r1, r2, r3;
                ldsm4(r0, r1, r2, r3,
                      Ks + (ntp * 16 + b_rowoff) * APH + kk * 16 + bcolsel);
                mma_f16(sc[ntp*2],   a0, a1, a2, a3, r0, r1);
                mma_f16(sc[ntp*2+1], a0, a1, a2, a3, r2, r3);
            }
        }

        // scale (exp2 domain) + bitmask
        unsigned long long w0 = *(const unsigned long long*)(mb0 + (k0 >> 5));
        unsigned long long w1 = *(const unsigned long long*)(mb1 + (k0 >> 5));
        #pragma unroll
        for (int nt = 0; nt < 8; nt++) {
            int p = nt * 8 + (qid << 1);
            sc[nt][0] = ((w0 >> p)     & 1) ? sc[nt][0] * SCALE2 : -1e30f;
            sc[nt][1] = ((w0 >> (p+1)) & 1) ? sc[nt][1] * SCALE2 : -1e30f;
            sc[nt][2] = ((w1 >> p)     & 1) ? sc[nt][2] * SCALE2 : -1e30f;
            sc[nt][3] = ((w1 >> (p+1)) & 1) ? sc[nt][3] * SCALE2 : -1e30f;
        }

        // online softmax (log2 domain)
        float mx0 = -3.0e38f, mx1 = -3.0e38f;
        #pragma unroll
        for (int nt = 0; nt < 8; nt++) {
            mx0 = fmaxf(mx0, fmaxf(sc[nt][0], sc[nt][1]));
            mx1 = fmaxf(mx1, fmaxf(sc[nt][2], sc[nt][3]));
        }
        mx0 = fmaxf(mx0, __shfl_xor_sync(0xffffffffu, mx0, 1));
        mx0 = fmaxf(mx0, __shfl_xor_sync(0xffffffffu, mx0, 2));
        mx1 = fmaxf(mx1, __shfl_xor_sync(0xffffffffu, mx1, 1));
        mx1 = fmaxf(mx1, __shfl_xor_sync(0xffffffffu, mx1, 2));

        float mn0 = fmaxf(m0, mx0), mn1 = fmaxf(m1, mx1);
        float corr0 = fex2(m0 - mn0), corr1 = fex2(m1 - mn1);
        m0 = mn0; m1 = mn1;

        // p = exp2(sc - mn) computed in half2; result IS the P A-fragment word
        unsigned pfrag[8][2];
        float ps0 = 0.f, ps1 = 0.f;
        #pragma unroll
        for (int nt = 0; nt < 8; nt++) {
            __half2 e0 = h2exp2(__floats2half2_rn(sc[nt][0] - mn0, sc[nt][1] - mn0));
            __half2 e1 = h2exp2(__floats2half2_rn(sc[nt][2] - mn1, sc[nt][3] - mn1));
            pfrag[nt][0] = *(unsigned*)&e0;
            pfrag[nt][1] = *(unsigned*)&e1;
            float2 f0 = __half22float2(e0);
            float2 f1 = __half22float2(e1);
            ps0 += f0.x + f0.y;
            ps1 += f1.x + f1.y;
        }
        ps0 += __shfl_xor_sync(0xffffffffu, ps0, 1);
        ps0 += __shfl_xor_sync(0xffffffffu, ps0, 2);
        ps1 += __shfl_xor_sync(0xffffffffu, ps1, 1);
        ps1 += __shfl_xor_sync(0xffffffffu, ps1, 2);
        l0 = l0 * corr0 + ps0;
        l1 = l1 * corr1 + ps1;
        #pragma unroll
        for (int nt = 0; nt < 8; nt++) {
            o[nt][0] *= corr0; o[nt][1] *= corr0;
            o[nt][2] *= corr1; o[nt][3] *= corr1;
        }

        // O += P V  (P fragments straight from pfrag)
        #pragma unroll
        for (int kk = 0; kk < 4; kk++) {
            unsigned a0 = pfrag[2*kk][0];
            unsigned a1 = pfrag[2*kk][1];
            unsigned a2 = pfrag[2*kk+1][0];
            unsigned a3 = pfrag[2*kk+1][1];
            #pragma unroll
            for (int ntp = 0; ntp < 4; ntp++) {
                unsigned r0, r1, r2, r3;
                ldsm4(r0, r1, r2, r3,
                      Vs + (ntp * 16 + b_rowoff) * APH + kk * 16 + bcolsel);
                mma_f16(o[ntp*2],   a0, a1, a2, a3, r0, r1);
                mma_f16(o[ntp*2+1], a0, a1, a2, a3, r2, r3);
            }
        }
        st++; if (st >= 3) st = 0;
    }

    // epilogue: write context as HALF directly into g_ah (A of out-proj)
    float inv0 = 1.0f / l0, inv1 = 1.0f / l1;
    int r0 = q0 + wm + grp, r1 = r0 + 8;
    #pragma unroll
    for (int nt = 0; nt < 8; nt++) {
        int col = h * HD + nt * 8 + (qid << 1);
        *(unsigned*)&g_ah[((size_t)b * NS + r0) * NDIM + col] =
            packh2(o[nt][0] * inv0, o[nt][1] * inv0);
        *(unsigned*)&g_ah[((size_t)b * NS + r1) * NDIM + col] =
            packh2(o[nt][2] * inv1, o[nt][3] * inv1);
    }
}

// ---------------------------------------------------------------------------
extern "C" void kernel_launch(void* const* d_in, const int* in_sizes, int n_in,
                              void* d_out, int out_size) {
    const float* query = (const float*)d_in[0];
    const float* key   = (const float*)d_in[1];
    const float* value = (const float*)d_in[2];
    const int*   mask  = (const int*)d_in[3];
    const float* Wq = (const float*)d_in[4];
    const float* bq = (const float*)d_in[5];
    const float* Wk = (const float*)d_in[6];
    const float* bk = (const float*)d_in[7];
    const float* Wv = (const float*)d_in[8];
    const float* bv = (const float*)d_in[9];
    const float* Wo = (const float*)d_in[10];
    const float* bo = (const float*)d_in[11];

    float* out  = (float*)d_out;                 // [B,S,1024]
    float* outK = out + OUT_ELEMS;               // [B,H,S,64] (post-RoPE k)
    float* outV = out + 2 * (size_t)OUT_ELEMS;   // [B,H,S,64] (v)

    __half* g_ah_p;  cudaGetSymbolAddress((void**)&g_ah_p, g_ah);
    __half* g_inh_p; cudaGetSymbolAddress((void**)&g_inh_p, g_inh);
    __half* g_wh_p;  cudaGetSymbolAddress((void**)&g_wh_p, g_wh);

    static int smem_set = 0;
    if (!smem_set) {
        cudaFuncSetAttribute(linear_tc_kernel, cudaFuncAttributeMaxDynamicSharedMemorySize,
                             LIN_SMEM);
        cudaFuncSetAttribute(attn_tc_kernel, cudaFuncAttributeMaxDynamicSharedMemorySize,
                             ATTN_SMEM);
        smem_set = 1;
    }

    const int A4 = NM * NDIM / 4;
    const int W4 = NDIM * NDIM / 4;
    const size_t WSZ = (size_t)NDIM * NDIM;

    rope_table_kernel<<<(NS * 32 + 255) / 256, 256>>>();
    mask_bits_kernel<<<(NB * NS * 32 + 255) / 256, 256>>>(mask);

    dim3 wgrid4(W4 / 512, 4);
    f2h_multi_kernel<<<wgrid4, 256>>>(Wq, Wk, Wv, Wo, g_wh_p, W4);
    dim3 igrid3(A4 / 512, 3);
    f2h_multi_kernel<<<igrid3, 256>>>(query, key, value, value, g_inh_p, A4);

    dim3 lgrid(NDIM / 256, NM / 128);   // (4, 32)
    linear_tc_kernel<<<lgrid, 256, LIN_SMEM>>>(g_inh_p,                     g_wh_p,         bq, out,  2);
    linear_tc_kernel<<<lgrid, 256, LIN_SMEM>>>(g_inh_p + (size_t)NM*NDIM,   g_wh_p + WSZ,   bk, outK, 3);
    linear_tc_kernel<<<lgrid, 256, LIN_SMEM>>>(g_inh_p + 2*(size_t)NM*NDIM, g_wh_p + 2*WSZ, bv, outV, 1);

    dim3 vgrid(NS / 128, NB * NH);
    vT_kernel<<<vgrid, 256>>>(outV);

    dim3 agrid(NS / 128, NB * NH);      // (16, 32)
    attn_tc_kernel<<<agrid, 256, ATTN_SMEM>>>();

    linear_tc_kernel<<<lgrid, 256, LIN_SMEM>>>(g_ah_p, g_wh_p + 3*WSZ, bo, out, 0);
}

// round 14
// speedup vs baseline: 6.0387x; 1.0290x over previous
#include <cuda_runtime.h>
#include <cuda_fp16.h>
#include <math.h>

#define NB 2
#define NS 2048
#define NH 16
#define HD 64
#define NDIM 1024
#define NM (NB*NS)
#define OUT_ELEMS (NB*NS*NDIM)   // 4194304 per tensor (out, k, v)

// Scratch (allocation-free rule: __device__ globals)
__device__ __align__(256) __half g_ah[NM*NDIM];       // ctx half (A of out-proj)
__device__ __align__(256) __half g_inh[3*NM*NDIM];    // half query/key/value inputs
__device__ __align__(256) __half g_wh[4*NDIM*NDIM];   // half Wq/Wk/Wv/Wo
__device__ __align__(256) __half g_qh[NB*NH*NS*HD];   // half Q (post-RoPE)
__device__ __align__(256) __half g_kh[NB*NH*NS*HD];   // half K (post-RoPE)
__device__ __align__(256) __half g_vTh[NB*NH*HD*NS];  // half V transposed [b,h,d,s]
__device__ __align__(256) unsigned g_mb[NB*NS*64];    // mask bitwords
__device__ float g_cos[NS*32];
__device__ float g_sin[NS*32];

#define SCALE2 0.18033688011112042f   // 0.125 * log2(e)

__device__ __forceinline__ unsigned packh2(float x, float y) {
    __half2 h = __floats2half2_rn(x, y);
    return *(unsigned*)&h;
}
__device__ __forceinline__ float fex2(float x) {
    float r; asm("ex2.approx.ftz.f32 %0, %1;" : "=f"(r) : "f"(x)); return r;
}
__device__ __forceinline__ void mma_f16(float c[4], unsigned a0, unsigned a1,
                                        unsigned a2, unsigned a3,
                                        unsigned b0, unsigned b1) {
    asm volatile(
        "mma.sync.aligned.m16n8k16.row.col.f32.f16.f16.f32 "
        "{%0,%1,%2,%3}, {%4,%5,%6,%7}, {%8,%9}, {%0,%1,%2,%3};"
        : "+f"(c[0]), "+f"(c[1]), "+f"(c[2]), "+f"(c[3])
        : "r"(a0), "r"(a1), "r"(a2), "r"(a3), "r"(b0), "r"(b1));
}
__device__ __forceinline__ void ldsm4(unsigned &r0, unsigned &r1, unsigned &r2,
                                      unsigned &r3, const void* p) {
    unsigned a = (unsigned)__cvta_generic_to_shared(p);
    asm volatile("ldmatrix.sync.aligned.m8n8.x4.shared.b16 {%0,%1,%2,%3}, [%4];"
                 : "=r"(r0), "=r"(r1), "=r"(r2), "=r"(r3) : "r"(a));
}
#define CP16(dst_u32, src_ptr) \
    asm volatile("cp.async.ca.shared.global [%0], [%1], 16;" \
                 :: "r"(dst_u32), "l"(src_ptr))
#define CP_COMMIT() asm volatile("cp.async.commit_group;" ::: "memory")
#define CP_WAIT1()  asm volatile("cp.async.wait_group 1;" ::: "memory")

// ---------------------------------------------------------------------------
// RoPE tables
// ---------------------------------------------------------------------------
__global__ void rope_table_kernel() {
    int idx = blockIdx.x * blockDim.x + threadIdx.x;
    if (idx >= NS * 32) return;
    int s = idx >> 5, j = idx & 31;
    float invf = (float)exp(-(double)j * (log(10000.0) / 32.0));
    float ang = (float)s * invf;
    g_cos[idx] = (float)cos((double)ang);
    g_sin[idx] = (float)sin((double)ang);
}

// mask [B,S,S] int32 -> bitwords
__global__ void mask_bits_kernel(const int* __restrict__ mask) {
    int gw = (blockIdx.x * blockDim.x + threadIdx.x) >> 5;
    int lane = threadIdx.x & 31;
    if (gw >= NB * NS) return;
    const int* mrow = mask + (size_t)gw * NS;
    unsigned* dst = g_mb + (size_t)gw * 64;
    for (int wd = 0; wd < 64; wd++) {
        unsigned bits = __ballot_sync(0xffffffffu, mrow[wd * 32 + lane] != 0);
        if (lane == 0) dst[wd] = bits;
    }
}

// batched fp32->fp16, 4 float4 per thread (MLP=4)
__global__ void f2h_multi_kernel(const float* s0, const float* s1,
                                 const float* s2, const float* s3,
                                 __half* __restrict__ out, int n4) {
    int i = (blockIdx.x * blockDim.x + threadIdx.x) * 4;
    if (i >= n4) return;
    const float* srcs[4] = {s0, s1, s2, s3};
    const float* in = srcs[blockIdx.y];
    __half* o = out + (size_t)blockIdx.y * n4 * 4;
    float4 v0 = ((const float4*)in)[i];
    float4 v1 = ((const float4*)in)[i + 1];
    float4 v2 = ((const float4*)in)[i + 2];
    float4 v3 = ((const float4*)in)[i + 3];
    uint4 u;
    u.x = packh2(v0.x, v0.y); u.y = packh2(v0.z, v0.w);
    u.z = packh2(v1.x, v1.y); u.w = packh2(v1.z, v1.w);
    *(uint4*)(o + (size_t)i * 4) = u;
    u.x = packh2(v2.x, v2.y); u.y = packh2(v2.z, v2.w);
    u.z = packh2(v3.x, v3.y); u.w = packh2(v3.z, v3.w);
    *(uint4*)(o + (size_t)i * 4 + 8) = u;
}

// ---------------------------------------------------------------------------
// Shared GEMM mainloop: 128m x 256n CTA tile, cp.async 3 stages, fp32 accum.
// ---------------------------------------------------------------------------
#define LP 40
#define LIN_SMEM (3*(128+256)*LP*2)   // 92160 bytes

struct LinCtx {
    int tid, w, lane, grp, qid, wm, wn;
    int lane15, acolsel, b_rowoff, bcolsel;
};

__device__ __forceinline__ void gemm_main(
    const __half* __restrict__ Ah, const __half* __restrict__ Wh,
    int m0, int n0, __half* lsm, const LinCtx& c, float acc[4][8][4])
{
    __half* AsB = lsm;
    __half* BsB = lsm + 3 * 128 * LP;
    unsigned As_u = (unsigned)__cvta_generic_to_shared(AsB);
    unsigned Bs_u = (unsigned)__cvta_generic_to_shared(BsB);

    int arow = c.tid >> 2, aseg = c.tid & 3;
    const __half* abase = Ah + (size_t)(m0 + arow) * NDIM + aseg * 8;
    const __half* bbase = Wh + (size_t)(n0 + arow) * NDIM + aseg * 8;

    #pragma unroll
    for (int mt = 0; mt < 4; mt++)
        #pragma unroll
        for (int nt = 0; nt < 8; nt++)
            #pragma unroll
            for (int r = 0; r < 4; r++) acc[mt][nt][r] = 0.f;

    auto issue = [&](int kt, int st) {
        unsigned adst = As_u + (st * 128 * LP) * 2;
        unsigned bdst = Bs_u + (st * 256 * LP) * 2;
        int koff = kt * 32;
        #pragma unroll
        for (int i = 0; i < 2; i++) {
            int row = arow + i * 64;
            CP16(adst + (row * LP + aseg * 8) * 2, abase + (size_t)i * 64 * NDIM + koff);
        }
        #pragma unroll
        for (int i = 0; i < 4; i++) {
            int row = arow + i * 64;
            CP16(bdst + (row * LP + aseg * 8) * 2, bbase + (size_t)i * 64 * NDIM + koff);
        }
    };

    issue(0, 0); CP_COMMIT();
    issue(1, 1); CP_COMMIT();

    const int NKT = NDIM / 32;
    int st = 0;
    for (int kt = 0; kt < NKT; kt++) {
        CP_WAIT1();
        __syncthreads();
        if (kt + 2 < NKT) {
            int nst = st + 2; if (nst >= 3) nst -= 3;
            issue(kt + 2, nst);
        }
        CP_COMMIT();

        const __half* Asst = AsB + st * 128 * LP;
        const __half* Bsst = BsB + st * 256 * LP;
        #pragma unroll
        for (int sl = 0; sl < 2; sl++) {
            int kof = sl * 16;
            unsigned afr[4][4], bfr[8][2];
            #pragma unroll
            for (int mt = 0; mt < 4; mt++)
                ldsm4(afr[mt][0], afr[mt][1], afr[mt][2], afr[mt][3],
                      Asst + (c.wm + mt * 16 + c.lane15) * LP + kof + c.acolsel);
            #pragma unroll
            for (int ntp = 0; ntp < 4; ntp++) {
                unsigned r0, r1, r2, r3;
                ldsm4(r0, r1, r2, r3,
                      Bsst + (c.wn + ntp * 16 + c.b_rowoff) * LP + kof + c.bcolsel);
                bfr[ntp*2][0]   = r0; bfr[ntp*2][1]   = r1;
                bfr[ntp*2+1][0] = r2; bfr[ntp*2+1][1] = r3;
            }
            #pragma unroll
            for (int mt = 0; mt < 4; mt++)
                #pragma unroll
                for (int nt = 0; nt < 8; nt++)
                    mma_f16(acc[mt][nt], afr[mt][0], afr[mt][1], afr[mt][2], afr[mt][3],
                            bfr[nt][0], bfr[nt][1]);
        }
        st++; if (st >= 3) st = 0;
    }
}

__device__ __forceinline__ LinCtx make_ctx() {
    LinCtx c;
    c.tid  = threadIdx.x;
    c.w    = c.tid >> 5;
    c.lane = c.tid & 31;
    c.grp  = c.lane >> 2;
    c.qid  = c.lane & 3;
    c.wm   = (c.w & 1) * 64;
    c.wn   = (c.w >> 1) * 64;
    c.lane15   = c.lane & 15;
    c.acolsel  = (c.lane >> 4) << 3;
    c.b_rowoff = (c.lane & 7) + ((c.lane >> 4) << 3);
    c.bcolsel  = ((c.lane >> 3) & 1) << 3;
    return c;
}

// ---------------------------------------------------------------------------
// Fused QKV projection: grid (4, 32, 3).  z=0 Q (RoPE -> g_qh half),
// z=1 K (RoPE -> outK fp32 + g_kh half), z=2 V (outV fp32 + g_vTh half).
// ---------------------------------------------------------------------------
__global__ __launch_bounds__(256)
void qkv_tc_kernel(const float* __restrict__ bq, const float* __restrict__ bk,
                   const float* __restrict__ bv, float* __restrict__ outK,
                   float* __restrict__ outV)
{
    extern __shared__ __align__(16) __half lsm[];
    LinCtx c = make_ctx();
    int z = blockIdx.z;
    int m0 = blockIdx.y << 7, n0 = blockIdx.x << 8;

    const __half* Ah = g_inh + (size_t)z * NM * NDIM;
    const __half* Wh = g_wh + (size_t)z * NDIM * NDIM;
    const float* bias = (z == 0) ? bq : (z == 1) ? bk : bv;

    float acc[4][8][4];
    gemm_main(Ah, Wh, m0, n0, lsm, c, acc);

    if (z == 2) {
        // V epilogue: fp32 head layout + half transposed layout
        #pragma unroll
        for (int mt = 0; mt < 4; mt++) {
            #pragma unroll
            for (int nt = 0; nt < 8; nt++) {
                int n = n0 + c.wn + nt * 8 + (c.qid << 1);
                float bx = bias[n], by = bias[n + 1];
                int h = n >> 6, d = n & 63;
                #pragma unroll
                for (int half = 0; half < 2; half++) {
                    int m = m0 + c.wm + mt * 16 + c.grp + half * 8;
                    int b = m >> 11, s = m & (NS - 1);
                    float vx = acc[mt][nt][half * 2 + 0] + bx;
                    float vy = acc[mt][nt][half * 2 + 1] + by;
                    size_t bh = (size_t)((b << 4) + h);
                    *(float2*)&outV[(bh * NS + s) * HD + d] = make_float2(vx, vy);
                    __half* vt = g_vTh + bh * HD * NS + (size_t)d * NS + s;
                    vt[0]  = __float2half_rn(vx);
                    vt[NS] = __float2half_rn(vy);
                }
            }
        }
    } else {
        // RoPE epilogue: pairs (ntp, ntp+4) give dims d and d+32 of one head.
        int h = (n0 + c.wn) >> 6;
        #pragma unroll
        for (int mt = 0; mt < 4; mt++) {
            #pragma unroll
            for (int half = 0; half < 2; half++) {
                int m = m0 + c.wm + mt * 16 + c.grp + half * 8;
                int b = m >> 11, s = m & (NS - 1);
                size_t rowbase = (((size_t)((b << 4) + h) * NS + s)) * HD;
                #pragma unroll
                for (int ntp = 0; ntp < 4; ntp++) {
                    int n = n0 + c.wn + ntp * 8 + (c.qid << 1);
                    int d = ntp * 8 + (c.qid << 1);
                    float x1a = acc[mt][ntp][half*2+0]   + bias[n];
                    float x1b = acc[mt][ntp][half*2+1]   + bias[n+1];
                    float x2a = acc[mt][ntp+4][half*2+0] + bias[n+32];
                    float x2b = acc[mt][ntp+4][half*2+1] + bias[n+33];
                    float2 cv = *(const float2*)&g_cos[(s << 5) + d];
                    float2 sv = *(const float2*)&g_sin[(s << 5) + d];
                    float o1a = x1a * cv.x - x2a * sv.x;
                    float o1b = x1b * cv.y - x2b * sv.y;
                    float o2a = x2a * cv.x + x1a * sv.x;
                    float o2b = x2b * cv.y + x1b * sv.y;
                    if (z == 0) {
                        *(unsigned*)&g_qh[rowbase + d]      = packh2(o1a, o1b);
                        *(unsigned*)&g_qh[rowbase + d + 32] = packh2(o2a, o2b);
                    } else {
                        *(float2*)&outK[rowbase + d]      = make_float2(o1a, o1b);
                        *(float2*)&outK[rowbase + d + 32] = make_float2(o2a, o2b);
                        *(unsigned*)&g_kh[rowbase + d]      = packh2(o1a, o1b);
                        *(unsigned*)&g_kh[rowbase + d + 32] = packh2(o2a, o2b);
                    }
                }
            }
        }
    }
}

// Out-projection: flat fp32 epilogue.
__global__ __launch_bounds__(256)
void out_tc_kernel(const float* __restrict__ bias, float* __restrict__ dst)
{
    extern __shared__ __align__(16) __half lsm[];
    LinCtx c = make_ctx();
    int m0 = blockIdx.y << 7, n0 = blockIdx.x << 8;

    float acc[4][8][4];
    gemm_main(g_ah, g_wh + 3 * (size_t)NDIM * NDIM, m0, n0, lsm, c, acc);

    #pragma unroll
    for (int mt = 0; mt < 4; mt++) {
        #pragma unroll
        for (int nt = 0; nt < 8; nt++) {
            int n = n0 + c.wn + nt * 8 + (c.qid << 1);
            float bx = bias[n], by = bias[n + 1];
            #pragma unroll
            for (int half = 0; half < 2; half++) {
                int m = m0 + c.wm + mt * 16 + c.grp + half * 8;
                float2 v;
                v.x = acc[mt][nt][half * 2 + 0] + bx;
                v.y = acc[mt][nt][half * 2 + 1] + by;
                *(float2*)&dst[(size_t)m * NDIM + n] = v;
            }
        }
    }
}

// ---------------------------------------------------------------------------
// FP16 MMA flash attention (unchanged from R13).
// ---------------------------------------------------------------------------
#define APH 72
#define ATTN_SMEM ((128*APH + 3*64*APH + 3*64*APH) * 2)

__global__ __launch_bounds__(256, 2)
void attn_tc_kernel()
{
    extern __shared__ __align__(16) __half asm_h[];
    __half* Qs  = asm_h;
    __half* Kst = asm_h + 128 * APH;
    __half* Vst = Kst + 3 * 64 * APH;
    unsigned K_u = (unsigned)__cvta_generic_to_shared(Kst);
    unsigned V_u = (unsigned)__cvta_generic_to_shared(Vst);

    int tid = threadIdx.x;
    int w = tid >> 5, lane = tid & 31;
    int grp = lane >> 2, qid = lane & 3;
    int wm = w << 4;
    int bh = blockIdx.y;
    int b = bh >> 4, h = bh & 15;
    int q0 = blockIdx.x << 7;

    int lane15   = lane & 15;
    int acolsel  = (lane >> 4) << 3;
    int b_rowoff = (lane & 7) + ((lane >> 4) << 3);
    int bcolsel  = ((lane >> 3) & 1) << 3;

    const __half* qptr  = g_qh + ((size_t)bh * NS + q0) * HD;
    const __half* kptr  = g_kh + (size_t)bh * NS * HD;
    const __half* vTptr = g_vTh + (size_t)bh * HD * NS;
    const unsigned* mb0 = g_mb + (size_t)(b * NS + q0 + wm + grp) * 64;
    const unsigned* mb1 = mb0 + 8 * 64;

    #pragma unroll
    for (int i = 0; i < 4; i++) {
        int cc = tid + (i << 8);
        int row = cc >> 3, seg = cc & 7;
        *(uint4*)&Qs[row * APH + seg * 8] = *(const uint4*)(qptr + row * HD + seg * 8);
    }

    int crow = tid >> 3, cseg = tid & 7;
    auto issueKV = [&](int t, int st) {
        int k0 = t << 6;
        #pragma unroll
        for (int i = 0; i < 2; i++) {
            int row = crow + i * 32;
            CP16(K_u + ((st * 64 + row) * APH + cseg * 8) * 2,
                 kptr + (size_t)(k0 + row) * HD + cseg * 8);
            CP16(V_u + ((st * 64 + row) * APH + cseg * 8) * 2,
                 vTptr + (size_t)row * NS + k0 + cseg * 8);
        }
    };

    issueKV(0, 0); CP_COMMIT();
    issueKV(1, 1); CP_COMMIT();

    float o[8][4];
    #pragma unroll
    for (int nt = 0; nt < 8; nt++)
        #pragma unroll
        for (int r = 0; r < 4; r++) o[nt][r] = 0.f;
    float m0 = -3.0e38f, m1 = -3.0e38f, l0 = 0.f, l1 = 0.f;

    const int NT = NS / 64;
    int st = 0;
    for (int t = 0; t < NT; t++) {
        CP_WAIT1();
        __syncthreads();
        if (t + 2 < NT) {
            int nst = st + 2; if (nst >= 3) nst -= 3;
            issueKV(t + 2, nst);
        }
        CP_COMMIT();

        const __half* Ks = Kst + st * 64 * APH;
        const __half* Vs = Vst + st * 64 * APH;
        int k0 = t << 6;

        float sc[8][4];
        #pragma unroll
        for (int nt = 0; nt < 8; nt++)
            #pragma unroll
            for (int r = 0; r < 4; r++) sc[nt][r] = 0.f;

        #pragma unroll
        for (int kk = 0; kk < 4; kk++) {
            unsigned a0, a1, a2, a3;
            ldsm4(a0, a1, a2, a3, &Qs[(wm + lane15) * APH + kk * 16 + acolsel]);
            #pragma unroll
            for (int ntp = 0; ntp < 4; ntp++) {
                unsigned r0, r1, r2, r3;
                ldsm4(r0, r1, r2, r3,
                      Ks + (ntp * 16 + b_rowoff) * APH + kk * 16 + bcolsel);
                mma_f16(sc[ntp*2],   a0, a1, a2, a3, r0, r1);
                mma_f16(sc[ntp*2+1], a0, a1, a2, a3, r2, r3);
            }
        }

        unsigned long long w0 = *(const unsigned long long*)(mb0 + (k0 >> 5));
        unsigned long long w1 = *(const unsigned long long*)(mb1 + (k0 >> 5));
        #pragma unroll
        for (int nt = 0; nt < 8; nt++) {
            int p = nt * 8 + (qid << 1);
            sc[nt][0] = ((w0 >> p)     & 1) ? sc[nt][0] * SCALE2 : -1e30f;
            sc[nt][1] = ((w0 >> (p+1)) & 1) ? sc[nt][1] * SCALE2 : -1e30f;
            sc[nt][2] = ((w1 >> p)     & 1) ? sc[nt][2] * SCALE2 : -1e30f;
            sc[nt][3] = ((w1 >> (p+1)) & 1) ? sc[nt][3] * SCALE2 : -1e30f;
        }

        float mx0 = -3.0e38f, mx1 = -3.0e38f;
        #pragma unroll
        for (int nt = 0; nt < 8; nt++) {
            mx0 = fmaxf(mx0, fmaxf(sc[nt][0], sc[nt][1]));
            mx1 = fmaxf(mx1, fmaxf(sc[nt][2], sc[nt][3]));
        }
        mx0 = fmaxf(mx0, __shfl_xor_sync(0xffffffffu, mx0, 1));
        mx0 = fmaxf(mx0, __shfl_xor_sync(0xffffffffu, mx0, 2));
        mx1 = fmaxf(mx1, __shfl_xor_sync(0xffffffffu, mx1, 1));
        mx1 = fmaxf(mx1, __shfl_xor_sync(0xffffffffu, mx1, 2));

        float mn0 = fmaxf(m0, mx0), mn1 = fmaxf(m1, mx1);
        float corr0 = fex2(m0 - mn0), corr1 = fex2(m1 - mn1);
        m0 = mn0; m1 = mn1;

        unsigned pfrag[8][2];
        float ps0 = 0.f, ps1 = 0.f;
        #pragma unroll
        for (int nt = 0; nt < 8; nt++) {
            __half2 e0 = h2exp2(__floats2half2_rn(sc[nt][0] - mn0, sc[nt][1] - mn0));
            __half2 e1 = h2exp2(__floats2half2_rn(sc[nt][2] - mn1, sc[nt][3] - mn1));
            pfrag[nt][0] = *(unsigned*)&e0;
            pfrag[nt][1] = *(unsigned*)&e1;
            float2 f0 = __half22float2(e0);
            float2 f1 = __half22float2(e1);
            ps0 += f0.x + f0.y;
            ps1 += f1.x + f1.y;
        }
        ps0 += __shfl_xor_sync(0xffffffffu, ps0, 1);
        ps0 += __shfl_xor_sync(0xffffffffu, ps0, 2);
        ps1 += __shfl_xor_sync(0xffffffffu, ps1, 1);
        ps1 += __shfl_xor_sync(0xffffffffu, ps1, 2);
        l0 = l0 * corr0 + ps0;
        l1 = l1 * corr1 + ps1;
        #pragma unroll
        for (int nt = 0; nt < 8; nt++) {
            o[nt][0] *= corr0; o[nt][1] *= corr0;
            o[nt][2] *= corr1; o[nt][3] *= corr1;
        }

        #pragma unroll
        for (int kk = 0; kk < 4; kk++) {
            unsigned a0 = pfrag[2*kk][0];
            unsigned a1 = pfrag[2*kk][1];
            unsigned a2 = pfrag[2*kk+1][0];
            unsigned a3 = pfrag[2*kk+1][1];
            #pragma unroll
            for (int ntp = 0; ntp < 4; ntp++) {
                unsigned r0, r1, r2, r3;
                ldsm4(r0, r1, r2, r3,
                      Vs + (ntp * 16 + b_rowoff) * APH + kk * 16 + bcolsel);
                mma_f16(o[ntp*2],   a0, a1, a2, a3, r0, r1);
                mma_f16(o[ntp*2+1], a0, a1, a2, a3, r2, r3);
            }
        }
        st++; if (st >= 3) st = 0;
    }

    float inv0 = 1.0f / l0, inv1 = 1.0f / l1;
    int r0 = q0 + wm + grp, r1 = r0 + 8;
    #pragma unroll
    for (int nt = 0; nt < 8; nt++) {
        int col = h * HD + nt * 8 + (qid << 1);
        *(unsigned*)&g_ah[((size_t)b * NS + r0) * NDIM + col] =
            packh2(o[nt][0] * inv0, o[nt][1] * inv0);
        *(unsigned*)&g_ah[((size_t)b * NS + r1) * NDIM + col] =
            packh2(o[nt][2] * inv1, o[nt][3] * inv1);
    }
}

// ---------------------------------------------------------------------------
extern "C" void kernel_launch(void* const* d_in, const int* in_sizes, int n_in,
                              void* d_out, int out_size) {
    const float* query = (const float*)d_in[0];
    const float* key   = (const float*)d_in[1];
    const float* value = (const float*)d_in[2];
    const int*   mask  = (const int*)d_in[3];
    const float* Wq = (const float*)d_in[4];
    const float* bq = (const float*)d_in[5];
    const float* Wk = (const float*)d_in[6];
    const float* bk = (const float*)d_in[7];
    const float* Wv = (const float*)d_in[8];
    const float* bv = (const float*)d_in[9];
    const float* Wo = (const float*)d_in[10];
    const float* bo = (const float*)d_in[11];

    float* out  = (float*)d_out;                 // [B,S,1024]
    float* outK = out + OUT_ELEMS;               // [B,H,S,64] (post-RoPE k)
    float* outV = out + 2 * (size_t)OUT_ELEMS;   // [B,H,S,64] (v)

    __half* g_inh_p; cudaGetSymbolAddress((void**)&g_inh_p, g_inh);
    __half* g_wh_p;  cudaGetSymbolAddress((void**)&g_wh_p, g_wh);

    static int smem_set = 0;
    if (!smem_set) {
        cudaFuncSetAttribute(qkv_tc_kernel, cudaFuncAttributeMaxDynamicSharedMemorySize,
                             LIN_SMEM);
        cudaFuncSetAttribute(out_tc_kernel, cudaFuncAttributeMaxDynamicSharedMemorySize,
                             LIN_SMEM);
        cudaFuncSetAttribute(attn_tc_kernel, cudaFuncAttributeMaxDynamicSharedMemorySize,
                             ATTN_SMEM);
        smem_set = 1;
    }

    const int A4 = NM * NDIM / 4;
    const int W4 = NDIM * NDIM / 4;

    rope_table_kernel<<<(NS * 32 + 255) / 256, 256>>>();
    mask_bits_kernel<<<(NB * NS * 32 + 255) / 256, 256>>>(mask);

    dim3 wgrid4(W4 / 1024, 4);
    f2h_multi_kernel<<<wgrid4, 256>>>(Wq, Wk, Wv, Wo, g_wh_p, W4);
    dim3 igrid3(A4 / 1024, 3);
    f2h_multi_kernel<<<igrid3, 256>>>(query, key, value, value, g_inh_p, A4);

    dim3 qkvgrid(NDIM / 256, NM / 128, 3);   // (4, 32, 3) = 384 CTAs
    qkv_tc_kernel<<<qkvgrid, 256, LIN_SMEM>>>(bq, bk, bv, outK, outV);

    dim3 agrid(NS / 128, NB * NH);           // (16, 32)
    attn_tc_kernel<<<agrid, 256, ATTN_SMEM>>>();

    dim3 ogrid(NDIM / 256, NM / 128);        // (4, 32)
    out_tc_kernel<<<ogrid, 256, LIN_SMEM>>>(bo, out);
}